// round 1
// baseline (speedup 1.0000x reference)
#include <cuda_runtime.h>
#include <math.h>

#define N_NODES 16384
#define E_EDGES 147456
#define HD 128
#define NSEG 32
#define SEGSZ 512
#define KEDGE 9

// ---------------- scratch (device globals; no allocation at runtime) ----------------
__device__ float g_t0[N_NODES * HD];
__device__ float g_h[N_NODES * HD];
__device__ float g_Ar[N_NODES * HD];
__device__ float g_Ac[N_NODES * HD];
__device__ float g_agg[N_NODES * HD];
__device__ float g_u[N_NODES * HD];
__device__ float g_hintra[N_NODES * HD];
__device__ float g_v2n[N_NODES * HD];
__device__ float g_cat[N_NODES * 2 * HD];
__device__ float g_mix[N_NODES * 2 * HD];
__device__ float g_ef[E_EDGES * 36];
__device__ float g_epre[E_EDGES * HD];
__device__ float g_t[E_EDGES * HD];
__device__ float g_m[E_EDGES * HD];
__device__ float g_mv[E_EDGES * HD];
__device__ float g_mvv[E_EDGES * HD];
__device__ float g_unit[E_EDGES * 3];
__device__ float g_va[N_NODES * 3 * HD];
__device__ float g_vb[N_NODES * 3 * HD];
__device__ float g_vp1[N_NODES * 3 * HD];
__device__ float g_vp2[N_NODES * 3 * HD];
__device__ float g_w[N_NODES];
__device__ float g_meanh[NSEG * HD];
__device__ float g_pv[N_NODES * 27];
__device__ float g_pred[NSEG * 27];

// ---------------- generic fp32 GEMM: C = f( rowscale[m] * (A@B) + bias[n] ) + residual ----------------
// A: (M,K) row-major, B: (K,N) row-major. 64x64 tile, BK=16, 256 threads, 4x4 per thread.
__global__ void gemm_kernel(const float* __restrict__ A, const float* __restrict__ B,
                            const float* __restrict__ bias, const float* __restrict__ rowscale,
                            const float* __restrict__ residual, float* __restrict__ C,
                            int M, int N, int K, int silu_act)
{
    __shared__ float As[16][64];
    __shared__ float Bs[16][64];
    const int bm = blockIdx.y * 64;
    const int bn = blockIdx.x * 64;
    const int tid = threadIdx.x;
    const int ty = tid >> 4;        // 0..15
    const int tx = tid & 15;        // 0..15

    float acc[4][4] = {};

    const int am = tid >> 2;        // 0..63
    const int ak = (tid & 3) * 4;   // 0,4,8,12
    const int bk = tid >> 4;        // 0..15
    const int bq = (tid & 15) * 4;  // 0..60

    for (int k0 = 0; k0 < K; k0 += 16) {
        // load A tile (transposed into smem)
        {
            int m = bm + am;
#pragma unroll
            for (int i = 0; i < 4; i++) {
                int k = k0 + ak + i;
                As[ak + i][am] = (m < M && k < K) ? A[(long)m * K + k] : 0.0f;
            }
        }
        // load B tile
        {
            int k = k0 + bk;
#pragma unroll
            for (int j = 0; j < 4; j++) {
                int n = bn + bq + j;
                Bs[bk][bq + j] = (k < K && n < N) ? B[(long)k * N + n] : 0.0f;
            }
        }
        __syncthreads();
#pragma unroll
        for (int k = 0; k < 16; k++) {
            float a[4], b[4];
#pragma unroll
            for (int i = 0; i < 4; i++) a[i] = As[k][ty * 4 + i];
#pragma unroll
            for (int j = 0; j < 4; j++) b[j] = Bs[k][tx * 4 + j];
#pragma unroll
            for (int i = 0; i < 4; i++)
#pragma unroll
                for (int j = 0; j < 4; j++)
                    acc[i][j] += a[i] * b[j];
        }
        __syncthreads();
    }

#pragma unroll
    for (int i = 0; i < 4; i++) {
        int m = bm + ty * 4 + i;
        if (m >= M) continue;
        float rs = rowscale ? rowscale[m] : 1.0f;
#pragma unroll
        for (int j = 0; j < 4; j++) {
            int n = bn + tx * 4 + j;
            if (n >= N) continue;
            float v = acc[i][j] * rs;
            if (bias) v += bias[n];
            if (silu_act) v = v / (1.0f + expf(-v));
            if (residual) v += residual[(long)m * N + n];
            C[(long)m * N + n] = v;
        }
    }
}

// ---------------- small kernels ----------------
__global__ void zero_kernel(float* p, int n) {
    int i = blockIdx.x * blockDim.x + threadIdx.x;
    if (i < n) p[i] = 0.0f;
}

__global__ void edge_geom_kernel(const float* __restrict__ X, const float* __restrict__ edge_attr,
                                 const int* __restrict__ edges,
                                 float* __restrict__ unit, float* __restrict__ ef)
{
    int e = blockIdx.x * blockDim.x + threadIdx.x;
    if (e >= E_EDGES) return;
    int r = edges[e];
    int c = edges[E_EDGES + e];
    float dx = X[r * 3 + 0] - X[c * 3 + 0];
    float dy = X[r * 3 + 1] - X[c * 3 + 1];
    float dz = X[r * 3 + 2] - X[c * 3 + 2];
    float norm = sqrtf(dx * dx + dy * dy + dz * dz) + 1e-8f;
    float invn = 1.0f / norm;
    unit[e * 3 + 0] = dx * invn;
    unit[e * 3 + 1] = dy * invn;
    unit[e * 3 + 2] = dz * invn;
    const float PI_ = 3.14159265358979323846f;
    float cn = fminf(norm, 1.0f);
    float cut = 0.5f * (cosf(PI_ * cn) + 1.0f);
    float f = cut * invn;
#pragma unroll
    for (int j = 0; j < 20; j++)
        ef[e * 36 + j] = sinf(norm * PI_ * (float)(j + 1)) * f;
#pragma unroll
    for (int j = 0; j < 16; j++)
        ef[e * 36 + 20 + j] = edge_attr[e * 16 + j];
}

// t[e] = silu(Ar[row[e]] + Ac[col[e]] + epre[e])   (epre already includes be1)
__global__ void edge_combine_kernel(const float* __restrict__ Ar, const float* __restrict__ Ac,
                                    const float* __restrict__ epre, const int* __restrict__ edges,
                                    float* __restrict__ out)
{
    int e = blockIdx.x;
    int hh = threadIdx.x;
    int r = edges[e];
    int c = edges[E_EDGES + e];
    float v = Ar[(long)r * HD + hh] + Ac[(long)c * HD + hh] + epre[(long)e * HD + hh];
    out[(long)e * HD + hh] = v / (1.0f + expf(-v));
}

// edges of node n occupy [n*9, n*9+9) because row = repeat(arange(N), 9)
__global__ void agg_kernel(const float* __restrict__ m, float* __restrict__ agg)
{
    int n = blockIdx.x;
    int hh = threadIdx.x;
    float a = 0.0f;
#pragma unroll
    for (int j = 0; j < KEDGE; j++)
        a += m[(long)(n * KEDGE + j) * HD + hh];
    agg[(long)n * HD + hh] = a;
}

__global__ void cat_kernel(const float* __restrict__ a, const float* __restrict__ b,
                           float* __restrict__ out)
{
    int idx = blockIdx.x * blockDim.x + threadIdx.x;
    if (idx >= N_NODES * 256) return;
    int n = idx >> 8;
    int c = idx & 255;
    out[idx] = (c < HD) ? a[(long)n * HD + c] : b[(long)n * HD + (c - HD)];
}

// v layout: (N, 3, 128): v[n*384 + c*128 + h]
__global__ void vupdate_kernel(const float* __restrict__ vin, float* __restrict__ vout,
                               const float* __restrict__ mv, const float* __restrict__ mvv,
                               const float* __restrict__ unit, const int* __restrict__ edges)
{
    int n = blockIdx.x;
    int hh = threadIdx.x;
    float a0 = vin[(long)n * 384 + 0 * HD + hh];
    float a1 = vin[(long)n * 384 + 1 * HD + hh];
    float a2 = vin[(long)n * 384 + 2 * HD + hh];
#pragma unroll
    for (int j = 0; j < KEDGE; j++) {
        int e = n * KEDGE + j;
        int c = edges[E_EDGES + e];
        float ux = unit[e * 3 + 0];
        float uy = unit[e * 3 + 1];
        float uz = unit[e * 3 + 2];
        float a = mv[(long)e * HD + hh];
        float b = mvv[(long)e * HD + hh];
        a0 += a * ux + b * vin[(long)c * 384 + 0 * HD + hh];
        a1 += a * uy + b * vin[(long)c * 384 + 1 * HD + hh];
        a2 += a * uz + b * vin[(long)c * 384 + 2 * HD + hh];
    }
    vout[(long)n * 384 + 0 * HD + hh] = a0;
    vout[(long)n * 384 + 1 * HD + hh] = a1;
    vout[(long)n * 384 + 2 * HD + hh] = a2;
}

__global__ void meanh_kernel(const float* __restrict__ hintra, float* __restrict__ meanh)
{
    int s = blockIdx.x;
    int k = threadIdx.x;
    float acc = 0.0f;
    for (int u = 0; u < SEGSZ; u++)
        acc += hintra[(long)(s * SEGSZ + u) * HD + k];
    meanh[s * HD + k] = acc * (1.0f / (float)SEGSZ);
}

__global__ void attn_kernel(const float* __restrict__ hintra, const float* __restrict__ meanh,
                            float* __restrict__ w)
{
    int s = blockIdx.x;
    int t = threadIdx.x;   // 0..511
    __shared__ float sm[HD];
    __shared__ float red[SEGSZ];
    int opp = s ^ 1;
    if (t < HD) sm[t] = meanh[opp * HD + t];
    __syncthreads();
    int node = s * SEGSZ + t;
    const float* hr = hintra + (long)node * HD;
    float sc = 0.0f;
#pragma unroll 8
    for (int k = 0; k < HD; k++) sc += hr[k] * sm[k];
    red[t] = sc;
    __syncthreads();
    for (int st = SEGSZ / 2; st > 0; st >>= 1) {
        if (t < st) red[t] = fmaxf(red[t], red[t + st]);
        __syncthreads();
    }
    float mx = red[0];
    __syncthreads();
    float ex = expf(sc - mx);
    red[t] = ex;
    __syncthreads();
    for (int st = SEGSZ / 2; st > 0; st >>= 1) {
        if (t < st) red[t] += red[t + st];
        __syncthreads();
    }
    w[node] = ex / red[0];
}

__global__ void v2n_kernel(const float* __restrict__ vp2, float* __restrict__ v2n)
{
    int idx = blockIdx.x * blockDim.x + threadIdx.x;
    if (idx >= N_NODES * HD) return;
    int n = idx / HD;
    int k = idx % HD;
    float a = vp2[(long)(n * 3 + 0) * HD + k];
    float b = vp2[(long)(n * 3 + 1) * HD + k];
    float c = vp2[(long)(n * 3 + 2) * HD + k];
    v2n[idx] = sqrtf(a * a + b * b + c * c + 1e-8f);
}

__global__ void pv_kernel(const float* __restrict__ vp1, const float* __restrict__ mix,
                          const float* __restrict__ Wf, float* __restrict__ pv)
{
    int n = blockIdx.x;
    int k = threadIdx.x;
    __shared__ float sd[3][HD];
    float hf = mix[(long)n * 256 + k];
    float bg = mix[(long)n * 256 + HD + k];
    float s = hf * bg;
    sd[0][k] = vp1[(long)(n * 3 + 0) * HD + k] * s;
    sd[1][k] = vp1[(long)(n * 3 + 1) * HD + k] * s;
    sd[2][k] = vp1[(long)(n * 3 + 2) * HD + k] * s;
    __syncthreads();
    if (k < 27) {
        int o = k / 3, c = k % 3;
        float acc = 0.0f;
#pragma unroll 8
        for (int kk = 0; kk < HD; kk++) acc += sd[c][kk] * Wf[kk * 9 + o];
        pv[(long)n * 27 + k] = acc;
    }
}

__global__ void predsum_kernel(const float* __restrict__ pv, float* __restrict__ pred)
{
    int s = blockIdx.x;
    int j = threadIdx.x;
    if (j >= 27) return;
    float acc = 0.0f;
    for (int u = 0; u < SEGSZ; u++)
        acc += pv[(long)(s * SEGSZ + u) * 27 + j];
    pred[s * 27 + j] = acc;
}

__global__ void final_kernel(const float* __restrict__ pred, float* __restrict__ out)
{
    int s = threadIdx.x;
    if (s >= NSEG) return;
    const float* p = pred + s * 27;   // p[o*3 + c]
#pragma unroll
    for (int r = 0; r < 3; r++) {
#pragma unroll
        for (int c = 0; c < 3; c++) {
            float A = p[0 * 3 + r] * p[1 * 3 + c]
                    + p[3 * 3 + r] * p[2 * 3 + c]
                    + p[4 * 3 + r] * p[5 * 3 + c]
                    + p[7 * 3 + r] * p[6 * 3 + c];
            out[s * 12 + r * 4 + c] = A * 100.0f;   // /(SF*SF), SF=0.1
        }
        out[s * 12 + r * 4 + 3] = p[8 * 3 + r] * 10.0f;  // /SF
    }
}

// ---------------- host driver ----------------
static void launch_gemm(const float* A, const float* B, const float* bias,
                        const float* rowscale, const float* residual, float* C,
                        int M, int N, int K, int silu_act)
{
    dim3 grid((N + 63) / 64, (M + 63) / 64);
    gemm_kernel<<<grid, 256>>>(A, B, bias, rowscale, residual, C, M, N, K, silu_act);
}

template <typename T>
static T* sym(const void* s)
{
    void* p = nullptr;
    cudaGetSymbolAddress(&p, s);
    return (T*)p;
}

extern "C" void kernel_launch(void* const* d_in, const int* in_sizes, int n_in,
                              void* d_out, int out_size)
{
    const float* X        = (const float*)d_in[0];
    const float* node_attr= (const float*)d_in[1];
    const float* edge_attr= (const float*)d_in[2];
    const float* W_in1    = (const float*)d_in[3];
    const float* b_in1    = (const float*)d_in[4];
    const float* W_in2    = (const float*)d_in[5];
    const float* b_in2    = (const float*)d_in[6];
    const float* We1      = (const float*)d_in[7];   // (4,292,128)
    const float* be1      = (const float*)d_in[8];   // (4,128)
    const float* We2      = (const float*)d_in[9];   // (4,128,128)
    const float* be2      = (const float*)d_in[10];
    const float* Wv       = (const float*)d_in[11];
    const float* Wvv      = (const float*)d_in[12];
    const float* Wh1      = (const float*)d_in[13];  // (4,256,128)
    const float* bh1      = (const float*)d_in[14];
    const float* Wh2      = (const float*)d_in[15];
    const float* bh2      = (const float*)d_in[16];
    const float* Wi1      = (const float*)d_in[17];
    const float* bi1      = (const float*)d_in[18];
    const float* Wi2      = (const float*)d_in[19];
    const float* bi2      = (const float*)d_in[20];
    const float* Wgv1     = (const float*)d_in[21];
    const float* Wgv2     = (const float*)d_in[22];
    const float* Wg1      = (const float*)d_in[23];  // (256,128)
    const float* bg1      = (const float*)d_in[24];
    const float* Wg2      = (const float*)d_in[25];  // (128,256)
    const float* bg2      = (const float*)d_in[26];
    const float* Wf       = (const float*)d_in[27];  // (128,9)
    const int*   edges    = (const int*)d_in[28];    // (2,E)
    float* out = (float*)d_out;

    float* p_t0     = sym<float>(g_t0);
    float* p_h      = sym<float>(g_h);
    float* p_Ar     = sym<float>(g_Ar);
    float* p_Ac     = sym<float>(g_Ac);
    float* p_agg    = sym<float>(g_agg);
    float* p_u      = sym<float>(g_u);
    float* p_hintra = sym<float>(g_hintra);
    float* p_v2n    = sym<float>(g_v2n);
    float* p_cat    = sym<float>(g_cat);
    float* p_mix    = sym<float>(g_mix);
    float* p_ef     = sym<float>(g_ef);
    float* p_epre   = sym<float>(g_epre);
    float* p_t      = sym<float>(g_t);
    float* p_m      = sym<float>(g_m);
    float* p_mv     = sym<float>(g_mv);
    float* p_mvv    = sym<float>(g_mvv);
    float* p_unit   = sym<float>(g_unit);
    float* p_va     = sym<float>(g_va);
    float* p_vb     = sym<float>(g_vb);
    float* p_vp1    = sym<float>(g_vp1);
    float* p_vp2    = sym<float>(g_vp2);
    float* p_w      = sym<float>(g_w);
    float* p_meanh  = sym<float>(g_meanh);
    float* p_pv     = sym<float>(g_pv);
    float* p_pred   = sym<float>(g_pred);

    // zero initial v
    zero_kernel<<<(N_NODES * 3 * HD + 255) / 256, 256>>>(p_va, N_NODES * 3 * HD);

    // edge geometry + [rbf | edge_attr] features
    edge_geom_kernel<<<(E_EDGES + 255) / 256, 256>>>(X, edge_attr, edges, p_unit, p_ef);

    // h = silu(node_attr @ W_in1 + b_in1) @ W_in2 + b_in2
    launch_gemm(node_attr, W_in1, b_in1, nullptr, nullptr, p_t0, N_NODES, HD, 64, 1);
    launch_gemm(p_t0, W_in2, b_in2, nullptr, nullptr, p_h, N_NODES, HD, HD, 0);

    float* vin = p_va;
    float* vout = p_vb;

    for (int i = 0; i < 4; i++) {
        const float* We1_i = We1 + (long)i * 292 * HD;
        const float* W_r   = We1_i;                 // rows 0..127
        const float* W_c   = We1_i + 128 * HD;      // rows 128..255
        const float* W_ef  = We1_i + 256 * HD;      // rows 256..291 (36 rows)
        const float* be1_i = be1 + i * HD;
        const float* We2_i = We2 + (long)i * HD * HD;
        const float* be2_i = be2 + i * HD;
        const float* Wv_i  = Wv  + (long)i * HD * HD;
        const float* Wvv_i = Wvv + (long)i * HD * HD;
        const float* Wh1_i = Wh1 + (long)i * 256 * HD;
        const float* bh1_i = bh1 + i * HD;
        const float* Wh2_i = Wh2 + (long)i * HD * HD;
        const float* bh2_i = bh2 + i * HD;
        const float* Wi1_i = Wi1 + (long)i * HD * HD;
        const float* bi1_i = bi1 + i * HD;
        const float* Wi2_i = Wi2 + (long)i * HD * HD;
        const float* bi2_i = bi2 + i * HD;

        // factorized edge-MLP input projection
        launch_gemm(p_h, W_r, nullptr, nullptr, nullptr, p_Ar, N_NODES, HD, HD, 0);
        launch_gemm(p_h, W_c, nullptr, nullptr, nullptr, p_Ac, N_NODES, HD, HD, 0);
        launch_gemm(p_ef, W_ef, be1_i, nullptr, nullptr, p_epre, E_EDGES, HD, 36, 0);
        edge_combine_kernel<<<E_EDGES, HD>>>(p_Ar, p_Ac, p_epre, edges, p_t);

        // m = t @ We2 + be2
        launch_gemm(p_t, We2_i, be2_i, nullptr, nullptr, p_m, E_EDGES, HD, HD, 0);

        // agg (edges sorted by row)
        agg_kernel<<<N_NODES, HD>>>(p_m, p_agg);

        // h_intra = h + silu([h|agg] @ Wh1 + bh1) @ Wh2 + bh2
        cat_kernel<<<(N_NODES * 256 + 255) / 256, 256>>>(p_h, p_agg, p_cat);
        launch_gemm(p_cat, Wh1_i, bh1_i, nullptr, nullptr, p_u, N_NODES, HD, 256, 1);
        launch_gemm(p_u, Wh2_i, bh2_i, nullptr, p_h, p_hintra, N_NODES, HD, HD, 0);

        // vector channel update
        launch_gemm(p_m, Wv_i,  nullptr, nullptr, nullptr, p_mv,  E_EDGES, HD, HD, 0);
        launch_gemm(p_m, Wvv_i, nullptr, nullptr, nullptr, p_mvv, E_EDGES, HD, HD, 0);
        vupdate_kernel<<<N_NODES, HD>>>(vin, vout, p_mv, p_mvv, p_unit, edges);

        // segment attention
        meanh_kernel<<<NSEG, HD>>>(p_hintra, p_meanh);
        attn_kernel<<<NSEG, SEGSZ>>>(p_hintra, p_meanh, p_w);
        launch_gemm(p_hintra, Wi1_i, bi1_i, p_w, nullptr, p_u, N_NODES, HD, HD, 1);
        launch_gemm(p_u, Wi2_i, bi2_i, nullptr, p_hintra, p_h, N_NODES, HD, HD, 0);

        // swap v buffers
        float* tmp = vin; vin = vout; vout = tmp;
    }
    // after 4 layers final v is in `vin`

    // v1 / v2 projections: treat v as (3N, 128)
    launch_gemm(vin, Wgv1, nullptr, nullptr, nullptr, p_vp1, 3 * N_NODES, HD, HD, 0);
    launch_gemm(vin, Wgv2, nullptr, nullptr, nullptr, p_vp2, 3 * N_NODES, HD, HD, 0);
    v2n_kernel<<<(N_NODES * HD + 255) / 256, 256>>>(p_vp2, p_v2n);

    // mix = silu([h|v2n] @ Wg1 + bg1) @ Wg2 + bg2
    cat_kernel<<<(N_NODES * 256 + 255) / 256, 256>>>(p_h, p_v2n, p_cat);
    launch_gemm(p_cat, Wg1, bg1, nullptr, nullptr, p_u, N_NODES, HD, 256, 1);
    launch_gemm(p_u, Wg2, bg2, nullptr, nullptr, p_mix, N_NODES, 256, HD, 0);

    // pv + segment reduce + epilogue
    pv_kernel<<<N_NODES, HD>>>(p_vp1, p_mix, Wf, p_pv);
    predsum_kernel<<<NSEG, 32>>>(p_pv, p_pred);
    final_kernel<<<1, 32>>>(p_pred, out);
}

// round 2
// speedup vs baseline: 1.1922x; 1.1922x over previous
#include <cuda_runtime.h>
#include <math.h>

#define N_NODES 16384
#define E_EDGES 147456
#define HD 128
#define NSEG 32
#define SEGSZ 512
#define KEDGE 9

// ---------------- scratch (device globals; no allocation at runtime) ----------------
__device__ float g_t0[N_NODES * HD];
__device__ float g_h[N_NODES * HD];
__device__ float g_Ar[N_NODES * HD];
__device__ float g_Ac[N_NODES * HD];
__device__ float g_agg[N_NODES * HD];
__device__ float g_u[N_NODES * HD];
__device__ float g_hintra[N_NODES * HD];
__device__ float g_v2n[N_NODES * HD];
__device__ float g_cat[N_NODES * 2 * HD];
__device__ float g_mix[N_NODES * 2 * HD];
__device__ float g_ef[E_EDGES * 36];
__device__ float g_epre[E_EDGES * HD];
__device__ float g_t[E_EDGES * HD];
__device__ float g_m[E_EDGES * HD];
__device__ float g_mv[E_EDGES * HD];
__device__ float g_mvv[E_EDGES * HD];
__device__ float g_unit[E_EDGES * 3];
__device__ float g_va[N_NODES * 3 * HD];
__device__ float g_vb[N_NODES * 3 * HD];
__device__ float g_vp1[N_NODES * 3 * HD];
__device__ float g_vp2[N_NODES * 3 * HD];
__device__ float g_w[N_NODES];
__device__ float g_meanh[NSEG * HD];
__device__ float g_pv[N_NODES * 27];
__device__ float g_pred[NSEG * 27];

// ---------------- packed f32x2 helpers ----------------
__device__ __forceinline__ unsigned long long pack2(float lo, float hi) {
    unsigned long long r;
    asm("mov.b64 %0, {%1, %2};" : "=l"(r) : "f"(lo), "f"(hi));
    return r;
}
__device__ __forceinline__ unsigned long long dup2(float v) {
    unsigned long long r;
    asm("mov.b64 %0, {%1, %1};" : "=l"(r) : "f"(v));
    return r;
}
__device__ __forceinline__ void fma2(unsigned long long& acc, unsigned long long a, unsigned long long b) {
    asm("fma.rn.f32x2 %0, %1, %2, %0;" : "+l"(acc) : "l"(a), "l"(b));
}
__device__ __forceinline__ void unpack2(unsigned long long p, float& lo, float& hi) {
    asm("mov.b64 {%0, %1}, %2;" : "=f"(lo), "=f"(hi) : "l"(p));
}

// ---------------- fast fp32 GEMM ----------------
// C = f( rowscale[m] * (A@B) + bias[n] ) + residual
// A: (M,K) row-major, B: (K,N) row-major. Block tile BM x 128, BK=16, 256 threads.
// Thread tile TM x 8, packed f32x2 accumulation. Requires: M % BM == 0, N % 128 == 0, K % 4 == 0.
template <int BM, int TM>
__global__ __launch_bounds__(256)
void gemm_tile_kernel(const float* __restrict__ A, const float* __restrict__ B,
                      const float* __restrict__ bias, const float* __restrict__ rowscale,
                      const float* __restrict__ residual, float* __restrict__ C,
                      int M, int N, int K, int silu_act)
{
    __shared__ float As[2][16][BM];
    __shared__ float Bs[2][16][128];
    const int bm = blockIdx.y * BM;
    const int bn = blockIdx.x * 128;
    const int t = threadIdx.x;
    const int ty = t >> 4;   // 0..15
    const int tx = t & 15;   // 0..15

    const int ALOADS = (BM * 16) / 1024;   // float4 loads per thread for A tile

    unsigned long long acc2[TM][4];
#pragma unroll
    for (int i = 0; i < TM; i++)
#pragma unroll
        for (int j = 0; j < 4; j++) acc2[i][j] = 0ull;

    const int tiles = (K + 15) >> 4;

    // prologue: load tile 0 into buffer 0
    {
#pragma unroll
        for (int r = 0; r < ALOADS; r++) {
            int idx = r * 256 + t;
            int row = idx >> 2, kc = (idx & 3) << 2;
            float4 v = make_float4(0.f, 0.f, 0.f, 0.f);
            if (kc < K) v = *(const float4*)&A[(long)(bm + row) * K + kc];
            As[0][kc + 0][row] = v.x; As[0][kc + 1][row] = v.y;
            As[0][kc + 2][row] = v.z; As[0][kc + 3][row] = v.w;
        }
#pragma unroll
        for (int r = 0; r < 2; r++) {
            int idx = r * 256 + t;
            int k = idx >> 5, n4 = (idx & 31) << 2;
            float4 v = make_float4(0.f, 0.f, 0.f, 0.f);
            if (k < K) v = *(const float4*)&B[(long)k * N + bn + n4];
            *(float4*)&Bs[0][k][n4] = v;
        }
    }
    __syncthreads();

    for (int tt = 0; tt < tiles; tt++) {
        const int buf = tt & 1;
        float4 pa[ALOADS], pb[2];
        if (tt + 1 < tiles) {
            const int k0n = (tt + 1) << 4;
#pragma unroll
            for (int r = 0; r < ALOADS; r++) {
                int idx = r * 256 + t;
                int row = idx >> 2, kc = (idx & 3) << 2;
                pa[r] = make_float4(0.f, 0.f, 0.f, 0.f);
                if (k0n + kc < K) pa[r] = *(const float4*)&A[(long)(bm + row) * K + k0n + kc];
            }
#pragma unroll
            for (int r = 0; r < 2; r++) {
                int idx = r * 256 + t;
                int k = idx >> 5, n4 = (idx & 31) << 2;
                pb[r] = make_float4(0.f, 0.f, 0.f, 0.f);
                if (k0n + k < K) pb[r] = *(const float4*)&B[(long)(k0n + k) * N + bn + n4];
            }
        }

#pragma unroll
        for (int k = 0; k < 16; k++) {
            float a[TM];
#pragma unroll
            for (int i = 0; i < TM; i += 4) {
                float4 av = *(const float4*)&As[buf][k][ty * TM + i];
                a[i] = av.x; a[i + 1] = av.y; a[i + 2] = av.z; a[i + 3] = av.w;
            }
            float4 b0 = *(const float4*)&Bs[buf][k][tx * 8];
            float4 b1 = *(const float4*)&Bs[buf][k][tx * 8 + 4];
            unsigned long long b2[4];
            b2[0] = pack2(b0.x, b0.y);
            b2[1] = pack2(b0.z, b0.w);
            b2[2] = pack2(b1.x, b1.y);
            b2[3] = pack2(b1.z, b1.w);
#pragma unroll
            for (int i = 0; i < TM; i++) {
                unsigned long long a2 = dup2(a[i]);
#pragma unroll
                for (int j = 0; j < 4; j++)
                    fma2(acc2[i][j], a2, b2[j]);
            }
        }

        if (tt + 1 < tiles) {
            const int nb = buf ^ 1;
#pragma unroll
            for (int r = 0; r < ALOADS; r++) {
                int idx = r * 256 + t;
                int row = idx >> 2, kc = (idx & 3) << 2;
                As[nb][kc + 0][row] = pa[r].x; As[nb][kc + 1][row] = pa[r].y;
                As[nb][kc + 2][row] = pa[r].z; As[nb][kc + 3][row] = pa[r].w;
            }
#pragma unroll
            for (int r = 0; r < 2; r++) {
                int idx = r * 256 + t;
                int k = idx >> 5, n4 = (idx & 31) << 2;
                *(float4*)&Bs[nb][k][n4] = pb[r];
            }
        }
        __syncthreads();
    }

    // epilogue
#pragma unroll
    for (int i = 0; i < TM; i++) {
        const int m = bm + ty * TM + i;
        const float rs = rowscale ? rowscale[m] : 1.0f;
        float cv[8];
#pragma unroll
        for (int j = 0; j < 4; j++) unpack2(acc2[i][j], cv[2 * j], cv[2 * j + 1]);
#pragma unroll
        for (int j = 0; j < 8; j++) {
            int n = bn + tx * 8 + j;
            float v = cv[j] * rs;
            if (bias) v += bias[n];
            if (silu_act) v = v / (1.0f + __expf(-v));
            if (residual) v += residual[(long)m * N + n];
            cv[j] = v;
        }
        float4* cp = (float4*)&C[(long)m * N + bn + tx * 8];
        cp[0] = make_float4(cv[0], cv[1], cv[2], cv[3]);
        cp[1] = make_float4(cv[4], cv[5], cv[6], cv[7]);
    }
}

// ---------------- small kernels ----------------
__global__ void zero_kernel(float* p, int n) {
    int i = blockIdx.x * blockDim.x + threadIdx.x;
    if (i < n) p[i] = 0.0f;
}

__global__ void edge_geom_kernel(const float* __restrict__ X, const float* __restrict__ edge_attr,
                                 const int* __restrict__ edges,
                                 float* __restrict__ unit, float* __restrict__ ef)
{
    int e = blockIdx.x * blockDim.x + threadIdx.x;
    if (e >= E_EDGES) return;
    int r = edges[e];
    int c = edges[E_EDGES + e];
    float dx = X[r * 3 + 0] - X[c * 3 + 0];
    float dy = X[r * 3 + 1] - X[c * 3 + 1];
    float dz = X[r * 3 + 2] - X[c * 3 + 2];
    float norm = sqrtf(dx * dx + dy * dy + dz * dz) + 1e-8f;
    float invn = 1.0f / norm;
    unit[e * 3 + 0] = dx * invn;
    unit[e * 3 + 1] = dy * invn;
    unit[e * 3 + 2] = dz * invn;
    const float PI_ = 3.14159265358979323846f;
    float cn = fminf(norm, 1.0f);
    float cut = 0.5f * (cosf(PI_ * cn) + 1.0f);
    float f = cut * invn;
#pragma unroll
    for (int j = 0; j < 20; j++)
        ef[e * 36 + j] = sinf(norm * PI_ * (float)(j + 1)) * f;
#pragma unroll
    for (int j = 0; j < 16; j++)
        ef[e * 36 + 20 + j] = edge_attr[e * 16 + j];
}

// t[e] = silu(Ar[row[e]] + Ac[col[e]] + epre[e])   (epre already includes be1)
__global__ void edge_combine_kernel(const float* __restrict__ Ar, const float* __restrict__ Ac,
                                    const float* __restrict__ epre, const int* __restrict__ edges,
                                    float* __restrict__ out)
{
    int e = blockIdx.x;
    int hh = threadIdx.x;
    int r = edges[e];
    int c = edges[E_EDGES + e];
    float v = Ar[(long)r * HD + hh] + Ac[(long)c * HD + hh] + epre[(long)e * HD + hh];
    out[(long)e * HD + hh] = v / (1.0f + __expf(-v));
}

// edges of node n occupy [n*9, n*9+9) because row = repeat(arange(N), 9)
__global__ void agg_kernel(const float* __restrict__ m, float* __restrict__ agg)
{
    int n = blockIdx.x;
    int hh = threadIdx.x;
    float a = 0.0f;
#pragma unroll
    for (int j = 0; j < KEDGE; j++)
        a += m[(long)(n * KEDGE + j) * HD + hh];
    agg[(long)n * HD + hh] = a;
}

__global__ void cat_kernel(const float* __restrict__ a, const float* __restrict__ b,
                           float* __restrict__ out)
{
    int idx = blockIdx.x * blockDim.x + threadIdx.x;
    if (idx >= N_NODES * 256) return;
    int n = idx >> 8;
    int c = idx & 255;
    out[idx] = (c < HD) ? a[(long)n * HD + c] : b[(long)n * HD + (c - HD)];
}

// v layout: (N, 3, 128): v[n*384 + c*128 + h]
__global__ void vupdate_kernel(const float* __restrict__ vin, float* __restrict__ vout,
                               const float* __restrict__ mv, const float* __restrict__ mvv,
                               const float* __restrict__ unit, const int* __restrict__ edges)
{
    int n = blockIdx.x;
    int hh = threadIdx.x;
    float a0 = vin[(long)n * 384 + 0 * HD + hh];
    float a1 = vin[(long)n * 384 + 1 * HD + hh];
    float a2 = vin[(long)n * 384 + 2 * HD + hh];
#pragma unroll
    for (int j = 0; j < KEDGE; j++) {
        int e = n * KEDGE + j;
        int c = edges[E_EDGES + e];
        float ux = unit[e * 3 + 0];
        float uy = unit[e * 3 + 1];
        float uz = unit[e * 3 + 2];
        float a = mv[(long)e * HD + hh];
        float b = mvv[(long)e * HD + hh];
        a0 += a * ux + b * vin[(long)c * 384 + 0 * HD + hh];
        a1 += a * uy + b * vin[(long)c * 384 + 1 * HD + hh];
        a2 += a * uz + b * vin[(long)c * 384 + 2 * HD + hh];
    }
    vout[(long)n * 384 + 0 * HD + hh] = a0;
    vout[(long)n * 384 + 1 * HD + hh] = a1;
    vout[(long)n * 384 + 2 * HD + hh] = a2;
}

__global__ void meanh_kernel(const float* __restrict__ hintra, float* __restrict__ meanh)
{
    int s = blockIdx.x;
    int k = threadIdx.x;
    float acc = 0.0f;
    for (int u = 0; u < SEGSZ; u++)
        acc += hintra[(long)(s * SEGSZ + u) * HD + k];
    meanh[s * HD + k] = acc * (1.0f / (float)SEGSZ);
}

__global__ void attn_kernel(const float* __restrict__ hintra, const float* __restrict__ meanh,
                            float* __restrict__ w)
{
    int s = blockIdx.x;
    int t = threadIdx.x;   // 0..511
    __shared__ float sm[HD];
    __shared__ float red[SEGSZ];
    int opp = s ^ 1;
    if (t < HD) sm[t] = meanh[opp * HD + t];
    __syncthreads();
    int node = s * SEGSZ + t;
    const float* hr = hintra + (long)node * HD;
    float sc = 0.0f;
#pragma unroll 8
    for (int k = 0; k < HD; k++) sc += hr[k] * sm[k];
    red[t] = sc;
    __syncthreads();
    for (int st = SEGSZ / 2; st > 0; st >>= 1) {
        if (t < st) red[t] = fmaxf(red[t], red[t + st]);
        __syncthreads();
    }
    float mx = red[0];
    __syncthreads();
    float ex = expf(sc - mx);
    red[t] = ex;
    __syncthreads();
    for (int st = SEGSZ / 2; st > 0; st >>= 1) {
        if (t < st) red[t] += red[t + st];
        __syncthreads();
    }
    w[node] = ex / red[0];
}

__global__ void v2n_kernel(const float* __restrict__ vp2, float* __restrict__ v2n)
{
    int idx = blockIdx.x * blockDim.x + threadIdx.x;
    if (idx >= N_NODES * HD) return;
    int n = idx / HD;
    int k = idx % HD;
    float a = vp2[(long)(n * 3 + 0) * HD + k];
    float b = vp2[(long)(n * 3 + 1) * HD + k];
    float c = vp2[(long)(n * 3 + 2) * HD + k];
    v2n[idx] = sqrtf(a * a + b * b + c * c + 1e-8f);
}

__global__ void pv_kernel(const float* __restrict__ vp1, const float* __restrict__ mix,
                          const float* __restrict__ Wf, float* __restrict__ pv)
{
    int n = blockIdx.x;
    int k = threadIdx.x;
    __shared__ float sd[3][HD];
    float hf = mix[(long)n * 256 + k];
    float bg = mix[(long)n * 256 + HD + k];
    float s = hf * bg;
    sd[0][k] = vp1[(long)(n * 3 + 0) * HD + k] * s;
    sd[1][k] = vp1[(long)(n * 3 + 1) * HD + k] * s;
    sd[2][k] = vp1[(long)(n * 3 + 2) * HD + k] * s;
    __syncthreads();
    if (k < 27) {
        int o = k / 3, c = k % 3;
        float acc = 0.0f;
#pragma unroll 8
        for (int kk = 0; kk < HD; kk++) acc += sd[c][kk] * Wf[kk * 9 + o];
        pv[(long)n * 27 + k] = acc;
    }
}

__global__ void predsum_kernel(const float* __restrict__ pv, float* __restrict__ pred)
{
    int s = blockIdx.x;
    int j = threadIdx.x;
    if (j >= 27) return;
    float acc = 0.0f;
    for (int u = 0; u < SEGSZ; u++)
        acc += pv[(long)(s * SEGSZ + u) * 27 + j];
    pred[s * 27 + j] = acc;
}

__global__ void final_kernel(const float* __restrict__ pred, float* __restrict__ out)
{
    int s = threadIdx.x;
    if (s >= NSEG) return;
    const float* p = pred + s * 27;   // p[o*3 + c]
#pragma unroll
    for (int r = 0; r < 3; r++) {
#pragma unroll
        for (int c = 0; c < 3; c++) {
            float A = p[0 * 3 + r] * p[1 * 3 + c]
                    + p[3 * 3 + r] * p[2 * 3 + c]
                    + p[4 * 3 + r] * p[5 * 3 + c]
                    + p[7 * 3 + r] * p[6 * 3 + c];
            out[s * 12 + r * 4 + c] = A * 100.0f;   // /(SF*SF), SF=0.1
        }
        out[s * 12 + r * 4 + 3] = p[8 * 3 + r] * 10.0f;  // /SF
    }
}

// ---------------- host driver ----------------
static void launch_gemm(const float* A, const float* B, const float* bias,
                        const float* rowscale, const float* residual, float* C,
                        int M, int N, int K, int silu_act)
{
    if (M >= 65536) {
        dim3 grid(N / 128, M / 128);
        gemm_tile_kernel<128, 8><<<grid, 256>>>(A, B, bias, rowscale, residual, C, M, N, K, silu_act);
    } else {
        dim3 grid(N / 128, M / 64);
        gemm_tile_kernel<64, 4><<<grid, 256>>>(A, B, bias, rowscale, residual, C, M, N, K, silu_act);
    }
}

template <typename T>
static T* sym(const void* s)
{
    void* p = nullptr;
    cudaGetSymbolAddress(&p, s);
    return (T*)p;
}

extern "C" void kernel_launch(void* const* d_in, const int* in_sizes, int n_in,
                              void* d_out, int out_size)
{
    const float* X        = (const float*)d_in[0];
    const float* node_attr= (const float*)d_in[1];
    const float* edge_attr= (const float*)d_in[2];
    const float* W_in1    = (const float*)d_in[3];
    const float* b_in1    = (const float*)d_in[4];
    const float* W_in2    = (const float*)d_in[5];
    const float* b_in2    = (const float*)d_in[6];
    const float* We1      = (const float*)d_in[7];   // (4,292,128)
    const float* be1      = (const float*)d_in[8];   // (4,128)
    const float* We2      = (const float*)d_in[9];   // (4,128,128)
    const float* be2      = (const float*)d_in[10];
    const float* Wv       = (const float*)d_in[11];
    const float* Wvv      = (const float*)d_in[12];
    const float* Wh1      = (const float*)d_in[13];  // (4,256,128)
    const float* bh1      = (const float*)d_in[14];
    const float* Wh2      = (const float*)d_in[15];
    const float* bh2      = (const float*)d_in[16];
    const float* Wi1      = (const float*)d_in[17];
    const float* bi1      = (const float*)d_in[18];
    const float* Wi2      = (const float*)d_in[19];
    const float* bi2      = (const float*)d_in[20];
    const float* Wgv1     = (const float*)d_in[21];
    const float* Wgv2     = (const float*)d_in[22];
    const float* Wg1      = (const float*)d_in[23];  // (256,128)
    const float* bg1      = (const float*)d_in[24];
    const float* Wg2      = (const float*)d_in[25];  // (128,256)
    const float* bg2      = (const float*)d_in[26];
    const float* Wf       = (const float*)d_in[27];  // (128,9)
    const int*   edges    = (const int*)d_in[28];    // (2,E)
    float* out = (float*)d_out;

    float* p_t0     = sym<float>(g_t0);
    float* p_h      = sym<float>(g_h);
    float* p_Ar     = sym<float>(g_Ar);
    float* p_Ac     = sym<float>(g_Ac);
    float* p_agg    = sym<float>(g_agg);
    float* p_u      = sym<float>(g_u);
    float* p_hintra = sym<float>(g_hintra);
    float* p_v2n    = sym<float>(g_v2n);
    float* p_cat    = sym<float>(g_cat);
    float* p_mix    = sym<float>(g_mix);
    float* p_ef     = sym<float>(g_ef);
    float* p_epre   = sym<float>(g_epre);
    float* p_t      = sym<float>(g_t);
    float* p_m      = sym<float>(g_m);
    float* p_mv     = sym<float>(g_mv);
    float* p_mvv    = sym<float>(g_mvv);
    float* p_unit   = sym<float>(g_unit);
    float* p_va     = sym<float>(g_va);
    float* p_vb     = sym<float>(g_vb);
    float* p_vp1    = sym<float>(g_vp1);
    float* p_vp2    = sym<float>(g_vp2);
    float* p_w      = sym<float>(g_w);
    float* p_meanh  = sym<float>(g_meanh);
    float* p_pv     = sym<float>(g_pv);
    float* p_pred   = sym<float>(g_pred);

    // zero initial v
    zero_kernel<<<(N_NODES * 3 * HD + 255) / 256, 256>>>(p_va, N_NODES * 3 * HD);

    // edge geometry + [rbf | edge_attr] features
    edge_geom_kernel<<<(E_EDGES + 255) / 256, 256>>>(X, edge_attr, edges, p_unit, p_ef);

    // h = silu(node_attr @ W_in1 + b_in1) @ W_in2 + b_in2
    launch_gemm(node_attr, W_in1, b_in1, nullptr, nullptr, p_t0, N_NODES, HD, 64, 1);
    launch_gemm(p_t0, W_in2, b_in2, nullptr, nullptr, p_h, N_NODES, HD, HD, 0);

    float* vin = p_va;
    float* vout = p_vb;

    for (int i = 0; i < 4; i++) {
        const float* We1_i = We1 + (long)i * 292 * HD;
        const float* W_r   = We1_i;                 // rows 0..127
        const float* W_c   = We1_i + 128 * HD;      // rows 128..255
        const float* W_ef  = We1_i + 256 * HD;      // rows 256..291 (36 rows)
        const float* be1_i = be1 + i * HD;
        const float* We2_i = We2 + (long)i * HD * HD;
        const float* be2_i = be2 + i * HD;
        const float* Wv_i  = Wv  + (long)i * HD * HD;
        const float* Wvv_i = Wvv + (long)i * HD * HD;
        const float* Wh1_i = Wh1 + (long)i * 256 * HD;
        const float* bh1_i = bh1 + i * HD;
        const float* Wh2_i = Wh2 + (long)i * HD * HD;
        const float* bh2_i = bh2 + i * HD;
        const float* Wi1_i = Wi1 + (long)i * HD * HD;
        const float* bi1_i = bi1 + i * HD;
        const float* Wi2_i = Wi2 + (long)i * HD * HD;
        const float* bi2_i = bi2 + i * HD;

        // factorized edge-MLP input projection
        launch_gemm(p_h, W_r, nullptr, nullptr, nullptr, p_Ar, N_NODES, HD, HD, 0);
        launch_gemm(p_h, W_c, nullptr, nullptr, nullptr, p_Ac, N_NODES, HD, HD, 0);
        launch_gemm(p_ef, W_ef, be1_i, nullptr, nullptr, p_epre, E_EDGES, HD, 36, 0);
        edge_combine_kernel<<<E_EDGES, HD>>>(p_Ar, p_Ac, p_epre, edges, p_t);

        // m = t @ We2 + be2
        launch_gemm(p_t, We2_i, be2_i, nullptr, nullptr, p_m, E_EDGES, HD, HD, 0);

        // agg (edges sorted by row)
        agg_kernel<<<N_NODES, HD>>>(p_m, p_agg);

        // h_intra = h + silu([h|agg] @ Wh1 + bh1) @ Wh2 + bh2
        cat_kernel<<<(N_NODES * 256 + 255) / 256, 256>>>(p_h, p_agg, p_cat);
        launch_gemm(p_cat, Wh1_i, bh1_i, nullptr, nullptr, p_u, N_NODES, HD, 256, 1);
        launch_gemm(p_u, Wh2_i, bh2_i, nullptr, p_h, p_hintra, N_NODES, HD, HD, 0);

        // vector channel update
        launch_gemm(p_m, Wv_i,  nullptr, nullptr, nullptr, p_mv,  E_EDGES, HD, HD, 0);
        launch_gemm(p_m, Wvv_i, nullptr, nullptr, nullptr, p_mvv, E_EDGES, HD, HD, 0);
        vupdate_kernel<<<N_NODES, HD>>>(vin, vout, p_mv, p_mvv, p_unit, edges);

        // segment attention
        meanh_kernel<<<NSEG, HD>>>(p_hintra, p_meanh);
        attn_kernel<<<NSEG, SEGSZ>>>(p_hintra, p_meanh, p_w);
        launch_gemm(p_hintra, Wi1_i, bi1_i, p_w, nullptr, p_u, N_NODES, HD, HD, 1);
        launch_gemm(p_u, Wi2_i, bi2_i, nullptr, p_hintra, p_h, N_NODES, HD, HD, 0);

        // swap v buffers
        float* tmp = vin; vin = vout; vout = tmp;
    }
    // after 4 layers final v is in `vin`

    // v1 / v2 projections: treat v as (3N, 128)
    launch_gemm(vin, Wgv1, nullptr, nullptr, nullptr, p_vp1, 3 * N_NODES, HD, HD, 0);
    launch_gemm(vin, Wgv2, nullptr, nullptr, nullptr, p_vp2, 3 * N_NODES, HD, HD, 0);
    v2n_kernel<<<(N_NODES * HD + 255) / 256, 256>>>(p_vp2, p_v2n);

    // mix = silu([h|v2n] @ Wg1 + bg1) @ Wg2 + bg2
    cat_kernel<<<(N_NODES * 256 + 255) / 256, 256>>>(p_h, p_v2n, p_cat);
    launch_gemm(p_cat, Wg1, bg1, nullptr, nullptr, p_u, N_NODES, HD, 256, 1);
    launch_gemm(p_u, Wg2, bg2, nullptr, nullptr, p_mix, N_NODES, 256, HD, 0);

    // pv + segment reduce + epilogue
    pv_kernel<<<N_NODES, HD>>>(p_vp1, p_mix, Wf, p_pv);
    predsum_kernel<<<NSEG, 32>>>(p_pv, p_pred);
    final_kernel<<<1, 32>>>(p_pred, out);
}

// round 3
// speedup vs baseline: 1.3587x; 1.1397x over previous
#include <cuda_runtime.h>
#include <math.h>

#define N_NODES 16384
#define E_EDGES 147456
#define HD 128
#define NSEG 32
#define SEGSZ 512
#define KEDGE 9
#define EFK 48   // padded [rbf|edge_attr] feature width (36 real + 12 zero)

#define FLAG_SILU 1
#define FLAG_RESPRE 2

// ---------------- scratch (device globals; no allocation at runtime) ----------------
__device__ float g_t0[N_NODES * HD];
__device__ float g_h[N_NODES * HD];
__device__ float g_ArAc[N_NODES * 2 * HD];
__device__ float g_agg[N_NODES * HD];
__device__ float g_u[N_NODES * HD];
__device__ float g_hintra[N_NODES * HD];
__device__ float g_v2n[N_NODES * HD];
__device__ float g_mix[N_NODES * 2 * HD];
__device__ float g_ef[E_EDGES * EFK];
__device__ float g_epre[E_EDGES * HD];
__device__ float g_t[E_EDGES * HD];
__device__ float g_mcat[(long)E_EDGES * 256];   // [m | mvv]
__device__ float g_unit[E_EDGES * 3];
__device__ float g_va[N_NODES * 3 * HD];
__device__ float g_vb[N_NODES * 3 * HD];
__device__ float g_Mmat[N_NODES * 3 * HD];
__device__ float g_vagg[N_NODES * 3 * HD];
__device__ float g_vp[(long)N_NODES * 3 * 256]; // [v@Wgv1 | v@Wgv2]
__device__ float g_w[N_NODES];
__device__ float g_meanh[NSEG * HD];
__device__ float g_pv[N_NODES * 27];
__device__ float g_pred[NSEG * 27];
// packed weights
__device__ float g_We1cat[4 * HD * 256];
__device__ float g_Wef[4 * EFK * HD];
__device__ float g_W2v[4 * HD * HD];
__device__ float g_W2cat[4 * HD * 256];
__device__ float g_b2cat[4 * 256];
__device__ float g_Wgvcat[HD * 256];

// ---------------- packed f32x2 helpers ----------------
__device__ __forceinline__ unsigned long long pack2(float lo, float hi) {
    unsigned long long r;
    asm("mov.b64 %0, {%1, %2};" : "=l"(r) : "f"(lo), "f"(hi));
    return r;
}
__device__ __forceinline__ unsigned long long dup2(float v) {
    unsigned long long r;
    asm("mov.b64 %0, {%1, %1};" : "=l"(r) : "f"(v));
    return r;
}
__device__ __forceinline__ void fma2(unsigned long long& acc, unsigned long long a, unsigned long long b) {
    asm("fma.rn.f32x2 %0, %1, %2, %0;" : "+l"(acc) : "l"(a), "l"(b));
}
__device__ __forceinline__ void unpack2(unsigned long long p, float& lo, float& hi) {
    asm("mov.b64 {%0, %1}, %2;" : "=f"(lo), "=f"(hi) : "l"(p));
}

// ---------------- fp32 GEMM: 128x128 tile, 8x8/thread, BK=16, double-buffered ----------------
// C = post( rowscale[m]*(A@B) + bias[n] [,+res pre] [,silu] [,+res post] )
// Requires: M%128==0, N%128==0, K%16==0, A rows 16B-aligned (K%4==0).
__global__ __launch_bounds__(256, 1)
void gemm128(const float* __restrict__ A, const float* __restrict__ B,
             const float* __restrict__ bias, const float* __restrict__ rowscale,
             const float* __restrict__ res, float* __restrict__ C,
             int M, int N, int K, int flags)
{
    __shared__ float As[2][16][128];
    __shared__ float Bs[2][16][128];
    const int bm = blockIdx.y * 128;
    const int bn = blockIdx.x * 128;
    const int t = threadIdx.x;
    const int ty = t >> 4;   // 0..15
    const int tx = t & 15;   // 0..15

    unsigned long long acc2[8][4];
#pragma unroll
    for (int i = 0; i < 8; i++)
#pragma unroll
        for (int j = 0; j < 4; j++) acc2[i][j] = 0ull;

    const int tiles = K >> 4;

    // A load indices: 2 float4 per thread
    const int a_row0 = t >> 2;            // 0..63
    const int a_kc = (t & 3) << 2;        // 0,4,8,12
    // B load indices
    const int b_k0 = t >> 5;              // 0..7
    const int b_n4 = (t & 31) << 2;       // 0..124

    // prologue
    {
#pragma unroll
        for (int r = 0; r < 2; r++) {
            int row = a_row0 + r * 64;
            float4 v = *(const float4*)&A[(long)(bm + row) * K + a_kc];
            As[0][a_kc + 0][row] = v.x; As[0][a_kc + 1][row] = v.y;
            As[0][a_kc + 2][row] = v.z; As[0][a_kc + 3][row] = v.w;
        }
#pragma unroll
        for (int r = 0; r < 2; r++) {
            int k = b_k0 + r * 8;
            *(float4*)&Bs[0][k][b_n4] = *(const float4*)&B[(long)k * N + bn + b_n4];
        }
    }
    __syncthreads();

    for (int tt = 0; tt < tiles; tt++) {
        const int buf = tt & 1;
        float4 pa[2], pb[2];
        if (tt + 1 < tiles) {
            const int k0n = (tt + 1) << 4;
#pragma unroll
            for (int r = 0; r < 2; r++) {
                int row = a_row0 + r * 64;
                pa[r] = *(const float4*)&A[(long)(bm + row) * K + k0n + a_kc];
            }
#pragma unroll
            for (int r = 0; r < 2; r++) {
                int k = b_k0 + r * 8;
                pb[r] = *(const float4*)&B[(long)(k0n + k) * N + bn + b_n4];
            }
        }

#pragma unroll
        for (int k = 0; k < 16; k++) {
            float a[8];
            float4 a0 = *(const float4*)&As[buf][k][ty * 8];
            float4 a1 = *(const float4*)&As[buf][k][ty * 8 + 4];
            a[0] = a0.x; a[1] = a0.y; a[2] = a0.z; a[3] = a0.w;
            a[4] = a1.x; a[5] = a1.y; a[6] = a1.z; a[7] = a1.w;
            float4 b0 = *(const float4*)&Bs[buf][k][tx * 8];
            float4 b1 = *(const float4*)&Bs[buf][k][tx * 8 + 4];
            unsigned long long b2[4];
            b2[0] = pack2(b0.x, b0.y);
            b2[1] = pack2(b0.z, b0.w);
            b2[2] = pack2(b1.x, b1.y);
            b2[3] = pack2(b1.z, b1.w);
#pragma unroll
            for (int i = 0; i < 8; i++) {
                unsigned long long ad = dup2(a[i]);
#pragma unroll
                for (int j = 0; j < 4; j++)
                    fma2(acc2[i][j], ad, b2[j]);
            }
        }

        if (tt + 1 < tiles) {
            const int nb = buf ^ 1;
#pragma unroll
            for (int r = 0; r < 2; r++) {
                int row = a_row0 + r * 64;
                As[nb][a_kc + 0][row] = pa[r].x; As[nb][a_kc + 1][row] = pa[r].y;
                As[nb][a_kc + 2][row] = pa[r].z; As[nb][a_kc + 3][row] = pa[r].w;
            }
#pragma unroll
            for (int r = 0; r < 2; r++) {
                int k = b_k0 + r * 8;
                *(float4*)&Bs[nb][k][b_n4] = pb[r];
            }
        }
        __syncthreads();
    }

    const bool silu = (flags & FLAG_SILU) != 0;
    const bool respre = (flags & FLAG_RESPRE) != 0;
#pragma unroll
    for (int i = 0; i < 8; i++) {
        const int m = bm + ty * 8 + i;
        const float rs = rowscale ? rowscale[m] : 1.0f;
        float cv[8];
#pragma unroll
        for (int j = 0; j < 4; j++) unpack2(acc2[i][j], cv[2 * j], cv[2 * j + 1]);
        const long base = (long)m * N + bn + tx * 8;
#pragma unroll
        for (int j = 0; j < 8; j++) {
            float v = cv[j] * rs;
            if (bias) v += bias[bn + tx * 8 + j];
            if (respre && res) v += res[base + j];
            if (silu) v = v / (1.0f + __expf(-v));
            if (!respre && res) v += res[base + j];
            cv[j] = v;
        }
        float4* cp = (float4*)&C[base];
        cp[0] = make_float4(cv[0], cv[1], cv[2], cv[3]);
        cp[1] = make_float4(cv[4], cv[5], cv[6], cv[7]);
    }
}

// ---------------- weight packing (run once per launch; tiny) ----------------
__global__ void pack_We1cat_kernel(const float* __restrict__ We1, float* __restrict__ out)
{
    int idx = blockIdx.x * blockDim.x + threadIdx.x;
    if (idx >= 4 * HD * 256) return;
    int l = idx / (HD * 256);
    int rem = idx - l * HD * 256;
    int k = rem >> 8;
    int n = rem & 255;
    const float* base = We1 + (long)l * 292 * HD;
    out[idx] = (n < HD) ? base[k * HD + n] : base[(HD + k) * HD + (n - HD)];
}

__global__ void pack_Wef_kernel(const float* __restrict__ We1, float* __restrict__ out)
{
    int idx = blockIdx.x * blockDim.x + threadIdx.x;
    if (idx >= 4 * EFK * HD) return;
    int l = idx / (EFK * HD);
    int rem = idx - l * EFK * HD;
    int k = rem >> 7;
    int n = rem & 127;
    out[idx] = (k < 36) ? We1[(long)l * 292 * HD + (256 + k) * HD + n] : 0.0f;
}

__global__ void pack_W2cat_kernel(const float* __restrict__ We2, const float* __restrict__ W2v,
                                  float* __restrict__ out)
{
    int idx = blockIdx.x * blockDim.x + threadIdx.x;
    if (idx >= 4 * HD * 256) return;
    int l = idx / (HD * 256);
    int rem = idx - l * HD * 256;
    int k = rem >> 8;
    int n = rem & 255;
    out[idx] = (n < HD) ? We2[(long)l * HD * HD + k * HD + n]
                        : W2v[(long)l * HD * HD + k * HD + (n - HD)];
}

__global__ void pack_b2cat_kernel(const float* __restrict__ be2, const float* __restrict__ Wvv,
                                  float* __restrict__ out)
{
    int l = blockIdx.x;
    int n = threadIdx.x;  // 0..255
    if (n < HD) {
        out[l * 256 + n] = be2[l * HD + n];
    } else {
        int nn = n - HD;
        float acc = 0.0f;
        const float* w = Wvv + (long)l * HD * HD;
        const float* b = be2 + l * HD;
#pragma unroll 8
        for (int k = 0; k < HD; k++) acc += b[k] * w[k * HD + nn];
        out[l * 256 + n] = acc;
    }
}

__global__ void pack_Wgv_kernel(const float* __restrict__ Wgv1, const float* __restrict__ Wgv2,
                                float* __restrict__ out)
{
    int idx = blockIdx.x * blockDim.x + threadIdx.x;
    if (idx >= HD * 256) return;
    int k = idx >> 8;
    int n = idx & 255;
    out[idx] = (n < HD) ? Wgv1[k * HD + n] : Wgv2[k * HD + (n - HD)];
}

// ---------------- small kernels ----------------
__global__ void zero_kernel(float* p, int n) {
    int i = blockIdx.x * blockDim.x + threadIdx.x;
    if (i < n) p[i] = 0.0f;
}

__global__ void edge_geom_kernel(const float* __restrict__ X, const float* __restrict__ edge_attr,
                                 const int* __restrict__ edges,
                                 float* __restrict__ unit, float* __restrict__ ef)
{
    int e = blockIdx.x * blockDim.x + threadIdx.x;
    if (e >= E_EDGES) return;
    int r = edges[e];
    int c = edges[E_EDGES + e];
    float dx = X[r * 3 + 0] - X[c * 3 + 0];
    float dy = X[r * 3 + 1] - X[c * 3 + 1];
    float dz = X[r * 3 + 2] - X[c * 3 + 2];
    float norm = sqrtf(dx * dx + dy * dy + dz * dz) + 1e-8f;
    float invn = 1.0f / norm;
    unit[e * 3 + 0] = dx * invn;
    unit[e * 3 + 1] = dy * invn;
    unit[e * 3 + 2] = dz * invn;
    const float PI_ = 3.14159265358979323846f;
    float cn = fminf(norm, 1.0f);
    float cut = 0.5f * (cosf(PI_ * cn) + 1.0f);
    float f = cut * invn;
#pragma unroll
    for (int j = 0; j < 20; j++)
        ef[(long)e * EFK + j] = sinf(norm * PI_ * (float)(j + 1)) * f;
#pragma unroll
    for (int j = 0; j < 16; j++)
        ef[(long)e * EFK + 20 + j] = edge_attr[e * 16 + j];
#pragma unroll
    for (int j = 36; j < EFK; j++)
        ef[(long)e * EFK + j] = 0.0f;
}

// t[e] = silu(ArAc[row][0:128] + ArAc[col][128:256] + epre[e])
__global__ void edge_combine_kernel(const float* __restrict__ ArAc,
                                    const float* __restrict__ epre, const int* __restrict__ edges,
                                    float* __restrict__ out)
{
    int e = blockIdx.x;
    int hh = threadIdx.x;
    int r = edges[e];
    int c = edges[E_EDGES + e];
    float v = ArAc[(long)r * 256 + hh] + ArAc[(long)c * 256 + HD + hh] + epre[(long)e * HD + hh];
    out[(long)e * HD + hh] = v / (1.0f + __expf(-v));
}

// agg[n] = sum_j m ; M_c[n] = sum_j m * unit_c  (edges of n are [9n, 9n+9))
__global__ void aggM_kernel(const float* __restrict__ mcat, const float* __restrict__ unit,
                            float* __restrict__ agg, float* __restrict__ Mmat)
{
    int n = blockIdx.x;
    int hh = threadIdx.x;
    float s = 0.f, mx = 0.f, my = 0.f, mz = 0.f;
#pragma unroll
    for (int j = 0; j < KEDGE; j++) {
        long e = (long)n * KEDGE + j;
        float mm = mcat[e * 256 + hh];
        float ux = unit[e * 3 + 0];
        float uy = unit[e * 3 + 1];
        float uz = unit[e * 3 + 2];
        s += mm; mx += mm * ux; my += mm * uy; mz += mm * uz;
    }
    agg[(long)n * HD + hh] = s;
    Mmat[(long)n * 384 + hh] = mx;
    Mmat[(long)n * 384 + HD + hh] = my;
    Mmat[(long)n * 384 + 256 + hh] = mz;
}

// v_new[n,c] = v_old[n,c] + vagg[n,c] + sum_j mvv[e] * v_old[col_e, c]
__global__ void vupdate_kernel(const float* __restrict__ vin, float* __restrict__ vout,
                               const float* __restrict__ mcat, const float* __restrict__ vagg,
                               const int* __restrict__ edges)
{
    int n = blockIdx.x;
    int hh = threadIdx.x;
    float a0 = vin[(long)n * 384 + hh]       + vagg[(long)n * 384 + hh];
    float a1 = vin[(long)n * 384 + 128 + hh] + vagg[(long)n * 384 + 128 + hh];
    float a2 = vin[(long)n * 384 + 256 + hh] + vagg[(long)n * 384 + 256 + hh];
#pragma unroll
    for (int j = 0; j < KEDGE; j++) {
        long e = (long)n * KEDGE + j;
        int c = edges[E_EDGES + e];
        float b = mcat[e * 256 + HD + hh];
        a0 += b * vin[(long)c * 384 + hh];
        a1 += b * vin[(long)c * 384 + 128 + hh];
        a2 += b * vin[(long)c * 384 + 256 + hh];
    }
    vout[(long)n * 384 + hh] = a0;
    vout[(long)n * 384 + 128 + hh] = a1;
    vout[(long)n * 384 + 256 + hh] = a2;
}

__global__ void meanh_kernel(const float* __restrict__ hintra, float* __restrict__ meanh)
{
    int s = blockIdx.x;
    int k = threadIdx.x;
    float acc = 0.0f;
    for (int u = 0; u < SEGSZ; u++)
        acc += hintra[(long)(s * SEGSZ + u) * HD + k];
    meanh[s * HD + k] = acc * (1.0f / (float)SEGSZ);
}

__global__ void attn_kernel(const float* __restrict__ hintra, const float* __restrict__ meanh,
                            float* __restrict__ w)
{
    int s = blockIdx.x;
    int t = threadIdx.x;   // 0..511
    __shared__ float sm[HD];
    __shared__ float red[SEGSZ];
    int opp = s ^ 1;
    if (t < HD) sm[t] = meanh[opp * HD + t];
    __syncthreads();
    int node = s * SEGSZ + t;
    const float* hr = hintra + (long)node * HD;
    float sc = 0.0f;
#pragma unroll 8
    for (int k = 0; k < HD; k++) sc += hr[k] * sm[k];
    red[t] = sc;
    __syncthreads();
    for (int st = SEGSZ / 2; st > 0; st >>= 1) {
        if (t < st) red[t] = fmaxf(red[t], red[t + st]);
        __syncthreads();
    }
    float mx = red[0];
    __syncthreads();
    float ex = expf(sc - mx);
    red[t] = ex;
    __syncthreads();
    for (int st = SEGSZ / 2; st > 0; st >>= 1) {
        if (t < st) red[t] += red[t + st];
        __syncthreads();
    }
    w[node] = ex / red[0];
}

__global__ void v2n_kernel(const float* __restrict__ vp, float* __restrict__ v2n)
{
    int idx = blockIdx.x * blockDim.x + threadIdx.x;
    if (idx >= N_NODES * HD) return;
    int n = idx / HD;
    int k = idx % HD;
    float a = vp[(long)(n * 3 + 0) * 256 + HD + k];
    float b = vp[(long)(n * 3 + 1) * 256 + HD + k];
    float c = vp[(long)(n * 3 + 2) * 256 + HD + k];
    v2n[idx] = sqrtf(a * a + b * b + c * c + 1e-8f);
}

__global__ void pv_kernel(const float* __restrict__ vp, const float* __restrict__ mix,
                          const float* __restrict__ Wf, float* __restrict__ pv)
{
    int n = blockIdx.x;
    int k = threadIdx.x;
    __shared__ float sd[3][HD];
    float hf = mix[(long)n * 256 + k];
    float bg = mix[(long)n * 256 + HD + k];
    float s = hf * bg;
    sd[0][k] = vp[(long)(n * 3 + 0) * 256 + k] * s;
    sd[1][k] = vp[(long)(n * 3 + 1) * 256 + k] * s;
    sd[2][k] = vp[(long)(n * 3 + 2) * 256 + k] * s;
    __syncthreads();
    if (k < 27) {
        int o = k / 3, c = k % 3;
        float acc = 0.0f;
#pragma unroll 8
        for (int kk = 0; kk < HD; kk++) acc += sd[c][kk] * Wf[kk * 9 + o];
        pv[(long)n * 27 + k] = acc;
    }
}

__global__ void predsum_kernel(const float* __restrict__ pv, float* __restrict__ pred)
{
    int s = blockIdx.x;
    int j = threadIdx.x;
    if (j >= 27) return;
    float acc = 0.0f;
    for (int u = 0; u < SEGSZ; u++)
        acc += pv[(long)(s * SEGSZ + u) * 27 + j];
    pred[s * 27 + j] = acc;
}

__global__ void final_kernel(const float* __restrict__ pred, float* __restrict__ out)
{
    int s = threadIdx.x;
    if (s >= NSEG) return;
    const float* p = pred + s * 27;
#pragma unroll
    for (int r = 0; r < 3; r++) {
#pragma unroll
        for (int c = 0; c < 3; c++) {
            float A = p[0 * 3 + r] * p[1 * 3 + c]
                    + p[3 * 3 + r] * p[2 * 3 + c]
                    + p[4 * 3 + r] * p[5 * 3 + c]
                    + p[7 * 3 + r] * p[6 * 3 + c];
            out[s * 12 + r * 4 + c] = A * 100.0f;
        }
        out[s * 12 + r * 4 + 3] = p[8 * 3 + r] * 10.0f;
    }
}

// ---------------- host driver ----------------
static void launch_gemm(const float* A, const float* B, const float* bias,
                        const float* rowscale, const float* res, float* C,
                        int M, int N, int K, int flags)
{
    dim3 grid(N / 128, M / 128);
    gemm128<<<grid, 256>>>(A, B, bias, rowscale, res, C, M, N, K, flags);
}

template <typename T>
static T* sym(const void* s)
{
    void* p = nullptr;
    cudaGetSymbolAddress(&p, s);
    return (T*)p;
}

extern "C" void kernel_launch(void* const* d_in, const int* in_sizes, int n_in,
                              void* d_out, int out_size)
{
    const float* X        = (const float*)d_in[0];
    const float* node_attr= (const float*)d_in[1];
    const float* edge_attr= (const float*)d_in[2];
    const float* W_in1    = (const float*)d_in[3];
    const float* b_in1    = (const float*)d_in[4];
    const float* W_in2    = (const float*)d_in[5];
    const float* b_in2    = (const float*)d_in[6];
    const float* We1      = (const float*)d_in[7];   // (4,292,128)
    const float* be1      = (const float*)d_in[8];
    const float* We2      = (const float*)d_in[9];
    const float* be2      = (const float*)d_in[10];
    const float* Wv       = (const float*)d_in[11];
    const float* Wvv      = (const float*)d_in[12];
    const float* Wh1      = (const float*)d_in[13];  // (4,256,128)
    const float* bh1      = (const float*)d_in[14];
    const float* Wh2      = (const float*)d_in[15];
    const float* bh2      = (const float*)d_in[16];
    const float* Wi1      = (const float*)d_in[17];
    const float* bi1      = (const float*)d_in[18];
    const float* Wi2      = (const float*)d_in[19];
    const float* bi2      = (const float*)d_in[20];
    const float* Wgv1     = (const float*)d_in[21];
    const float* Wgv2     = (const float*)d_in[22];
    const float* Wg1      = (const float*)d_in[23];  // (256,128)
    const float* bg1      = (const float*)d_in[24];
    const float* Wg2      = (const float*)d_in[25];  // (128,256)
    const float* bg2      = (const float*)d_in[26];
    const float* Wf       = (const float*)d_in[27];  // (128,9)
    const int*   edges    = (const int*)d_in[28];    // (2,E)
    float* out = (float*)d_out;

    float* p_t0     = sym<float>(g_t0);
    float* p_h      = sym<float>(g_h);
    float* p_ArAc   = sym<float>(g_ArAc);
    float* p_agg    = sym<float>(g_agg);
    float* p_u      = sym<float>(g_u);
    float* p_hintra = sym<float>(g_hintra);
    float* p_v2n    = sym<float>(g_v2n);
    float* p_mix    = sym<float>(g_mix);
    float* p_ef     = sym<float>(g_ef);
    float* p_epre   = sym<float>(g_epre);
    float* p_t      = sym<float>(g_t);
    float* p_mcat   = sym<float>(g_mcat);
    float* p_unit   = sym<float>(g_unit);
    float* p_va     = sym<float>(g_va);
    float* p_vb     = sym<float>(g_vb);
    float* p_Mmat   = sym<float>(g_Mmat);
    float* p_vagg   = sym<float>(g_vagg);
    float* p_vp     = sym<float>(g_vp);
    float* p_w      = sym<float>(g_w);
    float* p_meanh  = sym<float>(g_meanh);
    float* p_pv     = sym<float>(g_pv);
    float* p_pred   = sym<float>(g_pred);
    float* p_We1cat = sym<float>(g_We1cat);
    float* p_Wef    = sym<float>(g_Wef);
    float* p_W2v    = sym<float>(g_W2v);
    float* p_W2cat  = sym<float>(g_W2cat);
    float* p_b2cat  = sym<float>(g_b2cat);
    float* p_Wgvcat = sym<float>(g_Wgvcat);

    // ---- weight packing (cheap, once per replay) ----
    pack_We1cat_kernel<<<(4 * HD * 256 + 255) / 256, 256>>>(We1, p_We1cat);
    pack_Wef_kernel<<<(4 * EFK * HD + 255) / 256, 256>>>(We1, p_Wef);
    for (int l = 0; l < 4; l++)
        launch_gemm(We2 + (long)l * HD * HD, Wvv + (long)l * HD * HD, nullptr, nullptr, nullptr,
                    p_W2v + (long)l * HD * HD, HD, HD, HD, 0);
    pack_W2cat_kernel<<<(4 * HD * 256 + 255) / 256, 256>>>(We2, p_W2v, p_W2cat);
    pack_b2cat_kernel<<<4, 256>>>(be2, Wvv, p_b2cat);
    pack_Wgv_kernel<<<(HD * 256 + 255) / 256, 256>>>(Wgv1, Wgv2, p_Wgvcat);

    // zero initial v
    zero_kernel<<<(N_NODES * 3 * HD + 255) / 256, 256>>>(p_va, N_NODES * 3 * HD);

    // edge geometry + padded [rbf|edge_attr]
    edge_geom_kernel<<<(E_EDGES + 255) / 256, 256>>>(X, edge_attr, edges, p_unit, p_ef);

    // h = silu(node_attr @ W_in1 + b_in1) @ W_in2 + b_in2
    launch_gemm(node_attr, W_in1, b_in1, nullptr, nullptr, p_t0, N_NODES, HD, 64, FLAG_SILU);
    launch_gemm(p_t0, W_in2, b_in2, nullptr, nullptr, p_h, N_NODES, HD, HD, 0);

    float* vin = p_va;
    float* vout = p_vb;

    for (int i = 0; i < 4; i++) {
        const float* be1_i = be1 + i * HD;
        const float* Wv_i  = Wv  + (long)i * HD * HD;
        const float* Wh1_i = Wh1 + (long)i * 256 * HD;
        const float* bh1_i = bh1 + i * HD;
        const float* Wh2_i = Wh2 + (long)i * HD * HD;
        const float* bh2_i = bh2 + i * HD;
        const float* Wi1_i = Wi1 + (long)i * HD * HD;
        const float* bi1_i = bi1 + i * HD;
        const float* Wi2_i = Wi2 + (long)i * HD * HD;
        const float* bi2_i = bi2 + i * HD;

        // [Ar|Ac] = h @ [W_r|W_c]
        launch_gemm(p_h, p_We1cat + (long)i * HD * 256, nullptr, nullptr, nullptr,
                    p_ArAc, N_NODES, 256, HD, 0);
        // epre = ef @ Wef + be1
        launch_gemm(p_ef, p_Wef + (long)i * EFK * HD, be1_i, nullptr, nullptr,
                    p_epre, E_EDGES, HD, EFK, 0);
        edge_combine_kernel<<<E_EDGES, HD>>>(p_ArAc, p_epre, edges, p_t);

        // [m | mvv] = t @ [We2 | We2@Wvv] + [be2 | be2@Wvv]
        launch_gemm(p_t, p_W2cat + (long)i * HD * 256, p_b2cat + i * 256, nullptr, nullptr,
                    p_mcat, E_EDGES, 256, HD, 0);

        // agg + directional moments
        aggM_kernel<<<N_NODES, HD>>>(p_mcat, p_unit, p_agg, p_Mmat);

        // h_intra = h + silu(h@Wh1_top + agg@Wh1_bot + bh1) @ Wh2 + bh2
        launch_gemm(p_h, Wh1_i, nullptr, nullptr, nullptr, p_t0, N_NODES, HD, HD, 0);
        launch_gemm(p_agg, Wh1_i + HD * HD, bh1_i, nullptr, p_t0, p_u, N_NODES, HD, HD,
                    FLAG_SILU | FLAG_RESPRE);
        launch_gemm(p_u, Wh2_i, bh2_i, nullptr, p_h, p_hintra, N_NODES, HD, HD, 0);

        // vector channel: vagg = M @ Wv ; v update with mvv gather
        launch_gemm(p_Mmat, Wv_i, nullptr, nullptr, nullptr, p_vagg, 3 * N_NODES, HD, HD, 0);
        vupdate_kernel<<<N_NODES, HD>>>(vin, vout, p_mcat, p_vagg, edges);

        // segment attention
        meanh_kernel<<<NSEG, HD>>>(p_hintra, p_meanh);
        attn_kernel<<<NSEG, SEGSZ>>>(p_hintra, p_meanh, p_w);
        launch_gemm(p_hintra, Wi1_i, bi1_i, p_w, nullptr, p_u, N_NODES, HD, HD, FLAG_SILU);
        launch_gemm(p_u, Wi2_i, bi2_i, nullptr, p_hintra, p_h, N_NODES, HD, HD, 0);

        float* tmp = vin; vin = vout; vout = tmp;
    }

    // [v1 | v2] = v @ [Wgv1 | Wgv2]
    launch_gemm(vin, p_Wgvcat, nullptr, nullptr, nullptr, p_vp, 3 * N_NODES, 256, HD, 0);
    v2n_kernel<<<(N_NODES * HD + 255) / 256, 256>>>(p_vp, p_v2n);

    // mix = silu(h@Wg1_top + v2n@Wg1_bot + bg1) @ Wg2 + bg2
    launch_gemm(p_h, Wg1, nullptr, nullptr, nullptr, p_t0, N_NODES, HD, HD, 0);
    launch_gemm(p_v2n, Wg1 + HD * HD, bg1, nullptr, p_t0, p_u, N_NODES, HD, HD,
                FLAG_SILU | FLAG_RESPRE);
    launch_gemm(p_u, Wg2, bg2, nullptr, nullptr, p_mix, N_NODES, 256, HD, 0);

    // epilogue
    pv_kernel<<<N_NODES, HD>>>(p_vp, p_mix, Wf, p_pv);
    predsum_kernel<<<NSEG, 32>>>(p_pv, p_pred);
    final_kernel<<<1, 32>>>(p_pred, out);
}

// round 5
// speedup vs baseline: 1.6657x; 1.2260x over previous
#include <cuda_runtime.h>
#include <cuda_bf16.h>
#include <math.h>
#include <stdint.h>

#define N_NODES 16384
#define E_EDGES 147456
#define HD 128
#define NSEG 32
#define SEGSZ 512
#define KEDGE 9
#define EFK 64   // padded [rbf|edge_attr] feature width (36 real + 28 zero)

#define FLAG_SILU 1
#define FLAG_RESPRE 2

// ---------------- fp32 scratch ----------------
__device__ float g_t0[N_NODES * HD];
__device__ float g_h[N_NODES * HD];
__device__ float g_ArAc[N_NODES * 2 * HD];
__device__ float g_agg[N_NODES * HD];
__device__ float g_u[N_NODES * HD];
__device__ float g_hintra[N_NODES * HD];
__device__ float g_v2n[N_NODES * HD];
__device__ float g_mix[N_NODES * 2 * HD];
__device__ float g_ef[(long)E_EDGES * EFK];
__device__ float g_epre[(long)E_EDGES * HD];
__device__ float g_t[(long)E_EDGES * HD];
__device__ float g_mcat[(long)E_EDGES * 256];   // [m | mvv]
__device__ float g_unit[E_EDGES * 3];
__device__ float g_va[N_NODES * 3 * HD];
__device__ float g_vb[N_NODES * 3 * HD];
__device__ float g_Mmat[N_NODES * 3 * HD];
__device__ float g_vagg[N_NODES * 3 * HD];
__device__ float g_vp[(long)N_NODES * 3 * 256]; // [v@Wgv1 | v@Wgv2]
__device__ float g_w[N_NODES];
__device__ float g_meanh[NSEG * HD];
__device__ float g_pv[N_NODES * 27];
__device__ float g_pred[NSEG * 27];
// fp32 weight staging
__device__ float g_We1cat[4 * HD * 256];
__device__ float g_Wef[4 * EFK * HD];
__device__ float g_W2v[4 * HD * HD];
__device__ float g_W2cat[4 * HD * 256];
__device__ float g_b2cat[4 * 256];
__device__ float g_Wgvcat[HD * 256];

// ---------------- bf16 split operand buffers ----------------
__device__ __align__(16) __nv_bfloat16 a2_cat[(long)N_NODES * 768];
__device__ __align__(16) __nv_bfloat16 a2_u[(long)N_NODES * 384];
__device__ __align__(16) __nv_bfloat16 a2_x[(long)N_NODES * 384];
__device__ __align__(16) __nv_bfloat16 a2_t[(long)E_EDGES * 384];
__device__ __align__(16) __nv_bfloat16 a2_ef[(long)E_EDGES * 192];
__device__ __align__(16) __nv_bfloat16 a2_M[(long)3 * N_NODES * 384];
__device__ __align__(16) __nv_bfloat16 b2_We1cat[4 * 256 * 384];
__device__ __align__(16) __nv_bfloat16 b2_Wef[4 * 128 * 192];
__device__ __align__(16) __nv_bfloat16 b2_W2cat[4 * 256 * 384];
__device__ __align__(16) __nv_bfloat16 b2_Wh1[4 * 128 * 768];
__device__ __align__(16) __nv_bfloat16 b2_Wh2[4 * 128 * 384];
__device__ __align__(16) __nv_bfloat16 b2_Wv[4 * 128 * 384];
__device__ __align__(16) __nv_bfloat16 b2_Wi1[4 * 128 * 384];
__device__ __align__(16) __nv_bfloat16 b2_Wi2[4 * 128 * 384];
__device__ __align__(16) __nv_bfloat16 b2_Wgv[256 * 384];
__device__ __align__(16) __nv_bfloat16 b2_Wg1[128 * 768];
__device__ __align__(16) __nv_bfloat16 b2_Wg2[256 * 384];

// ---------------- helpers ----------------
__device__ __forceinline__ uint32_t smem_to_u32(const void* p) {
    uint32_t a;
    asm("{ .reg .u64 t; cvta.to.shared.u64 t, %1; cvt.u32.u64 %0, t; }" : "=r"(a) : "l"(p));
    return a;
}

// ---------------- bf16-split tensor-core GEMM via mma.sync (sm_80+ path) ----------------
// C[m, n] = post( sum_k A2[m,k] * B2[n,k] + bias [+res] [silu] [+res] )
// A2: (M, lda) bf16 row-major. B2: (Nt, Ktot) bf16 row-major (row n = K values).
// Block tile 128x128, BK=32, 8 warps (warp tile 64x32). Ktot % 32 == 0.
// grid = (Nt/128, M/128), 256 threads.
#define SMS 40   // smem row stride in bf16 elements (32 + 8 pad)

__global__ __launch_bounds__(256)
void tcgemm(const __nv_bfloat16* __restrict__ A2, int lda, int Ktot,
            const __nv_bfloat16* __restrict__ B2,
            const float* __restrict__ bias, const float* __restrict__ res,
            float* __restrict__ C, int Nt, int flags)
{
    __shared__ __align__(16) __nv_bfloat16 As[2][128 * SMS];
    __shared__ __align__(16) __nv_bfloat16 Bs[2][128 * SMS];

    const int t = threadIdx.x;
    const int lid = t & 31;
    const int wid = t >> 5;
    const int wm = wid & 1;        // 0..1 : 64-row slice
    const int wn = wid >> 1;       // 0..3 : 32-col slice
    const int bm = blockIdx.y * 128;
    const int bn = blockIdx.x * 128;

    float acc[4][4][4];
#pragma unroll
    for (int i = 0; i < 4; i++)
#pragma unroll
        for (int j = 0; j < 4; j++)
#pragma unroll
            for (int r = 0; r < 4; r++) acc[i][j][r] = 0.0f;

    // global->smem load mapping: 512 16B-units per tile, 2 per thread
    const int r0 = t >> 2;                 // rows 0..63   (unit = t)
    const int r1 = (t + 256) >> 2;         // rows 64..127 (unit = t+256)
    const int kq = (t & 3) << 3;           // 0,8,16,24

    // ldmatrix element offsets (per lane)
    const int a_row = wm * 64 + (lid & 7) + ((lid >> 3) & 1) * 8;
    const int a_col = ((lid >> 4) & 1) * 8;
    const int a_off = a_row * SMS + a_col;
    const int b_row = wn * 32 + (lid & 7);
    const int b_col = ((lid >> 3) & 1) * 8;   // lanes 16-31 mirror 0-15 (ignored by x2)
    const int b_off = b_row * SMS + b_col;

    const int iters = Ktot >> 5;

    // prologue: chunk 0 -> buf 0
    {
        *(uint4*)&As[0][r0 * SMS + kq] = *(const uint4*)(A2 + (long)(bm + r0) * lda + kq);
        *(uint4*)&As[0][r1 * SMS + kq] = *(const uint4*)(A2 + (long)(bm + r1) * lda + kq);
        *(uint4*)&Bs[0][r0 * SMS + kq] = *(const uint4*)(B2 + (long)(bn + r0) * Ktot + kq);
        *(uint4*)&Bs[0][r1 * SMS + kq] = *(const uint4*)(B2 + (long)(bn + r1) * Ktot + kq);
    }
    __syncthreads();

    for (int it = 0; it < iters; it++) {
        const int buf = it & 1;
        uint4 pa0, pa1, pb0, pb1;
        if (it + 1 < iters) {
            const int k0 = (it + 1) << 5;
            pa0 = *(const uint4*)(A2 + (long)(bm + r0) * lda + k0 + kq);
            pa1 = *(const uint4*)(A2 + (long)(bm + r1) * lda + k0 + kq);
            pb0 = *(const uint4*)(B2 + (long)(bn + r0) * Ktot + k0 + kq);
            pb1 = *(const uint4*)(B2 + (long)(bn + r1) * Ktot + k0 + kq);
        }

        const uint32_t aBase = smem_to_u32(&As[buf][0]);
        const uint32_t bBase = smem_to_u32(&Bs[buf][0]);
#pragma unroll
        for (int ks = 0; ks < 2; ks++) {
            uint32_t a[4][4];
#pragma unroll
            for (int i = 0; i < 4; i++) {
                const uint32_t addr = aBase + 2u * (a_off + i * 16 * SMS + ks * 16);
                asm volatile(
                    "ldmatrix.sync.aligned.m8n8.x4.shared.b16 {%0,%1,%2,%3}, [%4];"
                    : "=r"(a[i][0]), "=r"(a[i][1]), "=r"(a[i][2]), "=r"(a[i][3])
                    : "r"(addr));
            }
            uint32_t b[4][2];
#pragma unroll
            for (int j = 0; j < 4; j++) {
                const uint32_t addr = bBase + 2u * (b_off + j * 8 * SMS + ks * 16);
                asm volatile(
                    "ldmatrix.sync.aligned.m8n8.x2.shared.b16 {%0,%1}, [%2];"
                    : "=r"(b[j][0]), "=r"(b[j][1])
                    : "r"(addr));
            }
#pragma unroll
            for (int i = 0; i < 4; i++)
#pragma unroll
                for (int j = 0; j < 4; j++) {
                    asm volatile(
                        "mma.sync.aligned.m16n8k16.row.col.f32.bf16.bf16.f32 "
                        "{%0,%1,%2,%3}, {%4,%5,%6,%7}, {%8,%9}, {%0,%1,%2,%3};"
                        : "+f"(acc[i][j][0]), "+f"(acc[i][j][1]),
                          "+f"(acc[i][j][2]), "+f"(acc[i][j][3])
                        : "r"(a[i][0]), "r"(a[i][1]), "r"(a[i][2]), "r"(a[i][3]),
                          "r"(b[j][0]), "r"(b[j][1]));
                }
        }

        if (it + 1 < iters) {
            const int nb = buf ^ 1;
            *(uint4*)&As[nb][r0 * SMS + kq] = pa0;
            *(uint4*)&As[nb][r1 * SMS + kq] = pa1;
            *(uint4*)&Bs[nb][r0 * SMS + kq] = pb0;
            *(uint4*)&Bs[nb][r1 * SMS + kq] = pb1;
        }
        __syncthreads();
    }

    // epilogue
    const bool f_silu = (flags & FLAG_SILU) != 0;
    const bool f_respre = (flags & FLAG_RESPRE) != 0;
    const int g = lid >> 2;
    const int t2 = (lid & 3) << 1;
#pragma unroll
    for (int i = 0; i < 4; i++) {
#pragma unroll
        for (int j = 0; j < 4; j++) {
            const int n0 = bn + wn * 32 + j * 8 + t2;
#pragma unroll
            for (int half = 0; half < 2; half++) {
                const int m = bm + wm * 64 + i * 16 + g + half * 8;
                const long base = (long)m * Nt + n0;
                float v0 = acc[i][j][2 * half + 0];
                float v1 = acc[i][j][2 * half + 1];
                if (bias) { v0 += bias[n0]; v1 += bias[n0 + 1]; }
                if (f_respre && res) { v0 += res[base]; v1 += res[base + 1]; }
                if (f_silu) {
                    v0 = v0 / (1.0f + __expf(-v0));
                    v1 = v1 / (1.0f + __expf(-v1));
                }
                if (!f_respre && res) { v0 += res[base]; v1 += res[base + 1]; }
                *(float2*)&C[base] = make_float2(v0, v1);
            }
        }
    }
}

// ---------------- split / pack kernels ----------------
// dst[row] cols [coff, coff+3K): [hi | lo | hi] of (src * rowscale)
__global__ void splitA_kernel(const float* __restrict__ src, int K,
                              __nv_bfloat16* __restrict__ dst, int ldd, int coff,
                              const float* __restrict__ rowscale, long total)
{
    long idx = (long)blockIdx.x * blockDim.x + threadIdx.x;
    if (idx >= total) return;
    int k = (int)(idx % K);
    long row = idx / K;
    float x = src[idx];
    if (rowscale) x *= rowscale[row];
    __nv_bfloat16 hi = __float2bfloat16(x);
    __nv_bfloat16 lo = __float2bfloat16(x - __bfloat162float(hi));
    __nv_bfloat16* d = dst + row * ldd + coff;
    d[k] = hi;
    d[K + k] = lo;
    d[2 * K + k] = hi;
}

// B (K,N fp32, layer-strided) -> dst rows n: cols [coff, coff+3K) = [hi | hi | lo]
__global__ void packB_kernel(const float* __restrict__ B, long sstride, int K, int N,
                             __nv_bfloat16* __restrict__ dst, long dstride, int ldd, int coff)
{
    int idx = blockIdx.x * blockDim.x + threadIdx.x;
    if (idx >= K * N) return;
    int l = blockIdx.z;
    int k = idx / N, n = idx % N;
    float x = B[(long)l * sstride + idx];
    __nv_bfloat16 hi = __float2bfloat16(x);
    __nv_bfloat16 lo = __float2bfloat16(x - __bfloat162float(hi));
    __nv_bfloat16* d = dst + (long)l * dstride + (long)n * ldd + coff;
    d[k] = hi;
    d[K + k] = hi;
    d[2 * K + k] = lo;
}

// ---------------- fp32 GEMM (small cases + pack), grid.z batched ----------------
__device__ __forceinline__ unsigned long long pack2(float lo, float hi) {
    unsigned long long r;
    asm("mov.b64 %0, {%1, %2};" : "=l"(r) : "f"(lo), "f"(hi));
    return r;
}
__device__ __forceinline__ unsigned long long dup2(float v) {
    unsigned long long r;
    asm("mov.b64 %0, {%1, %1};" : "=l"(r) : "f"(v));
    return r;
}
__device__ __forceinline__ void fma2(unsigned long long& acc, unsigned long long a, unsigned long long b) {
    asm("fma.rn.f32x2 %0, %1, %2, %0;" : "+l"(acc) : "l"(a), "l"(b));
}
__device__ __forceinline__ void unpack2(unsigned long long p, float& lo, float& hi) {
    asm("mov.b64 {%0, %1}, %2;" : "=f"(lo), "=f"(hi) : "l"(p));
}

__global__ __launch_bounds__(256, 1)
void gemm128(const float* __restrict__ A, const float* __restrict__ B,
             const float* __restrict__ bias, const float* __restrict__ res,
             float* __restrict__ C, int M, int N, int K, int flags,
             long sA, long sB, long sC)
{
    A += blockIdx.z * sA; B += blockIdx.z * sB; C += blockIdx.z * sC;
    __shared__ float As[2][16][128];
    __shared__ float Bs[2][16][128];
    const int bm = blockIdx.y * 128;
    const int bn = blockIdx.x * 128;
    const int t = threadIdx.x;
    const int ty = t >> 4;
    const int tx = t & 15;

    unsigned long long acc2[8][4];
#pragma unroll
    for (int i = 0; i < 8; i++)
#pragma unroll
        for (int j = 0; j < 4; j++) acc2[i][j] = 0ull;

    const int tiles = K >> 4;
    const int a_row0 = t >> 2;
    const int a_kc = (t & 3) << 2;
    const int b_k0 = t >> 5;
    const int b_n4 = (t & 31) << 2;

    {
#pragma unroll
        for (int r = 0; r < 2; r++) {
            int row = a_row0 + r * 64;
            float4 v = *(const float4*)&A[(long)(bm + row) * K + a_kc];
            As[0][a_kc + 0][row] = v.x; As[0][a_kc + 1][row] = v.y;
            As[0][a_kc + 2][row] = v.z; As[0][a_kc + 3][row] = v.w;
        }
#pragma unroll
        for (int r = 0; r < 2; r++) {
            int k = b_k0 + r * 8;
            *(float4*)&Bs[0][k][b_n4] = *(const float4*)&B[(long)k * N + bn + b_n4];
        }
    }
    __syncthreads();

    for (int tt = 0; tt < tiles; tt++) {
        const int buf = tt & 1;
        float4 pa[2], pb[2];
        if (tt + 1 < tiles) {
            const int k0n = (tt + 1) << 4;
#pragma unroll
            for (int r = 0; r < 2; r++)
                pa[r] = *(const float4*)&A[(long)(bm + a_row0 + r * 64) * K + k0n + a_kc];
#pragma unroll
            for (int r = 0; r < 2; r++)
                pb[r] = *(const float4*)&B[(long)(k0n + b_k0 + r * 8) * N + bn + b_n4];
        }
#pragma unroll
        for (int k = 0; k < 16; k++) {
            float a[8];
            float4 a0 = *(const float4*)&As[buf][k][ty * 8];
            float4 a1 = *(const float4*)&As[buf][k][ty * 8 + 4];
            a[0] = a0.x; a[1] = a0.y; a[2] = a0.z; a[3] = a0.w;
            a[4] = a1.x; a[5] = a1.y; a[6] = a1.z; a[7] = a1.w;
            float4 b0 = *(const float4*)&Bs[buf][k][tx * 8];
            float4 b1 = *(const float4*)&Bs[buf][k][tx * 8 + 4];
            unsigned long long b2[4];
            b2[0] = pack2(b0.x, b0.y); b2[1] = pack2(b0.z, b0.w);
            b2[2] = pack2(b1.x, b1.y); b2[3] = pack2(b1.z, b1.w);
#pragma unroll
            for (int i = 0; i < 8; i++) {
                unsigned long long ad = dup2(a[i]);
#pragma unroll
                for (int j = 0; j < 4; j++) fma2(acc2[i][j], ad, b2[j]);
            }
        }
        if (tt + 1 < tiles) {
            const int nb = buf ^ 1;
#pragma unroll
            for (int r = 0; r < 2; r++) {
                int row = a_row0 + r * 64;
                As[nb][a_kc + 0][row] = pa[r].x; As[nb][a_kc + 1][row] = pa[r].y;
                As[nb][a_kc + 2][row] = pa[r].z; As[nb][a_kc + 3][row] = pa[r].w;
            }
#pragma unroll
            for (int r = 0; r < 2; r++)
                *(float4*)&Bs[nb][b_k0 + r * 8][b_n4] = pb[r];
        }
        __syncthreads();
    }

    const bool silu = (flags & FLAG_SILU) != 0;
    const bool respre = (flags & FLAG_RESPRE) != 0;
#pragma unroll
    for (int i = 0; i < 8; i++) {
        const int m = bm + ty * 8 + i;
        float cv[8];
#pragma unroll
        for (int j = 0; j < 4; j++) unpack2(acc2[i][j], cv[2 * j], cv[2 * j + 1]);
        const long base = (long)m * N + bn + tx * 8;
#pragma unroll
        for (int j = 0; j < 8; j++) {
            float v = cv[j];
            if (bias) v += bias[bn + tx * 8 + j];
            if (respre && res) v += res[base + j];
            if (silu) v = v / (1.0f + __expf(-v));
            if (!respre && res) v += res[base + j];
            cv[j] = v;
        }
        float4* cp = (float4*)&C[base];
        cp[0] = make_float4(cv[0], cv[1], cv[2], cv[3]);
        cp[1] = make_float4(cv[4], cv[5], cv[6], cv[7]);
    }
}

// ---------------- staging pack kernels (fp32) ----------------
__global__ void pack_We1cat_kernel(const float* __restrict__ We1, float* __restrict__ out)
{
    int idx = blockIdx.x * blockDim.x + threadIdx.x;
    if (idx >= 4 * HD * 256) return;
    int l = idx / (HD * 256);
    int rem = idx - l * HD * 256;
    int k = rem >> 8, n = rem & 255;
    const float* base = We1 + (long)l * 292 * HD;
    out[idx] = (n < HD) ? base[k * HD + n] : base[(HD + k) * HD + (n - HD)];
}
__global__ void pack_Wef_kernel(const float* __restrict__ We1, float* __restrict__ out)
{
    int idx = blockIdx.x * blockDim.x + threadIdx.x;
    if (idx >= 4 * EFK * HD) return;
    int l = idx / (EFK * HD);
    int rem = idx - l * EFK * HD;
    int k = rem >> 7, n = rem & 127;
    out[idx] = (k < 36) ? We1[(long)l * 292 * HD + (256 + k) * HD + n] : 0.0f;
}
__global__ void pack_W2cat_kernel(const float* __restrict__ We2, const float* __restrict__ W2v,
                                  float* __restrict__ out)
{
    int idx = blockIdx.x * blockDim.x + threadIdx.x;
    if (idx >= 4 * HD * 256) return;
    int l = idx / (HD * 256);
    int rem = idx - l * HD * 256;
    int k = rem >> 8, n = rem & 255;
    out[idx] = (n < HD) ? We2[(long)l * HD * HD + k * HD + n]
                        : W2v[(long)l * HD * HD + k * HD + (n - HD)];
}
__global__ void pack_b2cat_kernel(const float* __restrict__ be2, const float* __restrict__ Wvv,
                                  float* __restrict__ out)
{
    int l = blockIdx.x;
    int n = threadIdx.x;
    if (n < HD) {
        out[l * 256 + n] = be2[l * HD + n];
    } else {
        int nn = n - HD;
        float acc = 0.0f;
        const float* w = Wvv + (long)l * HD * HD;
        const float* b = be2 + l * HD;
#pragma unroll 8
        for (int k = 0; k < HD; k++) acc += b[k] * w[k * HD + nn];
        out[l * 256 + n] = acc;
    }
}
__global__ void pack_Wgv_kernel(const float* __restrict__ Wgv1, const float* __restrict__ Wgv2,
                                float* __restrict__ out)
{
    int idx = blockIdx.x * blockDim.x + threadIdx.x;
    if (idx >= HD * 256) return;
    int k = idx >> 8, n = idx & 255;
    out[idx] = (n < HD) ? Wgv1[k * HD + n] : Wgv2[k * HD + (n - HD)];
}

// ---------------- elementwise / reduction kernels ----------------
__global__ void zero_kernel(float* p, int n) {
    int i = blockIdx.x * blockDim.x + threadIdx.x;
    if (i < n) p[i] = 0.0f;
}

__global__ void edge_geom_kernel(const float* __restrict__ X, const float* __restrict__ edge_attr,
                                 const int* __restrict__ edges,
                                 float* __restrict__ unit, float* __restrict__ ef)
{
    int e = blockIdx.x * blockDim.x + threadIdx.x;
    if (e >= E_EDGES) return;
    int r = edges[e];
    int c = edges[E_EDGES + e];
    float dx = X[r * 3 + 0] - X[c * 3 + 0];
    float dy = X[r * 3 + 1] - X[c * 3 + 1];
    float dz = X[r * 3 + 2] - X[c * 3 + 2];
    float norm = sqrtf(dx * dx + dy * dy + dz * dz) + 1e-8f;
    float invn = 1.0f / norm;
    unit[e * 3 + 0] = dx * invn;
    unit[e * 3 + 1] = dy * invn;
    unit[e * 3 + 2] = dz * invn;
    const float PI_ = 3.14159265358979323846f;
    float cn = fminf(norm, 1.0f);
    float cut = 0.5f * (cosf(PI_ * cn) + 1.0f);
    float f = cut * invn;
#pragma unroll
    for (int j = 0; j < 20; j++)
        ef[(long)e * EFK + j] = sinf(norm * PI_ * (float)(j + 1)) * f;
#pragma unroll
    for (int j = 0; j < 16; j++)
        ef[(long)e * EFK + 20 + j] = edge_attr[e * 16 + j];
#pragma unroll
    for (int j = 36; j < EFK; j++)
        ef[(long)e * EFK + j] = 0.0f;
}

__global__ void edge_combine_kernel(const float* __restrict__ ArAc,
                                    const float* __restrict__ epre, const int* __restrict__ edges,
                                    float* __restrict__ out)
{
    int e = blockIdx.x;
    int hh = threadIdx.x;
    int r = edges[e];
    int c = edges[E_EDGES + e];
    float v = ArAc[(long)r * 256 + hh] + ArAc[(long)c * 256 + HD + hh] + epre[(long)e * HD + hh];
    out[(long)e * HD + hh] = v / (1.0f + __expf(-v));
}

__global__ void aggM_kernel(const float* __restrict__ mcat, const float* __restrict__ unit,
                            float* __restrict__ agg, float* __restrict__ Mmat)
{
    int n = blockIdx.x;
    int hh = threadIdx.x;
    float s = 0.f, mx = 0.f, my = 0.f, mz = 0.f;
#pragma unroll
    for (int j = 0; j < KEDGE; j++) {
        long e = (long)n * KEDGE + j;
        float mm = mcat[e * 256 + hh];
        float ux = unit[e * 3 + 0];
        float uy = unit[e * 3 + 1];
        float uz = unit[e * 3 + 2];
        s += mm; mx += mm * ux; my += mm * uy; mz += mm * uz;
    }
    agg[(long)n * HD + hh] = s;
    Mmat[(long)n * 384 + hh] = mx;
    Mmat[(long)n * 384 + HD + hh] = my;
    Mmat[(long)n * 384 + 256 + hh] = mz;
}

__global__ void vupdate_kernel(const float* __restrict__ vin, float* __restrict__ vout,
                               const float* __restrict__ mcat, const float* __restrict__ vagg,
                               const int* __restrict__ edges)
{
    int n = blockIdx.x;
    int hh = threadIdx.x;
    float a0 = vin[(long)n * 384 + hh]       + vagg[(long)n * 384 + hh];
    float a1 = vin[(long)n * 384 + 128 + hh] + vagg[(long)n * 384 + 128 + hh];
    float a2 = vin[(long)n * 384 + 256 + hh] + vagg[(long)n * 384 + 256 + hh];
#pragma unroll
    for (int j = 0; j < KEDGE; j++) {
        long e = (long)n * KEDGE + j;
        int c = edges[E_EDGES + e];
        float b = mcat[e * 256 + HD + hh];
        a0 += b * vin[(long)c * 384 + hh];
        a1 += b * vin[(long)c * 384 + 128 + hh];
        a2 += b * vin[(long)c * 384 + 256 + hh];
    }
    vout[(long)n * 384 + hh] = a0;
    vout[(long)n * 384 + 128 + hh] = a1;
    vout[(long)n * 384 + 256 + hh] = a2;
}

__global__ void meanh_kernel(const float* __restrict__ hintra, float* __restrict__ meanh)
{
    int s = blockIdx.x;
    int k = threadIdx.x;
    float acc = 0.0f;
    for (int u = 0; u < SEGSZ; u++)
        acc += hintra[(long)(s * SEGSZ + u) * HD + k];
    meanh[s * HD + k] = acc * (1.0f / (float)SEGSZ);
}

__global__ void attn_kernel(const float* __restrict__ hintra, const float* __restrict__ meanh,
                            float* __restrict__ w)
{
    int s = blockIdx.x;
    int t = threadIdx.x;
    __shared__ float sm[HD];
    __shared__ float red[SEGSZ];
    int opp = s ^ 1;
    if (t < HD) sm[t] = meanh[opp * HD + t];
    __syncthreads();
    int node = s * SEGSZ + t;
    const float* hr = hintra + (long)node * HD;
    float sc = 0.0f;
#pragma unroll 8
    for (int k = 0; k < HD; k++) sc += hr[k] * sm[k];
    red[t] = sc;
    __syncthreads();
    for (int st = SEGSZ / 2; st > 0; st >>= 1) {
        if (t < st) red[t] = fmaxf(red[t], red[t + st]);
        __syncthreads();
    }
    float mx = red[0];
    __syncthreads();
    float ex = expf(sc - mx);
    red[t] = ex;
    __syncthreads();
    for (int st = SEGSZ / 2; st > 0; st >>= 1) {
        if (t < st) red[t] += red[t + st];
        __syncthreads();
    }
    w[node] = ex / red[0];
}

__global__ void v2n_kernel(const float* __restrict__ vp, float* __restrict__ v2n)
{
    int idx = blockIdx.x * blockDim.x + threadIdx.x;
    if (idx >= N_NODES * HD) return;
    int n = idx / HD;
    int k = idx % HD;
    float a = vp[(long)(n * 3 + 0) * 256 + HD + k];
    float b = vp[(long)(n * 3 + 1) * 256 + HD + k];
    float c = vp[(long)(n * 3 + 2) * 256 + HD + k];
    v2n[idx] = sqrtf(a * a + b * b + c * c + 1e-8f);
}

__global__ void pv_kernel(const float* __restrict__ vp, const float* __restrict__ mix,
                          const float* __restrict__ Wf, float* __restrict__ pv)
{
    int n = blockIdx.x;
    int k = threadIdx.x;
    __shared__ float sd[3][HD];
    float hf = mix[(long)n * 256 + k];
    float bg = mix[(long)n * 256 + HD + k];
    float s = hf * bg;
    sd[0][k] = vp[(long)(n * 3 + 0) * 256 + k] * s;
    sd[1][k] = vp[(long)(n * 3 + 1) * 256 + k] * s;
    sd[2][k] = vp[(long)(n * 3 + 2) * 256 + k] * s;
    __syncthreads();
    if (k < 27) {
        int o = k / 3, c = k % 3;
        float acc = 0.0f;
#pragma unroll 8
        for (int kk = 0; kk < HD; kk++) acc += sd[c][kk] * Wf[kk * 9 + o];
        pv[(long)n * 27 + k] = acc;
    }
}

__global__ void predsum_kernel(const float* __restrict__ pv, float* __restrict__ pred)
{
    int s = blockIdx.x;
    int j = threadIdx.x;
    if (j >= 27) return;
    float acc = 0.0f;
    for (int u = 0; u < SEGSZ; u++)
        acc += pv[(long)(s * SEGSZ + u) * 27 + j];
    pred[s * 27 + j] = acc;
}

__global__ void final_kernel(const float* __restrict__ pred, float* __restrict__ out)
{
    int s = threadIdx.x;
    if (s >= NSEG) return;
    const float* p = pred + s * 27;
#pragma unroll
    for (int r = 0; r < 3; r++) {
#pragma unroll
        for (int c = 0; c < 3; c++) {
            float A = p[0 * 3 + r] * p[1 * 3 + c]
                    + p[3 * 3 + r] * p[2 * 3 + c]
                    + p[4 * 3 + r] * p[5 * 3 + c]
                    + p[7 * 3 + r] * p[6 * 3 + c];
            out[s * 12 + r * 4 + c] = A * 100.0f;
        }
        out[s * 12 + r * 4 + 3] = p[8 * 3 + r] * 10.0f;
    }
}

// ---------------- host driver ----------------
static void launch_tc(const __nv_bfloat16* A2, int lda, int Ktot, const __nv_bfloat16* B2,
                      const float* bias, const float* res, float* C, int M, int Nt, int flags)
{
    dim3 grid(Nt / 128, M / 128);
    tcgemm<<<grid, 256>>>(A2, lda, Ktot, B2, bias, res, C, Nt, flags);
}

static void launch_gemm(const float* A, const float* B, const float* bias,
                        const float* res, float* C, int M, int N, int K, int flags,
                        int batch = 1, long sA = 0, long sB = 0, long sC = 0)
{
    dim3 grid(N / 128, M / 128, batch);
    gemm128<<<grid, 256>>>(A, B, bias, res, C, M, N, K, flags, sA, sB, sC);
}

static void launch_split(const float* src, int M, int K, __nv_bfloat16* dst, int ldd, int coff,
                         const float* rowscale)
{
    long total = (long)M * K;
    splitA_kernel<<<(int)((total + 255) / 256), 256>>>(src, K, dst, ldd, coff, rowscale, total);
}

static void launch_packB(const float* B, long sstride, int K, int N,
                         __nv_bfloat16* dst, long dstride, int ldd, int coff, int layers)
{
    dim3 grid((K * N + 255) / 256, 1, layers);
    packB_kernel<<<grid, 256>>>(B, sstride, K, N, dst, dstride, ldd, coff);
}

template <typename T>
static T* sym(const void* s)
{
    void* p = nullptr;
    cudaGetSymbolAddress(&p, s);
    return (T*)p;
}

extern "C" void kernel_launch(void* const* d_in, const int* in_sizes, int n_in,
                              void* d_out, int out_size)
{
    const float* X        = (const float*)d_in[0];
    const float* node_attr= (const float*)d_in[1];
    const float* edge_attr= (const float*)d_in[2];
    const float* W_in1    = (const float*)d_in[3];
    const float* b_in1    = (const float*)d_in[4];
    const float* W_in2    = (const float*)d_in[5];
    const float* b_in2    = (const float*)d_in[6];
    const float* We1      = (const float*)d_in[7];
    const float* be1      = (const float*)d_in[8];
    const float* We2      = (const float*)d_in[9];
    const float* be2      = (const float*)d_in[10];
    const float* Wv       = (const float*)d_in[11];
    const float* Wvv      = (const float*)d_in[12];
    const float* Wh1      = (const float*)d_in[13];
    const float* bh1      = (const float*)d_in[14];
    const float* Wh2      = (const float*)d_in[15];
    const float* bh2      = (const float*)d_in[16];
    const float* Wi1      = (const float*)d_in[17];
    const float* bi1      = (const float*)d_in[18];
    const float* Wi2      = (const float*)d_in[19];
    const float* bi2      = (const float*)d_in[20];
    const float* Wgv1     = (const float*)d_in[21];
    const float* Wgv2     = (const float*)d_in[22];
    const float* Wg1      = (const float*)d_in[23];
    const float* bg1      = (const float*)d_in[24];
    const float* Wg2      = (const float*)d_in[25];
    const float* bg2      = (const float*)d_in[26];
    const float* Wf       = (const float*)d_in[27];
    const int*   edges    = (const int*)d_in[28];
    float* out = (float*)d_out;

    float* p_t0     = sym<float>(g_t0);
    float* p_h      = sym<float>(g_h);
    float* p_ArAc   = sym<float>(g_ArAc);
    float* p_agg    = sym<float>(g_agg);
    float* p_u      = sym<float>(g_u);
    float* p_hintra = sym<float>(g_hintra);
    float* p_v2n    = sym<float>(g_v2n);
    float* p_mix    = sym<float>(g_mix);
    float* p_ef     = sym<float>(g_ef);
    float* p_epre   = sym<float>(g_epre);
    float* p_t      = sym<float>(g_t);
    float* p_mcat   = sym<float>(g_mcat);
    float* p_unit   = sym<float>(g_unit);
    float* p_va     = sym<float>(g_va);
    float* p_vb     = sym<float>(g_vb);
    float* p_Mmat   = sym<float>(g_Mmat);
    float* p_vagg   = sym<float>(g_vagg);
    float* p_vp     = sym<float>(g_vp);
    float* p_w      = sym<float>(g_w);
    float* p_meanh  = sym<float>(g_meanh);
    float* p_pv     = sym<float>(g_pv);
    float* p_pred   = sym<float>(g_pred);
    float* p_We1cat = sym<float>(g_We1cat);
    float* p_Wef    = sym<float>(g_Wef);
    float* p_W2v    = sym<float>(g_W2v);
    float* p_W2cat  = sym<float>(g_W2cat);
    float* p_b2cat  = sym<float>(g_b2cat);
    float* p_Wgvcat = sym<float>(g_Wgvcat);

    __nv_bfloat16* pa_cat = sym<__nv_bfloat16>(a2_cat);
    __nv_bfloat16* pa_u   = sym<__nv_bfloat16>(a2_u);
    __nv_bfloat16* pa_x   = sym<__nv_bfloat16>(a2_x);
    __nv_bfloat16* pa_t   = sym<__nv_bfloat16>(a2_t);
    __nv_bfloat16* pa_ef  = sym<__nv_bfloat16>(a2_ef);
    __nv_bfloat16* pa_M   = sym<__nv_bfloat16>(a2_M);
    __nv_bfloat16* pb_We1 = sym<__nv_bfloat16>(b2_We1cat);
    __nv_bfloat16* pb_Wef = sym<__nv_bfloat16>(b2_Wef);
    __nv_bfloat16* pb_W2  = sym<__nv_bfloat16>(b2_W2cat);
    __nv_bfloat16* pb_Wh1 = sym<__nv_bfloat16>(b2_Wh1);
    __nv_bfloat16* pb_Wh2 = sym<__nv_bfloat16>(b2_Wh2);
    __nv_bfloat16* pb_Wv  = sym<__nv_bfloat16>(b2_Wv);
    __nv_bfloat16* pb_Wi1 = sym<__nv_bfloat16>(b2_Wi1);
    __nv_bfloat16* pb_Wi2 = sym<__nv_bfloat16>(b2_Wi2);
    __nv_bfloat16* pb_Wgv = sym<__nv_bfloat16>(b2_Wgv);
    __nv_bfloat16* pb_Wg1 = sym<__nv_bfloat16>(b2_Wg1);
    __nv_bfloat16* pb_Wg2 = sym<__nv_bfloat16>(b2_Wg2);

    // ---- weight staging + bf16 packs (once per replay) ----
    pack_We1cat_kernel<<<(4 * HD * 256 + 255) / 256, 256>>>(We1, p_We1cat);
    pack_Wef_kernel<<<(4 * EFK * HD + 255) / 256, 256>>>(We1, p_Wef);
    launch_gemm(We2, Wvv, nullptr, nullptr, p_W2v, HD, HD, HD, 0,
                4, (long)HD * HD, (long)HD * HD, (long)HD * HD);
    pack_W2cat_kernel<<<(4 * HD * 256 + 255) / 256, 256>>>(We2, p_W2v, p_W2cat);
    pack_b2cat_kernel<<<4, 256>>>(be2, Wvv, p_b2cat);
    pack_Wgv_kernel<<<(HD * 256 + 255) / 256, 256>>>(Wgv1, Wgv2, p_Wgvcat);

    launch_packB(p_We1cat, (long)HD * 256, 128, 256, pb_We1, (long)256 * 384, 384, 0, 4);
    launch_packB(p_Wef, (long)EFK * HD, 64, 128, pb_Wef, (long)128 * 192, 192, 0, 4);
    launch_packB(p_W2cat, (long)HD * 256, 128, 256, pb_W2, (long)256 * 384, 384, 0, 4);
    launch_packB(Wh1, (long)256 * HD, 128, 128, pb_Wh1, (long)128 * 768, 768, 0, 4);
    launch_packB(Wh1 + 128 * HD, (long)256 * HD, 128, 128, pb_Wh1, (long)128 * 768, 768, 384, 4);
    launch_packB(Wh2, (long)HD * HD, 128, 128, pb_Wh2, (long)128 * 384, 384, 0, 4);
    launch_packB(Wv, (long)HD * HD, 128, 128, pb_Wv, (long)128 * 384, 384, 0, 4);
    launch_packB(Wi1, (long)HD * HD, 128, 128, pb_Wi1, (long)128 * 384, 384, 0, 4);
    launch_packB(Wi2, (long)HD * HD, 128, 128, pb_Wi2, (long)128 * 384, 384, 0, 4);
    launch_packB(p_Wgvcat, 0, 128, 256, pb_Wgv, 0, 384, 0, 1);
    launch_packB(Wg1, 0, 128, 128, pb_Wg1, 0, 768, 0, 1);
    launch_packB(Wg1 + 128 * HD, 0, 128, 128, pb_Wg1, 0, 768, 384, 1);
    launch_packB(Wg2, 0, 128, 256, pb_Wg2, 0, 384, 0, 1);

    // zero initial v
    zero_kernel<<<(N_NODES * 3 * HD + 255) / 256, 256>>>(p_va, N_NODES * 3 * HD);

    // edge geometry + padded [rbf|edge_attr], split once (static across layers)
    edge_geom_kernel<<<(E_EDGES + 255) / 256, 256>>>(X, edge_attr, edges, p_unit, p_ef);
    launch_split(p_ef, E_EDGES, 64, pa_ef, 192, 0, nullptr);

    // h = silu(node_attr @ W_in1 + b_in1) @ W_in2 + b_in2   (fp32 path, K=64/128)
    launch_gemm(node_attr, W_in1, b_in1, nullptr, p_t0, N_NODES, HD, 64, FLAG_SILU);
    launch_gemm(p_t0, W_in2, b_in2, nullptr, p_h, N_NODES, HD, HD, 0);

    float* vin = p_va;
    float* vout = p_vb;

    for (int i = 0; i < 4; i++) {
        const float* be1_i = be1 + i * HD;
        const float* bh1_i = bh1 + i * HD;
        const float* bh2_i = bh2 + i * HD;
        const float* bi1_i = bi1 + i * HD;
        const float* bi2_i = bi2 + i * HD;

        // split h -> a2_cat[:, 0:384]
        launch_split(p_h, N_NODES, HD, pa_cat, 768, 0, nullptr);

        // [Ar|Ac] = h @ [W_r|W_c]
        launch_tc(pa_cat, 768, 384, pb_We1 + (long)i * 256 * 384,
                  nullptr, nullptr, p_ArAc, N_NODES, 256, 0);

        // epre = ef @ Wef + be1
        launch_tc(pa_ef, 192, 192, pb_Wef + (long)i * 128 * 192,
                  be1_i, nullptr, p_epre, E_EDGES, 128, 0);
        edge_combine_kernel<<<E_EDGES, HD>>>(p_ArAc, p_epre, edges, p_t);

        // [m | mvv] = t @ [We2 | We2@Wvv] + [be2 | be2@Wvv]
        launch_split(p_t, E_EDGES, HD, pa_t, 384, 0, nullptr);
        launch_tc(pa_t, 384, 384, pb_W2 + (long)i * 256 * 384,
                  p_b2cat + i * 256, nullptr, p_mcat, E_EDGES, 256, 0);

        // agg + directional moments
        aggM_kernel<<<N_NODES, HD>>>(p_mcat, p_unit, p_agg, p_Mmat);

        // u = silu([h|agg] @ Wh1 + bh1)
        launch_split(p_agg, N_NODES, HD, pa_cat, 768, 384, nullptr);
        launch_tc(pa_cat, 768, 768, pb_Wh1 + (long)i * 128 * 768,
                  bh1_i, nullptr, p_u, N_NODES, 128, FLAG_SILU);
        // h_intra = h + u @ Wh2 + bh2
        launch_split(p_u, N_NODES, HD, pa_u, 384, 0, nullptr);
        launch_tc(pa_u, 384, 384, pb_Wh2 + (long)i * 128 * 384,
                  bh2_i, p_h, p_hintra, N_NODES, 128, 0);

        // vector channel: vagg = M @ Wv ; v update with mvv gather
        launch_split(p_Mmat, 3 * N_NODES, HD, pa_M, 384, 0, nullptr);
        launch_tc(pa_M, 384, 384, pb_Wv + (long)i * 128 * 384,
                  nullptr, nullptr, p_vagg, 3 * N_NODES, 128, 0);
        vupdate_kernel<<<N_NODES, HD>>>(vin, vout, p_mcat, p_vagg, edges);

        // segment attention
        meanh_kernel<<<NSEG, HD>>>(p_hintra, p_meanh);
        attn_kernel<<<NSEG, SEGSZ>>>(p_hintra, p_meanh, p_w);
        // u = silu((hintra * w) @ Wi1 + bi1)   (rowscale folded into split)
        launch_split(p_hintra, N_NODES, HD, pa_x, 384, 0, p_w);
        launch_tc(pa_x, 384, 384, pb_Wi1 + (long)i * 128 * 384,
                  bi1_i, nullptr, p_u, N_NODES, 128, FLAG_SILU);
        // h = hintra + u @ Wi2 + bi2
        launch_split(p_u, N_NODES, HD, pa_u, 384, 0, nullptr);
        launch_tc(pa_u, 384, 384, pb_Wi2 + (long)i * 128 * 384,
                  bi2_i, p_hintra, p_h, N_NODES, 128, 0);

        float* tmp = vin; vin = vout; vout = tmp;
    }

    // [v1 | v2] = v @ [Wgv1 | Wgv2]
    launch_split(vin, 3 * N_NODES, HD, pa_M, 384, 0, nullptr);
    launch_tc(pa_M, 384, 384, pb_Wgv, nullptr, nullptr, p_vp, 3 * N_NODES, 256, 0);
    v2n_kernel<<<(N_NODES * HD + 255) / 256, 256>>>(p_vp, p_v2n);

    // mix = silu([h|v2n] @ Wg1 + bg1) @ Wg2 + bg2
    launch_split(p_h, N_NODES, HD, pa_cat, 768, 0, nullptr);
    launch_split(p_v2n, N_NODES, HD, pa_cat, 768, 384, nullptr);
    launch_tc(pa_cat, 768, 768, pb_Wg1, bg1, nullptr, p_u, N_NODES, 128, FLAG_SILU);
    launch_split(p_u, N_NODES, HD, pa_u, 384, 0, nullptr);
    launch_tc(pa_u, 384, 384, pb_Wg2, bg2, nullptr, p_mix, N_NODES, 256, 0);

    // epilogue
    pv_kernel<<<N_NODES, HD>>>(p_vp, p_mix, Wf, p_pv);
    predsum_kernel<<<NSEG, 32>>>(p_pv, p_pred);
    final_kernel<<<1, 32>>>(p_pred, out);
}

// round 6
// speedup vs baseline: 1.6899x; 1.0145x over previous
#include <cuda_runtime.h>
#include <cuda_bf16.h>
#include <math.h>
#include <stdint.h>

#define N_NODES 16384
#define E_EDGES 147456
#define HD 128
#define NSEG 32
#define SEGSZ 512
#define KEDGE 9
#define EFK 64

#define FLAG_SILU 1
#define FLAG_RESPRE 2
#define FLAG_COMBINE 4

// ---------------- fp32 scratch ----------------
__device__ float g_t0[N_NODES * HD];
__device__ float g_h[N_NODES * HD];
__device__ float g_ArAc[N_NODES * 2 * HD];
__device__ float g_hintra[N_NODES * HD];
__device__ float g_v2n[N_NODES * HD];
__device__ float g_mix[N_NODES * 2 * HD];
__device__ float g_ef[(long)E_EDGES * EFK];
__device__ float g_mcat[(long)E_EDGES * 256];   // [m | mvv]
__device__ float g_unit[E_EDGES * 3];
__device__ float g_va[N_NODES * 3 * HD];
__device__ float g_vb[N_NODES * 3 * HD];
__device__ float g_vagg[N_NODES * 3 * HD];
__device__ float g_vp[(long)N_NODES * 3 * 256]; // [v@Wgv1 | v@Wgv2]
__device__ float g_w[N_NODES];
__device__ float g_meanp[NSEG * 8 * HD];
__device__ float g_meanh[NSEG * HD];
__device__ float g_pv[N_NODES * 27];
__device__ float g_pred[NSEG * 27];
// fp32 weight staging
__device__ float g_We1cat[4 * HD * 256];
__device__ float g_Wef[4 * EFK * HD];
__device__ float g_W2v[4 * HD * HD];
__device__ float g_W2cat[4 * HD * 256];
__device__ float g_b2cat[4 * 256];
__device__ float g_Wgvcat[HD * 256];

// ---------------- bf16 split operand buffers ----------------
__device__ __align__(16) __nv_bfloat16 a2_cat[(long)N_NODES * 768];
__device__ __align__(16) __nv_bfloat16 a2_u[(long)N_NODES * 384];
__device__ __align__(16) __nv_bfloat16 a2_x[(long)N_NODES * 384];
__device__ __align__(16) __nv_bfloat16 a2_t[(long)E_EDGES * 384];
__device__ __align__(16) __nv_bfloat16 a2_ef[(long)E_EDGES * 192];
__device__ __align__(16) __nv_bfloat16 a2_M[(long)3 * N_NODES * 384];
__device__ __align__(16) __nv_bfloat16 b2_We1cat[4 * 256 * 384];
__device__ __align__(16) __nv_bfloat16 b2_Wef[4 * 128 * 192];
__device__ __align__(16) __nv_bfloat16 b2_W2cat[4 * 256 * 384];
__device__ __align__(16) __nv_bfloat16 b2_Wh1[4 * 128 * 768];
__device__ __align__(16) __nv_bfloat16 b2_Wh2[4 * 128 * 384];
__device__ __align__(16) __nv_bfloat16 b2_Wv[4 * 128 * 384];
__device__ __align__(16) __nv_bfloat16 b2_Wi1[4 * 128 * 384];
__device__ __align__(16) __nv_bfloat16 b2_Wi2[4 * 128 * 384];
__device__ __align__(16) __nv_bfloat16 b2_Wgv[256 * 384];
__device__ __align__(16) __nv_bfloat16 b2_Wg1[128 * 768];
__device__ __align__(16) __nv_bfloat16 b2_Wg2[256 * 384];

// ---------------- helpers ----------------
__device__ __forceinline__ uint32_t smem_to_u32(const void* p) {
    uint32_t a;
    asm("{ .reg .u64 t; cvta.to.shared.u64 t, %1; cvt.u32.u64 %0, t; }" : "=r"(a) : "l"(p));
    return a;
}
__device__ __forceinline__ void wsplit1(__nv_bfloat16* d, int K, float x) {
    __nv_bfloat16 hi = __float2bfloat16(x);
    __nv_bfloat16 lo = __float2bfloat16(x - __bfloat162float(hi));
    d[0] = hi; d[K] = lo; d[2 * K] = hi;
}

// ---------------- bf16-split tensor-core GEMM via mma.sync ----------------
// acc = A2 @ B2^T ; epilogue: +bias, [+ArAc combine], [+res pre], [silu], [+res post]
// Optional fp32 store to C; optional bf16 [hi|lo|hi] split store to sdst (ldd sldd, K=Nt).
// A2: (M, lda) bf16 row-major. B2: (Nt, Ktot) bf16 row-major. Ktot % 32 == 0.
#define SMS 40

__global__ __launch_bounds__(256)
void tcgemm(const __nv_bfloat16* __restrict__ A2, int lda, int Ktot,
            const __nv_bfloat16* __restrict__ B2,
            const float* __restrict__ bias, const float* __restrict__ res,
            float* __restrict__ C, int Nt, int flags,
            __nv_bfloat16* __restrict__ sdst, int sldd,
            const int* __restrict__ edges, const float* __restrict__ ArAc)
{
    __shared__ __align__(16) __nv_bfloat16 As[2][128 * SMS];
    __shared__ __align__(16) __nv_bfloat16 Bs[2][128 * SMS];

    const int t = threadIdx.x;
    const int lid = t & 31;
    const int wid = t >> 5;
    const int wm = wid & 1;
    const int wn = wid >> 1;
    const int bm = blockIdx.y * 128;
    const int bn = blockIdx.x * 128;

    float acc[4][4][4];
#pragma unroll
    for (int i = 0; i < 4; i++)
#pragma unroll
        for (int j = 0; j < 4; j++)
#pragma unroll
            for (int r = 0; r < 4; r++) acc[i][j][r] = 0.0f;

    const int r0 = t >> 2;
    const int r1 = (t + 256) >> 2;
    const int kq = (t & 3) << 3;

    const int a_row = wm * 64 + (lid & 7) + ((lid >> 3) & 1) * 8;
    const int a_col = ((lid >> 4) & 1) * 8;
    const int a_off = a_row * SMS + a_col;
    const int b_row = wn * 32 + (lid & 7);
    const int b_col = ((lid >> 3) & 1) * 8;
    const int b_off = b_row * SMS + b_col;

    const int iters = Ktot >> 5;

    {
        *(uint4*)&As[0][r0 * SMS + kq] = *(const uint4*)(A2 + (long)(bm + r0) * lda + kq);
        *(uint4*)&As[0][r1 * SMS + kq] = *(const uint4*)(A2 + (long)(bm + r1) * lda + kq);
        *(uint4*)&Bs[0][r0 * SMS + kq] = *(const uint4*)(B2 + (long)(bn + r0) * Ktot + kq);
        *(uint4*)&Bs[0][r1 * SMS + kq] = *(const uint4*)(B2 + (long)(bn + r1) * Ktot + kq);
    }
    __syncthreads();

    for (int it = 0; it < iters; it++) {
        const int buf = it & 1;
        uint4 pa0, pa1, pb0, pb1;
        if (it + 1 < iters) {
            const int k0 = (it + 1) << 5;
            pa0 = *(const uint4*)(A2 + (long)(bm + r0) * lda + k0 + kq);
            pa1 = *(const uint4*)(A2 + (long)(bm + r1) * lda + k0 + kq);
            pb0 = *(const uint4*)(B2 + (long)(bn + r0) * Ktot + k0 + kq);
            pb1 = *(const uint4*)(B2 + (long)(bn + r1) * Ktot + k0 + kq);
        }

        const uint32_t aBase = smem_to_u32(&As[buf][0]);
        const uint32_t bBase = smem_to_u32(&Bs[buf][0]);
#pragma unroll
        for (int ks = 0; ks < 2; ks++) {
            uint32_t a[4][4];
#pragma unroll
            for (int i = 0; i < 4; i++) {
                const uint32_t addr = aBase + 2u * (a_off + i * 16 * SMS + ks * 16);
                asm volatile(
                    "ldmatrix.sync.aligned.m8n8.x4.shared.b16 {%0,%1,%2,%3}, [%4];"
                    : "=r"(a[i][0]), "=r"(a[i][1]), "=r"(a[i][2]), "=r"(a[i][3])
                    : "r"(addr));
            }
            uint32_t b[4][2];
#pragma unroll
            for (int j = 0; j < 4; j++) {
                const uint32_t addr = bBase + 2u * (b_off + j * 8 * SMS + ks * 16);
                asm volatile(
                    "ldmatrix.sync.aligned.m8n8.x2.shared.b16 {%0,%1}, [%2];"
                    : "=r"(b[j][0]), "=r"(b[j][1])
                    : "r"(addr));
            }
#pragma unroll
            for (int i = 0; i < 4; i++)
#pragma unroll
                for (int j = 0; j < 4; j++) {
                    asm volatile(
                        "mma.sync.aligned.m16n8k16.row.col.f32.bf16.bf16.f32 "
                        "{%0,%1,%2,%3}, {%4,%5,%6,%7}, {%8,%9}, {%0,%1,%2,%3};"
                        : "+f"(acc[i][j][0]), "+f"(acc[i][j][1]),
                          "+f"(acc[i][j][2]), "+f"(acc[i][j][3])
                        : "r"(a[i][0]), "r"(a[i][1]), "r"(a[i][2]), "r"(a[i][3]),
                          "r"(b[j][0]), "r"(b[j][1]));
                }
        }

        if (it + 1 < iters) {
            const int nb = buf ^ 1;
            *(uint4*)&As[nb][r0 * SMS + kq] = pa0;
            *(uint4*)&As[nb][r1 * SMS + kq] = pa1;
            *(uint4*)&Bs[nb][r0 * SMS + kq] = pb0;
            *(uint4*)&Bs[nb][r1 * SMS + kq] = pb1;
        }
        __syncthreads();
    }

    // epilogue
    const bool f_silu = (flags & FLAG_SILU) != 0;
    const bool f_respre = (flags & FLAG_RESPRE) != 0;
    const bool f_comb = (flags & FLAG_COMBINE) != 0;
    const int g = lid >> 2;
    const int t2 = (lid & 3) << 1;
#pragma unroll
    for (int i = 0; i < 4; i++) {
#pragma unroll
        for (int half = 0; half < 2; half++) {
            const int m = bm + wm * 64 + i * 16 + g + half * 8;
            int rrow = 0, ccol = 0;
            if (f_comb) { rrow = m / KEDGE; ccol = edges[E_EDGES + m]; }
#pragma unroll
            for (int j = 0; j < 4; j++) {
                const int n0 = bn + wn * 32 + j * 8 + t2;
                const long base = (long)m * Nt + n0;
                float v0 = acc[i][j][2 * half + 0];
                float v1 = acc[i][j][2 * half + 1];
                if (bias) { v0 += bias[n0]; v1 += bias[n0 + 1]; }
                if (f_comb) {
                    v0 += ArAc[(long)rrow * 256 + n0] + ArAc[(long)ccol * 256 + 128 + n0];
                    v1 += ArAc[(long)rrow * 256 + n0 + 1] + ArAc[(long)ccol * 256 + 128 + n0 + 1];
                }
                if (f_respre && res) { v0 += res[base]; v1 += res[base + 1]; }
                if (f_silu) {
                    v0 = v0 / (1.0f + __expf(-v0));
                    v1 = v1 / (1.0f + __expf(-v1));
                }
                if (!f_respre && res) { v0 += res[base]; v1 += res[base + 1]; }
                if (C) *(float2*)&C[base] = make_float2(v0, v1);
                if (sdst) {
                    __nv_bfloat16 h0 = __float2bfloat16(v0);
                    __nv_bfloat16 h1 = __float2bfloat16(v1);
                    __nv_bfloat16 l0 = __float2bfloat16(v0 - __bfloat162float(h0));
                    __nv_bfloat16 l1 = __float2bfloat16(v1 - __bfloat162float(h1));
                    __nv_bfloat16* d = sdst + (long)m * sldd + n0;
                    __nv_bfloat162 hv; hv.x = h0; hv.y = h1;
                    __nv_bfloat162 lv; lv.x = l0; lv.y = l1;
                    *(__nv_bfloat162*)&d[0] = hv;
                    *(__nv_bfloat162*)&d[Nt] = lv;
                    *(__nv_bfloat162*)&d[2 * Nt] = hv;
                }
            }
        }
    }
}

// ---------------- split / pack kernels ----------------
__global__ void splitA_kernel(const float* __restrict__ src, int K,
                              __nv_bfloat16* __restrict__ dst, int ldd, int coff,
                              const float* __restrict__ rowscale, long total)
{
    long idx = (long)blockIdx.x * blockDim.x + threadIdx.x;
    if (idx >= total) return;
    int k = (int)(idx % K);
    long row = idx / K;
    float x = src[idx];
    if (rowscale) x *= rowscale[row];
    wsplit1(dst + row * ldd + coff + k, K, x);
}

__global__ void packB_kernel(const float* __restrict__ B, long sstride, int K, int N,
                             __nv_bfloat16* __restrict__ dst, long dstride, int ldd, int coff)
{
    int idx = blockIdx.x * blockDim.x + threadIdx.x;
    if (idx >= K * N) return;
    int l = blockIdx.z;
    int k = idx / N, n = idx % N;
    float x = B[(long)l * sstride + idx];
    __nv_bfloat16 hi = __float2bfloat16(x);
    __nv_bfloat16 lo = __float2bfloat16(x - __bfloat162float(hi));
    __nv_bfloat16* d = dst + (long)l * dstride + (long)n * ldd + coff;
    d[k] = hi;
    d[K + k] = hi;
    d[2 * K + k] = lo;
}

// ---------------- fp32 GEMM (initial MLP + weight pack), grid.z batched ----------------
__device__ __forceinline__ unsigned long long pack2(float lo, float hi) {
    unsigned long long r;
    asm("mov.b64 %0, {%1, %2};" : "=l"(r) : "f"(lo), "f"(hi));
    return r;
}
__device__ __forceinline__ unsigned long long dup2(float v) {
    unsigned long long r;
    asm("mov.b64 %0, {%1, %1};" : "=l"(r) : "f"(v));
    return r;
}
__device__ __forceinline__ void fma2(unsigned long long& acc, unsigned long long a, unsigned long long b) {
    asm("fma.rn.f32x2 %0, %1, %2, %0;" : "+l"(acc) : "l"(a), "l"(b));
}
__device__ __forceinline__ void unpack2(unsigned long long p, float& lo, float& hi) {
    asm("mov.b64 {%0, %1}, %2;" : "=f"(lo), "=f"(hi) : "l"(p));
}

__global__ __launch_bounds__(256, 1)
void gemm128(const float* __restrict__ A, const float* __restrict__ B,
             const float* __restrict__ bias, const float* __restrict__ res,
             float* __restrict__ C, int M, int N, int K, int flags,
             long sA, long sB, long sC)
{
    A += blockIdx.z * sA; B += blockIdx.z * sB; C += blockIdx.z * sC;
    __shared__ float As[2][16][128];
    __shared__ float Bs[2][16][128];
    const int bm = blockIdx.y * 128;
    const int bn = blockIdx.x * 128;
    const int t = threadIdx.x;
    const int ty = t >> 4;
    const int tx = t & 15;

    unsigned long long acc2[8][4];
#pragma unroll
    for (int i = 0; i < 8; i++)
#pragma unroll
        for (int j = 0; j < 4; j++) acc2[i][j] = 0ull;

    const int tiles = K >> 4;
    const int a_row0 = t >> 2;
    const int a_kc = (t & 3) << 2;
    const int b_k0 = t >> 5;
    const int b_n4 = (t & 31) << 2;

    {
#pragma unroll
        for (int r = 0; r < 2; r++) {
            int row = a_row0 + r * 64;
            float4 v = *(const float4*)&A[(long)(bm + row) * K + a_kc];
            As[0][a_kc + 0][row] = v.x; As[0][a_kc + 1][row] = v.y;
            As[0][a_kc + 2][row] = v.z; As[0][a_kc + 3][row] = v.w;
        }
#pragma unroll
        for (int r = 0; r < 2; r++) {
            int k = b_k0 + r * 8;
            *(float4*)&Bs[0][k][b_n4] = *(const float4*)&B[(long)k * N + bn + b_n4];
        }
    }
    __syncthreads();

    for (int tt = 0; tt < tiles; tt++) {
        const int buf = tt & 1;
        float4 pa[2], pb[2];
        if (tt + 1 < tiles) {
            const int k0n = (tt + 1) << 4;
#pragma unroll
            for (int r = 0; r < 2; r++)
                pa[r] = *(const float4*)&A[(long)(bm + a_row0 + r * 64) * K + k0n + a_kc];
#pragma unroll
            for (int r = 0; r < 2; r++)
                pb[r] = *(const float4*)&B[(long)(k0n + b_k0 + r * 8) * N + bn + b_n4];
        }
#pragma unroll
        for (int k = 0; k < 16; k++) {
            float a[8];
            float4 a0 = *(const float4*)&As[buf][k][ty * 8];
            float4 a1 = *(const float4*)&As[buf][k][ty * 8 + 4];
            a[0] = a0.x; a[1] = a0.y; a[2] = a0.z; a[3] = a0.w;
            a[4] = a1.x; a[5] = a1.y; a[6] = a1.z; a[7] = a1.w;
            float4 b0 = *(const float4*)&Bs[buf][k][tx * 8];
            float4 b1 = *(const float4*)&Bs[buf][k][tx * 8 + 4];
            unsigned long long b2[4];
            b2[0] = pack2(b0.x, b0.y); b2[1] = pack2(b0.z, b0.w);
            b2[2] = pack2(b1.x, b1.y); b2[3] = pack2(b1.z, b1.w);
#pragma unroll
            for (int i = 0; i < 8; i++) {
                unsigned long long ad = dup2(a[i]);
#pragma unroll
                for (int j = 0; j < 4; j++) fma2(acc2[i][j], ad, b2[j]);
            }
        }
        if (tt + 1 < tiles) {
            const int nb = buf ^ 1;
#pragma unroll
            for (int r = 0; r < 2; r++) {
                int row = a_row0 + r * 64;
                As[nb][a_kc + 0][row] = pa[r].x; As[nb][a_kc + 1][row] = pa[r].y;
                As[nb][a_kc + 2][row] = pa[r].z; As[nb][a_kc + 3][row] = pa[r].w;
            }
#pragma unroll
            for (int r = 0; r < 2; r++)
                *(float4*)&Bs[nb][b_k0 + r * 8][b_n4] = pb[r];
        }
        __syncthreads();
    }

    const bool silu = (flags & FLAG_SILU) != 0;
    const bool respre = (flags & FLAG_RESPRE) != 0;
#pragma unroll
    for (int i = 0; i < 8; i++) {
        const int m = bm + ty * 8 + i;
        float cv[8];
#pragma unroll
        for (int j = 0; j < 4; j++) unpack2(acc2[i][j], cv[2 * j], cv[2 * j + 1]);
        const long base = (long)m * N + bn + tx * 8;
#pragma unroll
        for (int j = 0; j < 8; j++) {
            float v = cv[j];
            if (bias) v += bias[bn + tx * 8 + j];
            if (respre && res) v += res[base + j];
            if (silu) v = v / (1.0f + __expf(-v));
            if (!respre && res) v += res[base + j];
            cv[j] = v;
        }
        float4* cp = (float4*)&C[base];
        cp[0] = make_float4(cv[0], cv[1], cv[2], cv[3]);
        cp[1] = make_float4(cv[4], cv[5], cv[6], cv[7]);
    }
}

// ---------------- staging pack kernels (fp32) ----------------
__global__ void pack_We1cat_kernel(const float* __restrict__ We1, float* __restrict__ out)
{
    int idx = blockIdx.x * blockDim.x + threadIdx.x;
    if (idx >= 4 * HD * 256) return;
    int l = idx / (HD * 256);
    int rem = idx - l * HD * 256;
    int k = rem >> 8, n = rem & 255;
    const float* base = We1 + (long)l * 292 * HD;
    out[idx] = (n < HD) ? base[k * HD + n] : base[(HD + k) * HD + (n - HD)];
}
__global__ void pack_Wef_kernel(const float* __restrict__ We1, float* __restrict__ out)
{
    int idx = blockIdx.x * blockDim.x + threadIdx.x;
    if (idx >= 4 * EFK * HD) return;
    int l = idx / (EFK * HD);
    int rem = idx - l * EFK * HD;
    int k = rem >> 7, n = rem & 127;
    out[idx] = (k < 36) ? We1[(long)l * 292 * HD + (256 + k) * HD + n] : 0.0f;
}
__global__ void pack_W2cat_kernel(const float* __restrict__ We2, const float* __restrict__ W2v,
                                  float* __restrict__ out)
{
    int idx = blockIdx.x * blockDim.x + threadIdx.x;
    if (idx >= 4 * HD * 256) return;
    int l = idx / (HD * 256);
    int rem = idx - l * HD * 256;
    int k = rem >> 8, n = rem & 255;
    out[idx] = (n < HD) ? We2[(long)l * HD * HD + k * HD + n]
                        : W2v[(long)l * HD * HD + k * HD + (n - HD)];
}
__global__ void pack_b2cat_kernel(const float* __restrict__ be2, const float* __restrict__ Wvv,
                                  float* __restrict__ out)
{
    int l = blockIdx.x;
    int n = threadIdx.x;
    if (n < HD) {
        out[l * 256 + n] = be2[l * HD + n];
    } else {
        int nn = n - HD;
        float acc = 0.0f;
        const float* w = Wvv + (long)l * HD * HD;
        const float* b = be2 + l * HD;
#pragma unroll 8
        for (int k = 0; k < HD; k++) acc += b[k] * w[k * HD + nn];
        out[l * 256 + n] = acc;
    }
}
__global__ void pack_Wgv_kernel(const float* __restrict__ Wgv1, const float* __restrict__ Wgv2,
                                float* __restrict__ out)
{
    int idx = blockIdx.x * blockDim.x + threadIdx.x;
    if (idx >= HD * 256) return;
    int k = idx >> 8, n = idx & 255;
    out[idx] = (n < HD) ? Wgv1[k * HD + n] : Wgv2[k * HD + (n - HD)];
}

// ---------------- elementwise / reduction kernels ----------------
__global__ void zero_kernel(float* p, int n) {
    int i = blockIdx.x * blockDim.x + threadIdx.x;
    if (i < n) p[i] = 0.0f;
}

__global__ void edge_geom_kernel(const float* __restrict__ X, const float* __restrict__ edge_attr,
                                 const int* __restrict__ edges,
                                 float* __restrict__ unit, float* __restrict__ ef)
{
    int e = blockIdx.x * blockDim.x + threadIdx.x;
    if (e >= E_EDGES) return;
    int r = edges[e];
    int c = edges[E_EDGES + e];
    float dx = X[r * 3 + 0] - X[c * 3 + 0];
    float dy = X[r * 3 + 1] - X[c * 3 + 1];
    float dz = X[r * 3 + 2] - X[c * 3 + 2];
    float norm = sqrtf(dx * dx + dy * dy + dz * dz) + 1e-8f;
    float invn = 1.0f / norm;
    unit[e * 3 + 0] = dx * invn;
    unit[e * 3 + 1] = dy * invn;
    unit[e * 3 + 2] = dz * invn;
    const float PI_ = 3.14159265358979323846f;
    float cn = fminf(norm, 1.0f);
    float cut = 0.5f * (cosf(PI_ * cn) + 1.0f);
    float f = cut * invn;
#pragma unroll
    for (int j = 0; j < 20; j++)
        ef[(long)e * EFK + j] = sinf(norm * PI_ * (float)(j + 1)) * f;
#pragma unroll
    for (int j = 0; j < 16; j++)
        ef[(long)e * EFK + 20 + j] = edge_attr[e * 16 + j];
#pragma unroll
    for (int j = 36; j < EFK; j++)
        ef[(long)e * EFK + j] = 0.0f;
}

// agg/M with fused bf16 split output.
// aggdst: pa_cat + 384 (ldd 768), Mdst: pa_M (ldd 384)
__global__ void aggM_kernel(const float* __restrict__ mcat, const float* __restrict__ unit,
                            __nv_bfloat16* __restrict__ aggdst, __nv_bfloat16* __restrict__ Mdst)
{
    int n = blockIdx.x;
    int hh = threadIdx.x;
    float s = 0.f, mx = 0.f, my = 0.f, mz = 0.f;
#pragma unroll
    for (int j = 0; j < KEDGE; j++) {
        long e = (long)n * KEDGE + j;
        float mm = mcat[e * 256 + hh];
        float ux = unit[e * 3 + 0];
        float uy = unit[e * 3 + 1];
        float uz = unit[e * 3 + 2];
        s += mm; mx += mm * ux; my += mm * uy; mz += mm * uz;
    }
    wsplit1(aggdst + (long)n * 768 + hh, 128, s);
    wsplit1(Mdst + (long)(3 * n + 0) * 384 + hh, 128, mx);
    wsplit1(Mdst + (long)(3 * n + 1) * 384 + hh, 128, my);
    wsplit1(Mdst + (long)(3 * n + 2) * 384 + hh, 128, mz);
}

__global__ void vupdate_kernel(const float* __restrict__ vin, float* __restrict__ vout,
                               const float* __restrict__ mcat, const float* __restrict__ vagg,
                               const int* __restrict__ edges)
{
    int n = blockIdx.x;
    int hh = threadIdx.x;
    float a0 = vin[(long)n * 384 + hh]       + vagg[(long)n * 384 + hh];
    float a1 = vin[(long)n * 384 + 128 + hh] + vagg[(long)n * 384 + 128 + hh];
    float a2 = vin[(long)n * 384 + 256 + hh] + vagg[(long)n * 384 + 256 + hh];
#pragma unroll
    for (int j = 0; j < KEDGE; j++) {
        long e = (long)n * KEDGE + j;
        int c = edges[E_EDGES + e];
        float b = mcat[e * 256 + HD + hh];
        a0 += b * vin[(long)c * 384 + hh];
        a1 += b * vin[(long)c * 384 + 128 + hh];
        a2 += b * vin[(long)c * 384 + 256 + hh];
    }
    vout[(long)n * 384 + hh] = a0;
    vout[(long)n * 384 + 128 + hh] = a1;
    vout[(long)n * 384 + 256 + hh] = a2;
}

__global__ void meanh1_kernel(const float* __restrict__ hintra, float* __restrict__ part)
{
    int s = blockIdx.x;
    int c = blockIdx.y;
    int k = threadIdx.x;
    float acc = 0.0f;
    const float* p = hintra + ((long)s * SEGSZ + c * 64) * HD + k;
#pragma unroll 8
    for (int u = 0; u < 64; u++) acc += p[u * HD];
    part[(s * 8 + c) * HD + k] = acc;
}
__global__ void meanh2_kernel(const float* __restrict__ part, float* __restrict__ meanh)
{
    int s = blockIdx.x;
    int k = threadIdx.x;
    float a = 0.0f;
#pragma unroll
    for (int c = 0; c < 8; c++) a += part[(s * 8 + c) * HD + k];
    meanh[s * HD + k] = a * (1.0f / (float)SEGSZ);
}

__global__ void attn_kernel(const float* __restrict__ hintra, const float* __restrict__ meanh,
                            float* __restrict__ w)
{
    int s = blockIdx.x;
    int t = threadIdx.x;
    __shared__ float sm[HD];
    __shared__ float red[SEGSZ];
    int opp = s ^ 1;
    if (t < HD) sm[t] = meanh[opp * HD + t];
    __syncthreads();
    int node = s * SEGSZ + t;
    const float* hr = hintra + (long)node * HD;
    float sc = 0.0f;
#pragma unroll 8
    for (int k = 0; k < HD; k++) sc += hr[k] * sm[k];
    red[t] = sc;
    __syncthreads();
    for (int st = SEGSZ / 2; st > 0; st >>= 1) {
        if (t < st) red[t] = fmaxf(red[t], red[t + st]);
        __syncthreads();
    }
    float mx = red[0];
    __syncthreads();
    float ex = expf(sc - mx);
    red[t] = ex;
    __syncthreads();
    for (int st = SEGSZ / 2; st > 0; st >>= 1) {
        if (t < st) red[t] += red[t + st];
        __syncthreads();
    }
    w[node] = ex / red[0];
}

__global__ void v2n_kernel(const float* __restrict__ vp, float* __restrict__ v2n)
{
    int idx = blockIdx.x * blockDim.x + threadIdx.x;
    if (idx >= N_NODES * HD) return;
    int n = idx / HD;
    int k = idx % HD;
    float a = vp[(long)(n * 3 + 0) * 256 + HD + k];
    float b = vp[(long)(n * 3 + 1) * 256 + HD + k];
    float c = vp[(long)(n * 3 + 2) * 256 + HD + k];
    v2n[idx] = sqrtf(a * a + b * b + c * c + 1e-8f);
}

__global__ void pv_kernel(const float* __restrict__ vp, const float* __restrict__ mix,
                          const float* __restrict__ Wf, float* __restrict__ pv)
{
    int n = blockIdx.x;
    int k = threadIdx.x;
    __shared__ float sd[3][HD];
    float hf = mix[(long)n * 256 + k];
    float bg = mix[(long)n * 256 + HD + k];
    float s = hf * bg;
    sd[0][k] = vp[(long)(n * 3 + 0) * 256 + k] * s;
    sd[1][k] = vp[(long)(n * 3 + 1) * 256 + k] * s;
    sd[2][k] = vp[(long)(n * 3 + 2) * 256 + k] * s;
    __syncthreads();
    if (k < 27) {
        int o = k / 3, c = k % 3;
        float acc = 0.0f;
#pragma unroll 8
        for (int kk = 0; kk < HD; kk++) acc += sd[c][kk] * Wf[kk * 9 + o];
        pv[(long)n * 27 + k] = acc;
    }
}

__global__ void predsum_kernel(const float* __restrict__ pv, float* __restrict__ pred)
{
    int s = blockIdx.x;
    int j = threadIdx.x;
    if (j >= 27) return;
    float acc = 0.0f;
    for (int u = 0; u < SEGSZ; u++)
        acc += pv[(long)(s * SEGSZ + u) * 27 + j];
    pred[s * 27 + j] = acc;
}

__global__ void final_kernel(const float* __restrict__ pred, float* __restrict__ out)
{
    int s = threadIdx.x;
    if (s >= NSEG) return;
    const float* p = pred + s * 27;
#pragma unroll
    for (int r = 0; r < 3; r++) {
#pragma unroll
        for (int c = 0; c < 3; c++) {
            float A = p[0 * 3 + r] * p[1 * 3 + c]
                    + p[3 * 3 + r] * p[2 * 3 + c]
                    + p[4 * 3 + r] * p[5 * 3 + c]
                    + p[7 * 3 + r] * p[6 * 3 + c];
            out[s * 12 + r * 4 + c] = A * 100.0f;
        }
        out[s * 12 + r * 4 + 3] = p[8 * 3 + r] * 10.0f;
    }
}

// ---------------- host driver ----------------
static void launch_tc(const __nv_bfloat16* A2, int lda, int Ktot, const __nv_bfloat16* B2,
                      const float* bias, const float* res, float* C, int M, int Nt, int flags,
                      __nv_bfloat16* sdst = nullptr, int sldd = 0,
                      const int* edges = nullptr, const float* ArAc = nullptr)
{
    dim3 grid(Nt / 128, M / 128);
    tcgemm<<<grid, 256>>>(A2, lda, Ktot, B2, bias, res, C, Nt, flags, sdst, sldd, edges, ArAc);
}

static void launch_gemm(const float* A, const float* B, const float* bias,
                        const float* res, float* C, int M, int N, int K, int flags,
                        int batch = 1, long sA = 0, long sB = 0, long sC = 0)
{
    dim3 grid(N / 128, M / 128, batch);
    gemm128<<<grid, 256>>>(A, B, bias, res, C, M, N, K, flags, sA, sB, sC);
}

static void launch_split(const float* src, int M, int K, __nv_bfloat16* dst, int ldd, int coff,
                         const float* rowscale)
{
    long total = (long)M * K;
    splitA_kernel<<<(int)((total + 255) / 256), 256>>>(src, K, dst, ldd, coff, rowscale, total);
}

static void launch_packB(const float* B, long sstride, int K, int N,
                         __nv_bfloat16* dst, long dstride, int ldd, int coff, int layers)
{
    dim3 grid((K * N + 255) / 256, 1, layers);
    packB_kernel<<<grid, 256>>>(B, sstride, K, N, dst, dstride, ldd, coff);
}

template <typename T>
static T* sym(const void* s)
{
    void* p = nullptr;
    cudaGetSymbolAddress(&p, s);
    return (T*)p;
}

extern "C" void kernel_launch(void* const* d_in, const int* in_sizes, int n_in,
                              void* d_out, int out_size)
{
    const float* X        = (const float*)d_in[0];
    const float* node_attr= (const float*)d_in[1];
    const float* edge_attr= (const float*)d_in[2];
    const float* W_in1    = (const float*)d_in[3];
    const float* b_in1    = (const float*)d_in[4];
    const float* W_in2    = (const float*)d_in[5];
    const float* b_in2    = (const float*)d_in[6];
    const float* We1      = (const float*)d_in[7];
    const float* be1      = (const float*)d_in[8];
    const float* We2      = (const float*)d_in[9];
    const float* be2      = (const float*)d_in[10];
    const float* Wv       = (const float*)d_in[11];
    const float* Wvv      = (const float*)d_in[12];
    const float* Wh1      = (const float*)d_in[13];
    const float* bh1      = (const float*)d_in[14];
    const float* Wh2      = (const float*)d_in[15];
    const float* bh2      = (const float*)d_in[16];
    const float* Wi1      = (const float*)d_in[17];
    const float* bi1      = (const float*)d_in[18];
    const float* Wi2      = (const float*)d_in[19];
    const float* bi2      = (const float*)d_in[20];
    const float* Wgv1     = (const float*)d_in[21];
    const float* Wgv2     = (const float*)d_in[22];
    const float* Wg1      = (const float*)d_in[23];
    const float* bg1      = (const float*)d_in[24];
    const float* Wg2      = (const float*)d_in[25];
    const float* bg2      = (const float*)d_in[26];
    const float* Wf       = (const float*)d_in[27];
    const int*   edges    = (const int*)d_in[28];
    float* out = (float*)d_out;

    float* p_t0     = sym<float>(g_t0);
    float* p_h      = sym<float>(g_h);
    float* p_ArAc   = sym<float>(g_ArAc);
    float* p_hintra = sym<float>(g_hintra);
    float* p_v2n    = sym<float>(g_v2n);
    float* p_mix    = sym<float>(g_mix);
    float* p_ef     = sym<float>(g_ef);
    float* p_mcat   = sym<float>(g_mcat);
    float* p_unit   = sym<float>(g_unit);
    float* p_va     = sym<float>(g_va);
    float* p_vb     = sym<float>(g_vb);
    float* p_vagg   = sym<float>(g_vagg);
    float* p_vp     = sym<float>(g_vp);
    float* p_w      = sym<float>(g_w);
    float* p_meanp  = sym<float>(g_meanp);
    float* p_meanh  = sym<float>(g_meanh);
    float* p_pv     = sym<float>(g_pv);
    float* p_pred   = sym<float>(g_pred);
    float* p_We1cat = sym<float>(g_We1cat);
    float* p_Wef    = sym<float>(g_Wef);
    float* p_W2v    = sym<float>(g_W2v);
    float* p_W2cat  = sym<float>(g_W2cat);
    float* p_b2cat  = sym<float>(g_b2cat);
    float* p_Wgvcat = sym<float>(g_Wgvcat);

    __nv_bfloat16* pa_cat = sym<__nv_bfloat16>(a2_cat);
    __nv_bfloat16* pa_u   = sym<__nv_bfloat16>(a2_u);
    __nv_bfloat16* pa_x   = sym<__nv_bfloat16>(a2_x);
    __nv_bfloat16* pa_t   = sym<__nv_bfloat16>(a2_t);
    __nv_bfloat16* pa_ef  = sym<__nv_bfloat16>(a2_ef);
    __nv_bfloat16* pa_M   = sym<__nv_bfloat16>(a2_M);
    __nv_bfloat16* pb_We1 = sym<__nv_bfloat16>(b2_We1cat);
    __nv_bfloat16* pb_Wef = sym<__nv_bfloat16>(b2_Wef);
    __nv_bfloat16* pb_W2  = sym<__nv_bfloat16>(b2_W2cat);
    __nv_bfloat16* pb_Wh1 = sym<__nv_bfloat16>(b2_Wh1);
    __nv_bfloat16* pb_Wh2 = sym<__nv_bfloat16>(b2_Wh2);
    __nv_bfloat16* pb_Wv  = sym<__nv_bfloat16>(b2_Wv);
    __nv_bfloat16* pb_Wi1 = sym<__nv_bfloat16>(b2_Wi1);
    __nv_bfloat16* pb_Wi2 = sym<__nv_bfloat16>(b2_Wi2);
    __nv_bfloat16* pb_Wgv = sym<__nv_bfloat16>(b2_Wgv);
    __nv_bfloat16* pb_Wg1 = sym<__nv_bfloat16>(b2_Wg1);
    __nv_bfloat16* pb_Wg2 = sym<__nv_bfloat16>(b2_Wg2);

    // ---- weight staging + bf16 packs ----
    pack_We1cat_kernel<<<(4 * HD * 256 + 255) / 256, 256>>>(We1, p_We1cat);
    pack_Wef_kernel<<<(4 * EFK * HD + 255) / 256, 256>>>(We1, p_Wef);
    launch_gemm(We2, Wvv, nullptr, nullptr, p_W2v, HD, HD, HD, 0,
                4, (long)HD * HD, (long)HD * HD, (long)HD * HD);
    pack_W2cat_kernel<<<(4 * HD * 256 + 255) / 256, 256>>>(We2, p_W2v, p_W2cat);
    pack_b2cat_kernel<<<4, 256>>>(be2, Wvv, p_b2cat);
    pack_Wgv_kernel<<<(HD * 256 + 255) / 256, 256>>>(Wgv1, Wgv2, p_Wgvcat);

    launch_packB(p_We1cat, (long)HD * 256, 128, 256, pb_We1, (long)256 * 384, 384, 0, 4);
    launch_packB(p_Wef, (long)EFK * HD, 64, 128, pb_Wef, (long)128 * 192, 192, 0, 4);
    launch_packB(p_W2cat, (long)HD * 256, 128, 256, pb_W2, (long)256 * 384, 384, 0, 4);
    launch_packB(Wh1, (long)256 * HD, 128, 128, pb_Wh1, (long)128 * 768, 768, 0, 4);
    launch_packB(Wh1 + 128 * HD, (long)256 * HD, 128, 128, pb_Wh1, (long)128 * 768, 768, 384, 4);
    launch_packB(Wh2, (long)HD * HD, 128, 128, pb_Wh2, (long)128 * 384, 384, 0, 4);
    launch_packB(Wv, (long)HD * HD, 128, 128, pb_Wv, (long)128 * 384, 384, 0, 4);
    launch_packB(Wi1, (long)HD * HD, 128, 128, pb_Wi1, (long)128 * 384, 384, 0, 4);
    launch_packB(Wi2, (long)HD * HD, 128, 128, pb_Wi2, (long)128 * 384, 384, 0, 4);
    launch_packB(p_Wgvcat, 0, 128, 256, pb_Wgv, 0, 384, 0, 1);
    launch_packB(Wg1, 0, 128, 128, pb_Wg1, 0, 768, 0, 1);
    launch_packB(Wg1 + 128 * HD, 0, 128, 128, pb_Wg1, 0, 768, 384, 1);
    launch_packB(Wg2, 0, 128, 256, pb_Wg2, 0, 384, 0, 1);

    // zero initial v
    zero_kernel<<<(N_NODES * 3 * HD + 255) / 256, 256>>>(p_va, N_NODES * 3 * HD);

    // edge geometry + split ef (static across layers)
    edge_geom_kernel<<<(E_EDGES + 255) / 256, 256>>>(X, edge_attr, edges, p_unit, p_ef);
    launch_split(p_ef, E_EDGES, 64, pa_ef, 192, 0, nullptr);

    // h = silu(node_attr @ W_in1 + b_in1) @ W_in2 + b_in2  (fp32), split h into pa_cat[0:384]
    launch_gemm(node_attr, W_in1, b_in1, nullptr, p_t0, N_NODES, HD, 64, FLAG_SILU);
    launch_gemm(p_t0, W_in2, b_in2, nullptr, p_h, N_NODES, HD, HD, 0);
    launch_split(p_h, N_NODES, HD, pa_cat, 768, 0, nullptr);

    float* vin = p_va;
    float* vout = p_vb;

    for (int i = 0; i < 4; i++) {
        const float* be1_i = be1 + i * HD;
        const float* bh1_i = bh1 + i * HD;
        const float* bh2_i = bh2 + i * HD;
        const float* bi1_i = bi1 + i * HD;
        const float* bi2_i = bi2 + i * HD;

        // [Ar|Ac] = h @ [W_r|W_c]   (reads pa_cat[0:384])
        launch_tc(pa_cat, 768, 384, pb_We1 + (long)i * 256 * 384,
                  nullptr, nullptr, p_ArAc, N_NODES, 256, 0);

        // t = silu(ef@Wef + be1 + Ar[row] + Ac[col]) -> split bf16 pa_t directly
        launch_tc(pa_ef, 192, 192, pb_Wef + (long)i * 128 * 192,
                  be1_i, nullptr, nullptr, E_EDGES, 128, FLAG_SILU | FLAG_COMBINE,
                  pa_t, 384, edges, p_ArAc);

        // [m | mvv] = t @ [We2 | We2@Wvv] + [be2 | be2@Wvv]
        launch_tc(pa_t, 384, 384, pb_W2 + (long)i * 256 * 384,
                  p_b2cat + i * 256, nullptr, p_mcat, E_EDGES, 256, 0);

        // agg + directional moments -> split bf16 outputs
        aggM_kernel<<<N_NODES, HD>>>(p_mcat, p_unit, pa_cat + 384, pa_M);

        // u = silu([h|agg] @ Wh1 + bh1) -> split pa_u (no fp32)
        launch_tc(pa_cat, 768, 768, pb_Wh1 + (long)i * 128 * 768,
                  bh1_i, nullptr, nullptr, N_NODES, 128, FLAG_SILU, pa_u, 384);
        // h_intra = h + u @ Wh2 + bh2
        launch_tc(pa_u, 384, 384, pb_Wh2 + (long)i * 128 * 384,
                  bh2_i, p_h, p_hintra, N_NODES, 128, 0);

        // vagg = M @ Wv ; v update
        launch_tc(pa_M, 384, 384, pb_Wv + (long)i * 128 * 384,
                  nullptr, nullptr, p_vagg, 3 * N_NODES, 128, 0);
        vupdate_kernel<<<N_NODES, HD>>>(vin, vout, p_mcat, p_vagg, edges);

        // segment attention
        {
            dim3 g1(NSEG, 8);
            meanh1_kernel<<<g1, HD>>>(p_hintra, p_meanp);
            meanh2_kernel<<<NSEG, HD>>>(p_meanp, p_meanh);
        }
        attn_kernel<<<NSEG, SEGSZ>>>(p_hintra, p_meanh, p_w);
        // u = silu((hintra*w) @ Wi1 + bi1) -> split pa_u
        launch_split(p_hintra, N_NODES, HD, pa_x, 384, 0, p_w);
        launch_tc(pa_x, 384, 384, pb_Wi1 + (long)i * 128 * 384,
                  bi1_i, nullptr, nullptr, N_NODES, 128, FLAG_SILU, pa_u, 384);
        // h = hintra + u @ Wi2 + bi2 ; also split new h into pa_cat[0:384]
        launch_tc(pa_u, 384, 384, pb_Wi2 + (long)i * 128 * 384,
                  bi2_i, p_hintra, p_h, N_NODES, 128, 0, pa_cat, 768);

        float* tmp = vin; vin = vout; vout = tmp;
    }

    // [v1 | v2] = v @ [Wgv1 | Wgv2]
    launch_split(vin, 3 * N_NODES, HD, pa_M, 384, 0, nullptr);
    launch_tc(pa_M, 384, 384, pb_Wgv, nullptr, nullptr, p_vp, 3 * N_NODES, 256, 0);
    v2n_kernel<<<(N_NODES * HD + 255) / 256, 256>>>(p_vp, p_v2n);

    // mix = silu([h|v2n] @ Wg1 + bg1) @ Wg2 + bg2   (h split already in pa_cat[0:384])
    launch_split(p_v2n, N_NODES, HD, pa_cat, 768, 384, nullptr);
    launch_tc(pa_cat, 768, 768, pb_Wg1, bg1, nullptr, nullptr, N_NODES, 128, FLAG_SILU, pa_u, 384);
    launch_tc(pa_u, 384, 384, pb_Wg2, bg2, nullptr, p_mix, N_NODES, 256, 0);

    // epilogue
    pv_kernel<<<N_NODES, HD>>>(p_vp, p_mix, Wf, p_pv);
    predsum_kernel<<<NSEG, 32>>>(p_pv, p_pred);
    final_kernel<<<1, 32>>>(p_pred, out);
}

// round 7
// speedup vs baseline: 1.8935x; 1.1205x over previous
#include <cuda_runtime.h>
#include <cuda_bf16.h>
#include <math.h>
#include <stdint.h>

#define N_NODES 16384
#define E_EDGES 147456
#define HD 128
#define NSEG 32
#define SEGSZ 512
#define KEDGE 9
#define EFK 64

#define FLAG_SILU 1
#define FLAG_RESPRE 2
#define FLAG_COMBINE 4

// ---------------- fp32 scratch ----------------
__device__ float g_t0[N_NODES * HD];
__device__ float g_h[N_NODES * HD];
__device__ float g_ArAc[N_NODES * 2 * HD];
__device__ float g_hintra[N_NODES * HD];
__device__ float g_v2n[N_NODES * HD];
__device__ float g_mix[N_NODES * 2 * HD];
__device__ float g_ef[(long)E_EDGES * EFK];
__device__ float g_mvv[(long)E_EDGES * HD];
__device__ float g_unit[E_EDGES * 3];
__device__ float g_usum[N_NODES * 3];
__device__ float g_va[N_NODES * 3 * HD];
__device__ float g_vb[N_NODES * 3 * HD];
__device__ float g_vagg[N_NODES * 3 * HD];
__device__ float g_vp[(long)N_NODES * 3 * 256];
__device__ float g_w[N_NODES];
__device__ float g_meanp[NSEG * 8 * HD];
__device__ float g_meanh[NSEG * HD];
__device__ float g_pv[N_NODES * 27];
__device__ float g_pred[NSEG * 27];
// fp32 weight staging
__device__ float g_We1cat[4 * HD * 256];
__device__ float g_Wef[4 * EFK * HD];
__device__ float g_W2v[4 * HD * HD];   // We2 @ Wvv
__device__ float g_MWv[4 * HD * HD];   // We2 @ Wv
__device__ float g_Wgvcat[HD * 256];
__device__ float g_b9[4 * HD];
__device__ float g_bWv[4 * HD];
__device__ float g_bWvv[4 * HD];

// ---------------- bf16 split operand buffers ----------------
__device__ __align__(16) __nv_bfloat16 a2_cat[(long)N_NODES * 768];
__device__ __align__(16) __nv_bfloat16 a2_u[(long)N_NODES * 384];
__device__ __align__(16) __nv_bfloat16 a2_x[(long)N_NODES * 384];
__device__ __align__(16) __nv_bfloat16 a2_t[(long)E_EDGES * 384];
__device__ __align__(16) __nv_bfloat16 a2_ef[(long)E_EDGES * 192];
__device__ __align__(16) __nv_bfloat16 a2_M[(long)3 * N_NODES * 384];
__device__ __align__(16) __nv_bfloat16 b2_We1cat[4 * 256 * 384];
__device__ __align__(16) __nv_bfloat16 b2_Wef[4 * 128 * 192];
__device__ __align__(16) __nv_bfloat16 b2_W2v[4 * 128 * 384];
__device__ __align__(16) __nv_bfloat16 b2_MWv[4 * 128 * 384];
__device__ __align__(16) __nv_bfloat16 b2_We2[4 * 128 * 384];
__device__ __align__(16) __nv_bfloat16 b2_Wh1[4 * 128 * 768];
__device__ __align__(16) __nv_bfloat16 b2_Wh2[4 * 128 * 384];
__device__ __align__(16) __nv_bfloat16 b2_Wi1[4 * 128 * 384];
__device__ __align__(16) __nv_bfloat16 b2_Wi2[4 * 128 * 384];
__device__ __align__(16) __nv_bfloat16 b2_Wgv[256 * 384];
__device__ __align__(16) __nv_bfloat16 b2_Wg1[128 * 768];
__device__ __align__(16) __nv_bfloat16 b2_Wg2[256 * 384];

// ---------------- helpers ----------------
__device__ __forceinline__ uint32_t smem_to_u32(const void* p) {
    uint32_t a;
    asm("{ .reg .u64 t; cvta.to.shared.u64 t, %1; cvt.u32.u64 %0, t; }" : "=r"(a) : "l"(p));
    return a;
}
__device__ __forceinline__ void wsplit1(__nv_bfloat16* d, int K, float x) {
    __nv_bfloat16 hi = __float2bfloat16(x);
    __nv_bfloat16 lo = __float2bfloat16(x - __bfloat162float(hi));
    d[0] = hi; d[K] = lo; d[2 * K] = hi;
}
#define CP16(dst, src) \
    asm volatile("cp.async.cg.shared.global [%0], [%1], 16;" :: "r"(dst), "l"(src) : "memory")
#define CP_COMMIT() asm volatile("cp.async.commit_group;" ::: "memory")
#define CP_WAIT1()  asm volatile("cp.async.wait_group 1;" ::: "memory")
#define CP_WAIT0()  asm volatile("cp.async.wait_group 0;" ::: "memory")

// ---------------- bf16-split tensor-core GEMM via mma.sync + cp.async ----------------
// A2: (M, lda) bf16 row-major. B2: (Nt, Ktot) bf16 row-major. Ktot % 32 == 0.
// 128x128 block tile, 8 warps (64x32 warp tile), 2-stage cp.async pipeline.
#define SMS 40

__global__ __launch_bounds__(256)
void tcgemm(const __nv_bfloat16* __restrict__ A2, int lda, int Ktot,
            const __nv_bfloat16* __restrict__ B2,
            const float* __restrict__ bias, const float* __restrict__ res,
            float* __restrict__ C, int Nt, int flags,
            __nv_bfloat16* __restrict__ sdst, int sldd,
            const int* __restrict__ edges, const float* __restrict__ ArAc)
{
    __shared__ __align__(16) __nv_bfloat16 As[2][128 * SMS];
    __shared__ __align__(16) __nv_bfloat16 Bs[2][128 * SMS];

    const int t = threadIdx.x;
    const int lid = t & 31;
    const int wid = t >> 5;
    const int wm = wid & 1;
    const int wn = wid >> 1;
    const int bm = blockIdx.y * 128;
    const int bn = blockIdx.x * 128;

    float acc[4][4][4];
#pragma unroll
    for (int i = 0; i < 4; i++)
#pragma unroll
        for (int j = 0; j < 4; j++)
#pragma unroll
            for (int r = 0; r < 4; r++) acc[i][j][r] = 0.0f;

    const int r0 = t >> 2;
    const int r1 = r0 + 64;
    const int kq = (t & 3) << 3;

    const int a_row = wm * 64 + (lid & 7) + ((lid >> 3) & 1) * 8;
    const int a_col = ((lid >> 4) & 1) * 8;
    const int a_off = a_row * SMS + a_col;
    const int b_row = wn * 32 + (lid & 7);
    const int b_col = ((lid >> 3) & 1) * 8;
    const int b_off = b_row * SMS + b_col;

    const int iters = Ktot >> 5;

    // prologue: stage 0
    CP16(smem_to_u32(&As[0][r0 * SMS + kq]), A2 + (long)(bm + r0) * lda + kq);
    CP16(smem_to_u32(&As[0][r1 * SMS + kq]), A2 + (long)(bm + r1) * lda + kq);
    CP16(smem_to_u32(&Bs[0][r0 * SMS + kq]), B2 + (long)(bn + r0) * Ktot + kq);
    CP16(smem_to_u32(&Bs[0][r1 * SMS + kq]), B2 + (long)(bn + r1) * Ktot + kq);
    CP_COMMIT();

    for (int it = 0; it < iters; it++) {
        const int buf = it & 1;
        if (it + 1 < iters) {
            const int nb = buf ^ 1;
            const int k0 = (it + 1) << 5;
            CP16(smem_to_u32(&As[nb][r0 * SMS + kq]), A2 + (long)(bm + r0) * lda + k0 + kq);
            CP16(smem_to_u32(&As[nb][r1 * SMS + kq]), A2 + (long)(bm + r1) * lda + k0 + kq);
            CP16(smem_to_u32(&Bs[nb][r0 * SMS + kq]), B2 + (long)(bn + r0) * Ktot + k0 + kq);
            CP16(smem_to_u32(&Bs[nb][r1 * SMS + kq]), B2 + (long)(bn + r1) * Ktot + k0 + kq);
            CP_COMMIT();
            CP_WAIT1();
        } else {
            CP_WAIT0();
        }
        __syncthreads();

        const uint32_t aBase = smem_to_u32(&As[buf][0]);
        const uint32_t bBase = smem_to_u32(&Bs[buf][0]);
#pragma unroll
        for (int ks = 0; ks < 2; ks++) {
            uint32_t a[4][4];
#pragma unroll
            for (int i = 0; i < 4; i++) {
                const uint32_t addr = aBase + 2u * (a_off + i * 16 * SMS + ks * 16);
                asm volatile(
                    "ldmatrix.sync.aligned.m8n8.x4.shared.b16 {%0,%1,%2,%3}, [%4];"
                    : "=r"(a[i][0]), "=r"(a[i][1]), "=r"(a[i][2]), "=r"(a[i][3])
                    : "r"(addr));
            }
            uint32_t b[4][2];
#pragma unroll
            for (int j = 0; j < 4; j++) {
                const uint32_t addr = bBase + 2u * (b_off + j * 8 * SMS + ks * 16);
                asm volatile(
                    "ldmatrix.sync.aligned.m8n8.x2.shared.b16 {%0,%1}, [%2];"
                    : "=r"(b[j][0]), "=r"(b[j][1])
                    : "r"(addr));
            }
#pragma unroll
            for (int i = 0; i < 4; i++)
#pragma unroll
                for (int j = 0; j < 4; j++) {
                    asm volatile(
                        "mma.sync.aligned.m16n8k16.row.col.f32.bf16.bf16.f32 "
                        "{%0,%1,%2,%3}, {%4,%5,%6,%7}, {%8,%9}, {%0,%1,%2,%3};"
                        : "+f"(acc[i][j][0]), "+f"(acc[i][j][1]),
                          "+f"(acc[i][j][2]), "+f"(acc[i][j][3])
                        : "r"(a[i][0]), "r"(a[i][1]), "r"(a[i][2]), "r"(a[i][3]),
                          "r"(b[j][0]), "r"(b[j][1]));
                }
        }
        __syncthreads();
    }

    // epilogue
    const bool f_silu = (flags & FLAG_SILU) != 0;
    const bool f_respre = (flags & FLAG_RESPRE) != 0;
    const bool f_comb = (flags & FLAG_COMBINE) != 0;
    const int g = lid >> 2;
    const int t2 = (lid & 3) << 1;
#pragma unroll
    for (int i = 0; i < 4; i++) {
#pragma unroll
        for (int half = 0; half < 2; half++) {
            const int m = bm + wm * 64 + i * 16 + g + half * 8;
            int rrow = 0, ccol = 0;
            if (f_comb) { rrow = m / KEDGE; ccol = edges[E_EDGES + m]; }
#pragma unroll
            for (int j = 0; j < 4; j++) {
                const int n0 = bn + wn * 32 + j * 8 + t2;
                const long base = (long)m * Nt + n0;
                float v0 = acc[i][j][2 * half + 0];
                float v1 = acc[i][j][2 * half + 1];
                if (bias) { v0 += bias[n0]; v1 += bias[n0 + 1]; }
                if (f_comb) {
                    v0 += ArAc[(long)rrow * 256 + n0] + ArAc[(long)ccol * 256 + 128 + n0];
                    v1 += ArAc[(long)rrow * 256 + n0 + 1] + ArAc[(long)ccol * 256 + 128 + n0 + 1];
                }
                if (f_respre && res) { v0 += res[base]; v1 += res[base + 1]; }
                if (f_silu) {
                    v0 = v0 / (1.0f + __expf(-v0));
                    v1 = v1 / (1.0f + __expf(-v1));
                }
                if (!f_respre && res) { v0 += res[base]; v1 += res[base + 1]; }
                if (C) *(float2*)&C[base] = make_float2(v0, v1);
                if (sdst) {
                    __nv_bfloat16 h0 = __float2bfloat16(v0);
                    __nv_bfloat16 h1 = __float2bfloat16(v1);
                    __nv_bfloat16 l0 = __float2bfloat16(v0 - __bfloat162float(h0));
                    __nv_bfloat16 l1 = __float2bfloat16(v1 - __bfloat162float(h1));
                    __nv_bfloat16* d = sdst + (long)m * sldd + n0;
                    __nv_bfloat162 hv; hv.x = h0; hv.y = h1;
                    __nv_bfloat162 lv; lv.x = l0; lv.y = l1;
                    *(__nv_bfloat162*)&d[0] = hv;
                    *(__nv_bfloat162*)&d[Nt] = lv;
                    *(__nv_bfloat162*)&d[2 * Nt] = hv;
                }
            }
        }
    }
}

// ---------------- split kernel (fp32 -> [hi|lo|hi]) ----------------
__global__ void splitA_kernel(const float* __restrict__ src, int K,
                              __nv_bfloat16* __restrict__ dst, int ldd, int coff,
                              const float* __restrict__ rowscale, long total)
{
    long idx = (long)blockIdx.x * blockDim.x + threadIdx.x;
    if (idx >= total) return;
    int k = (int)(idx % K);
    long row = idx / K;
    float x = src[idx];
    if (rowscale) x *= rowscale[row];
    wsplit1(dst + row * ldd + coff + k, K, x);
}

// ---------------- fp32 GEMM (setup / initial MLP), grid.z batched ----------------
__device__ __forceinline__ unsigned long long pack2(float lo, float hi) {
    unsigned long long r;
    asm("mov.b64 %0, {%1, %2};" : "=l"(r) : "f"(lo), "f"(hi));
    return r;
}
__device__ __forceinline__ unsigned long long dup2(float v) {
    unsigned long long r;
    asm("mov.b64 %0, {%1, %1};" : "=l"(r) : "f"(v));
    return r;
}
__device__ __forceinline__ void fma2(unsigned long long& acc, unsigned long long a, unsigned long long b) {
    asm("fma.rn.f32x2 %0, %1, %2, %0;" : "+l"(acc) : "l"(a), "l"(b));
}
__device__ __forceinline__ void unpack2(unsigned long long p, float& lo, float& hi) {
    asm("mov.b64 {%0, %1}, %2;" : "=f"(lo), "=f"(hi) : "l"(p));
}

__global__ __launch_bounds__(256, 1)
void gemm128(const float* __restrict__ A, const float* __restrict__ B,
             const float* __restrict__ bias, const float* __restrict__ res,
             float* __restrict__ C, int M, int N, int K, int flags,
             long sA, long sB, long sC)
{
    A += blockIdx.z * sA; B += blockIdx.z * sB; C += blockIdx.z * sC;
    __shared__ float As[2][16][128];
    __shared__ float Bs[2][16][128];
    const int bm = blockIdx.y * 128;
    const int bn = blockIdx.x * 128;
    const int t = threadIdx.x;
    const int ty = t >> 4;
    const int tx = t & 15;

    unsigned long long acc2[8][4];
#pragma unroll
    for (int i = 0; i < 8; i++)
#pragma unroll
        for (int j = 0; j < 4; j++) acc2[i][j] = 0ull;

    const int tiles = K >> 4;
    const int a_row0 = t >> 2;
    const int a_kc = (t & 3) << 2;
    const int b_k0 = t >> 5;
    const int b_n4 = (t & 31) << 2;

    {
#pragma unroll
        for (int r = 0; r < 2; r++) {
            int row = a_row0 + r * 64;
            float4 v = *(const float4*)&A[(long)(bm + row) * K + a_kc];
            As[0][a_kc + 0][row] = v.x; As[0][a_kc + 1][row] = v.y;
            As[0][a_kc + 2][row] = v.z; As[0][a_kc + 3][row] = v.w;
        }
#pragma unroll
        for (int r = 0; r < 2; r++) {
            int k = b_k0 + r * 8;
            *(float4*)&Bs[0][k][b_n4] = *(const float4*)&B[(long)k * N + bn + b_n4];
        }
    }
    __syncthreads();

    for (int tt = 0; tt < tiles; tt++) {
        const int buf = tt & 1;
        float4 pa[2], pb[2];
        if (tt + 1 < tiles) {
            const int k0n = (tt + 1) << 4;
#pragma unroll
            for (int r = 0; r < 2; r++)
                pa[r] = *(const float4*)&A[(long)(bm + a_row0 + r * 64) * K + k0n + a_kc];
#pragma unroll
            for (int r = 0; r < 2; r++)
                pb[r] = *(const float4*)&B[(long)(k0n + b_k0 + r * 8) * N + bn + b_n4];
        }
#pragma unroll
        for (int k = 0; k < 16; k++) {
            float a[8];
            float4 a0 = *(const float4*)&As[buf][k][ty * 8];
            float4 a1 = *(const float4*)&As[buf][k][ty * 8 + 4];
            a[0] = a0.x; a[1] = a0.y; a[2] = a0.z; a[3] = a0.w;
            a[4] = a1.x; a[5] = a1.y; a[6] = a1.z; a[7] = a1.w;
            float4 b0 = *(const float4*)&Bs[buf][k][tx * 8];
            float4 b1 = *(const float4*)&Bs[buf][k][tx * 8 + 4];
            unsigned long long b2[4];
            b2[0] = pack2(b0.x, b0.y); b2[1] = pack2(b0.z, b0.w);
            b2[2] = pack2(b1.x, b1.y); b2[3] = pack2(b1.z, b1.w);
#pragma unroll
            for (int i = 0; i < 8; i++) {
                unsigned long long ad = dup2(a[i]);
#pragma unroll
                for (int j = 0; j < 4; j++) fma2(acc2[i][j], ad, b2[j]);
            }
        }
        if (tt + 1 < tiles) {
            const int nb = buf ^ 1;
#pragma unroll
            for (int r = 0; r < 2; r++) {
                int row = a_row0 + r * 64;
                As[nb][a_kc + 0][row] = pa[r].x; As[nb][a_kc + 1][row] = pa[r].y;
                As[nb][a_kc + 2][row] = pa[r].z; As[nb][a_kc + 3][row] = pa[r].w;
            }
#pragma unroll
            for (int r = 0; r < 2; r++)
                *(float4*)&Bs[nb][b_k0 + r * 8][b_n4] = pb[r];
        }
        __syncthreads();
    }

    const bool silu = (flags & FLAG_SILU) != 0;
#pragma unroll
    for (int i = 0; i < 8; i++) {
        const int m = bm + ty * 8 + i;
        float cv[8];
#pragma unroll
        for (int j = 0; j < 4; j++) unpack2(acc2[i][j], cv[2 * j], cv[2 * j + 1]);
        const long base = (long)m * N + bn + tx * 8;
#pragma unroll
        for (int j = 0; j < 8; j++) {
            float v = cv[j];
            if (bias) v += bias[bn + tx * 8 + j];
            if (silu) v = v / (1.0f + __expf(-v));
            if (res) v += res[base + j];
            cv[j] = v;
        }
        float4* cp = (float4*)&C[base];
        cp[0] = make_float4(cv[0], cv[1], cv[2], cv[3]);
        cp[1] = make_float4(cv[4], cv[5], cv[6], cv[7]);
    }
}

// ---------------- staging pack kernels (fp32) ----------------
__global__ void pack_We1cat_kernel(const float* __restrict__ We1, float* __restrict__ out)
{
    int idx = blockIdx.x * blockDim.x + threadIdx.x;
    if (idx >= 4 * HD * 256) return;
    int l = idx / (HD * 256);
    int rem = idx - l * HD * 256;
    int k = rem >> 8, n = rem & 255;
    const float* base = We1 + (long)l * 292 * HD;
    out[idx] = (n < HD) ? base[k * HD + n] : base[(HD + k) * HD + (n - HD)];
}
__global__ void pack_Wef_kernel(const float* __restrict__ We1, float* __restrict__ out)
{
    int idx = blockIdx.x * blockDim.x + threadIdx.x;
    if (idx >= 4 * EFK * HD) return;
    int l = idx / (EFK * HD);
    int rem = idx - l * EFK * HD;
    int k = rem >> 7, n = rem & 127;
    out[idx] = (k < 36) ? We1[(long)l * 292 * HD + (256 + k) * HD + n] : 0.0f;
}
__global__ void pack_Wgv_kernel(const float* __restrict__ Wgv1, const float* __restrict__ Wgv2,
                                float* __restrict__ out)
{
    int idx = blockIdx.x * blockDim.x + threadIdx.x;
    if (idx >= HD * 256) return;
    int k = idx >> 8, n = idx & 255;
    out[idx] = (n < HD) ? Wgv1[k * HD + n] : Wgv2[k * HD + (n - HD)];
}
// b9 = 9*be2 ; bWv = be2@Wv ; bWvv = be2@Wvv   (per layer)
__global__ void bias_pre_kernel(const float* __restrict__ be2, const float* __restrict__ Wv,
                                const float* __restrict__ Wvv,
                                float* __restrict__ b9, float* __restrict__ bWv,
                                float* __restrict__ bWvv)
{
    int l = blockIdx.x;
    int n = threadIdx.x;
    const float* b = be2 + l * HD;
    b9[l * HD + n] = 9.0f * b[n];
    float s1 = 0.f, s2 = 0.f;
    const float* w1 = Wv + (long)l * HD * HD;
    const float* w2 = Wvv + (long)l * HD * HD;
#pragma unroll 8
    for (int k = 0; k < HD; k++) {
        s1 += b[k] * w1[k * HD + n];
        s2 += b[k] * w2[k * HD + n];
    }
    bWv[l * HD + n] = s1;
    bWvv[l * HD + n] = s2;
}

// ---------------- single fused bf16 B-pack ----------------
#define NJOBS 14
struct PackJobs {
    const float* src[NJOBS];
    long sstride[NJOBS];
    long dstride[NJOBS];
    __nv_bfloat16* dst[NJOBS];
    int K[NJOBS];
    int N[NJOBS];
    int ldd[NJOBS];
    int coff[NJOBS];
    int layers[NJOBS];
};
__global__ void pack_all_kernel(PackJobs J)
{
    int j = blockIdx.y;
    int l = blockIdx.z;
    if (l >= J.layers[j]) return;
    int idx = blockIdx.x * 256 + threadIdx.x;
    int KN = J.K[j] * J.N[j];
    if (idx >= KN) return;
    int k = idx / J.N[j], n = idx % J.N[j];
    float x = J.src[j][(long)l * J.sstride[j] + idx];
    __nv_bfloat16 hi = __float2bfloat16(x);
    __nv_bfloat16 lo = __float2bfloat16(x - __bfloat162float(hi));
    __nv_bfloat16* d = J.dst[j] + (long)l * J.dstride[j] + (long)n * J.ldd[j] + J.coff[j];
    d[k] = hi;
    d[J.K[j] + k] = hi;
    d[2 * J.K[j] + k] = lo;
}

// ---------------- elementwise / reduction kernels ----------------
__global__ void edge_geom_kernel(const float* __restrict__ X, const float* __restrict__ edge_attr,
                                 const int* __restrict__ edges,
                                 float* __restrict__ unit, float* __restrict__ ef)
{
    int e = blockIdx.x * blockDim.x + threadIdx.x;
    if (e >= E_EDGES) return;
    int r = edges[e];
    int c = edges[E_EDGES + e];
    float dx = X[r * 3 + 0] - X[c * 3 + 0];
    float dy = X[r * 3 + 1] - X[c * 3 + 1];
    float dz = X[r * 3 + 2] - X[c * 3 + 2];
    float norm = sqrtf(dx * dx + dy * dy + dz * dz) + 1e-8f;
    float invn = 1.0f / norm;
    unit[e * 3 + 0] = dx * invn;
    unit[e * 3 + 1] = dy * invn;
    unit[e * 3 + 2] = dz * invn;
    const float PI_ = 3.14159265358979323846f;
    float cn = fminf(norm, 1.0f);
    float cut = 0.5f * (cosf(PI_ * cn) + 1.0f);
    float f = cut * invn;
#pragma unroll
    for (int j = 0; j < 20; j++)
        ef[(long)e * EFK + j] = sinf(norm * PI_ * (float)(j + 1)) * f;
#pragma unroll
    for (int j = 0; j < 16; j++)
        ef[(long)e * EFK + 20 + j] = edge_attr[e * 16 + j];
#pragma unroll
    for (int j = 36; j < EFK; j++)
        ef[(long)e * EFK + j] = 0.0f;
}

// aggregate t over each node's 9 edges: agg_t -> aggdst (split, ld 384, coff 0),
// Mt (t weighted by unit components) -> Mdst (split, 3 rows/node), Usum[n,c] = sum_j u_c
__global__ void aggT_kernel(const __nv_bfloat16* __restrict__ t2, const float* __restrict__ unit,
                            __nv_bfloat16* __restrict__ aggdst, __nv_bfloat16* __restrict__ Mdst,
                            float* __restrict__ usum)
{
    int n = blockIdx.x;
    int hh = threadIdx.x;
    float s = 0.f, mx = 0.f, my = 0.f, mz = 0.f;
#pragma unroll
    for (int j = 0; j < KEDGE; j++) {
        long e = (long)n * KEDGE + j;
        float tt = __bfloat162float(t2[e * 384 + hh]) + __bfloat162float(t2[e * 384 + 128 + hh]);
        float ux = unit[e * 3 + 0];
        float uy = unit[e * 3 + 1];
        float uz = unit[e * 3 + 2];
        s += tt; mx += tt * ux; my += tt * uy; mz += tt * uz;
    }
    wsplit1(aggdst + (long)n * 384 + hh, 128, s);
    wsplit1(Mdst + (long)(3 * n + 0) * 384 + hh, 128, mx);
    wsplit1(Mdst + (long)(3 * n + 1) * 384 + hh, 128, my);
    wsplit1(Mdst + (long)(3 * n + 2) * 384 + hh, 128, mz);
    if (hh < 3) {
        float u = 0.f;
#pragma unroll
        for (int j = 0; j < KEDGE; j++) u += unit[((long)n * KEDGE + j) * 3 + hh];
        usum[n * 3 + hh] = u;
    }
}

// v_new[n,c] = vin[n,c] + vagg[n,c] + Usum[n,c]*bWv + sum_j mvv[e] * vin[col_e,c]
__global__ void vupdate_kernel(const float* __restrict__ vin, float* __restrict__ vout,
                               const float* __restrict__ mvv, const float* __restrict__ vagg,
                               const float* __restrict__ usum, const float* __restrict__ bWv,
                               const int* __restrict__ edges)
{
    int n = blockIdx.x;
    int hh = threadIdx.x;
    float bw = bWv[hh];
    float a0 = vagg[(long)n * 384 + hh]       + usum[n * 3 + 0] * bw;
    float a1 = vagg[(long)n * 384 + 128 + hh] + usum[n * 3 + 1] * bw;
    float a2 = vagg[(long)n * 384 + 256 + hh] + usum[n * 3 + 2] * bw;
    if (vin) {
        a0 += vin[(long)n * 384 + hh];
        a1 += vin[(long)n * 384 + 128 + hh];
        a2 += vin[(long)n * 384 + 256 + hh];
#pragma unroll
        for (int j = 0; j < KEDGE; j++) {
            long e = (long)n * KEDGE + j;
            int c = edges[E_EDGES + e];
            float b = mvv[e * HD + hh];
            a0 += b * vin[(long)c * 384 + hh];
            a1 += b * vin[(long)c * 384 + 128 + hh];
            a2 += b * vin[(long)c * 384 + 256 + hh];
        }
    }
    vout[(long)n * 384 + hh] = a0;
    vout[(long)n * 384 + 128 + hh] = a1;
    vout[(long)n * 384 + 256 + hh] = a2;
}

__global__ void meanh1_kernel(const float* __restrict__ hintra, float* __restrict__ part)
{
    int s = blockIdx.x;
    int c = blockIdx.y;
    int k = threadIdx.x;
    float acc = 0.0f;
    const float* p = hintra + ((long)s * SEGSZ + c * 64) * HD + k;
#pragma unroll 8
    for (int u = 0; u < 64; u++) acc += p[u * HD];
    part[(s * 8 + c) * HD + k] = acc;
}
__global__ void meanh2_kernel(const float* __restrict__ part, float* __restrict__ meanh)
{
    int s = blockIdx.x;
    int k = threadIdx.x;
    float a = 0.0f;
#pragma unroll
    for (int c = 0; c < 8; c++) a += part[(s * 8 + c) * HD + k];
    meanh[s * HD + k] = a * (1.0f / (float)SEGSZ);
}

__global__ void attn_kernel(const float* __restrict__ hintra, const float* __restrict__ meanh,
                            float* __restrict__ w)
{
    int s = blockIdx.x;
    int t = threadIdx.x;
    __shared__ float sm[HD];
    __shared__ float red[SEGSZ];
    int opp = s ^ 1;
    if (t < HD) sm[t] = meanh[opp * HD + t];
    __syncthreads();
    int node = s * SEGSZ + t;
    const float* hr = hintra + (long)node * HD;
    float sc = 0.0f;
#pragma unroll 8
    for (int k = 0; k < HD; k++) sc += hr[k] * sm[k];
    red[t] = sc;
    __syncthreads();
    for (int st = SEGSZ / 2; st > 0; st >>= 1) {
        if (t < st) red[t] = fmaxf(red[t], red[t + st]);
        __syncthreads();
    }
    float mx = red[0];
    __syncthreads();
    float ex = expf(sc - mx);
    red[t] = ex;
    __syncthreads();
    for (int st = SEGSZ / 2; st > 0; st >>= 1) {
        if (t < st) red[t] += red[t + st];
        __syncthreads();
    }
    w[node] = ex / red[0];
}

__global__ void v2n_kernel(const float* __restrict__ vp, float* __restrict__ v2n)
{
    int idx = blockIdx.x * blockDim.x + threadIdx.x;
    if (idx >= N_NODES * HD) return;
    int n = idx / HD;
    int k = idx % HD;
    float a = vp[(long)(n * 3 + 0) * 256 + HD + k];
    float b = vp[(long)(n * 3 + 1) * 256 + HD + k];
    float c = vp[(long)(n * 3 + 2) * 256 + HD + k];
    v2n[idx] = sqrtf(a * a + b * b + c * c + 1e-8f);
}

__global__ void pv_kernel(const float* __restrict__ vp, const float* __restrict__ mix,
                          const float* __restrict__ Wf, float* __restrict__ pv)
{
    int n = blockIdx.x;
    int k = threadIdx.x;
    __shared__ float sd[3][HD];
    float hf = mix[(long)n * 256 + k];
    float bg = mix[(long)n * 256 + HD + k];
    float s = hf * bg;
    sd[0][k] = vp[(long)(n * 3 + 0) * 256 + k] * s;
    sd[1][k] = vp[(long)(n * 3 + 1) * 256 + k] * s;
    sd[2][k] = vp[(long)(n * 3 + 2) * 256 + k] * s;
    __syncthreads();
    if (k < 27) {
        int o = k / 3, c = k % 3;
        float acc = 0.0f;
#pragma unroll 8
        for (int kk = 0; kk < HD; kk++) acc += sd[c][kk] * Wf[kk * 9 + o];
        pv[(long)n * 27 + k] = acc;
    }
}

__global__ void predsum_kernel(const float* __restrict__ pv, float* __restrict__ pred)
{
    int s = blockIdx.x;
    int j = threadIdx.x;
    if (j >= 27) return;
    float acc = 0.0f;
    for (int u = 0; u < SEGSZ; u++)
        acc += pv[(long)(s * SEGSZ + u) * 27 + j];
    pred[s * 27 + j] = acc;
}

__global__ void final_kernel(const float* __restrict__ pred, float* __restrict__ out)
{
    int s = threadIdx.x;
    if (s >= NSEG) return;
    const float* p = pred + s * 27;
#pragma unroll
    for (int r = 0; r < 3; r++) {
#pragma unroll
        for (int c = 0; c < 3; c++) {
            float A = p[0 * 3 + r] * p[1 * 3 + c]
                    + p[3 * 3 + r] * p[2 * 3 + c]
                    + p[4 * 3 + r] * p[5 * 3 + c]
                    + p[7 * 3 + r] * p[6 * 3 + c];
            out[s * 12 + r * 4 + c] = A * 100.0f;
        }
        out[s * 12 + r * 4 + 3] = p[8 * 3 + r] * 10.0f;
    }
}

// ---------------- host driver ----------------
static void launch_tc(const __nv_bfloat16* A2, int lda, int Ktot, const __nv_bfloat16* B2,
                      const float* bias, const float* res, float* C, int M, int Nt, int flags,
                      __nv_bfloat16* sdst = nullptr, int sldd = 0,
                      const int* edges = nullptr, const float* ArAc = nullptr)
{
    dim3 grid(Nt / 128, M / 128);
    tcgemm<<<grid, 256>>>(A2, lda, Ktot, B2, bias, res, C, Nt, flags, sdst, sldd, edges, ArAc);
}

static void launch_gemm(const float* A, const float* B, const float* bias,
                        const float* res, float* C, int M, int N, int K, int flags,
                        int batch = 1, long sA = 0, long sB = 0, long sC = 0)
{
    dim3 grid(N / 128, M / 128, batch);
    gemm128<<<grid, 256>>>(A, B, bias, res, C, M, N, K, flags, sA, sB, sC);
}

static void launch_split(const float* src, int M, int K, __nv_bfloat16* dst, int ldd, int coff,
                         const float* rowscale)
{
    long total = (long)M * K;
    splitA_kernel<<<(int)((total + 255) / 256), 256>>>(src, K, dst, ldd, coff, rowscale, total);
}

template <typename T>
static T* sym(const void* s)
{
    void* p = nullptr;
    cudaGetSymbolAddress(&p, s);
    return (T*)p;
}

extern "C" void kernel_launch(void* const* d_in, const int* in_sizes, int n_in,
                              void* d_out, int out_size)
{
    const float* X        = (const float*)d_in[0];
    const float* node_attr= (const float*)d_in[1];
    const float* edge_attr= (const float*)d_in[2];
    const float* W_in1    = (const float*)d_in[3];
    const float* b_in1    = (const float*)d_in[4];
    const float* W_in2    = (const float*)d_in[5];
    const float* b_in2    = (const float*)d_in[6];
    const float* We1      = (const float*)d_in[7];
    const float* be1      = (const float*)d_in[8];
    const float* We2      = (const float*)d_in[9];
    const float* be2      = (const float*)d_in[10];
    const float* Wv       = (const float*)d_in[11];
    const float* Wvv      = (const float*)d_in[12];
    const float* Wh1      = (const float*)d_in[13];
    const float* bh1      = (const float*)d_in[14];
    const float* Wh2      = (const float*)d_in[15];
    const float* bh2      = (const float*)d_in[16];
    const float* Wi1      = (const float*)d_in[17];
    const float* bi1      = (const float*)d_in[18];
    const float* Wi2      = (const float*)d_in[19];
    const float* bi2      = (const float*)d_in[20];
    const float* Wgv1     = (const float*)d_in[21];
    const float* Wgv2     = (const float*)d_in[22];
    const float* Wg1      = (const float*)d_in[23];
    const float* bg1      = (const float*)d_in[24];
    const float* Wg2      = (const float*)d_in[25];
    const float* bg2      = (const float*)d_in[26];
    const float* Wf       = (const float*)d_in[27];
    const int*   edges    = (const int*)d_in[28];
    float* out = (float*)d_out;

    float* p_t0     = sym<float>(g_t0);
    float* p_h      = sym<float>(g_h);
    float* p_ArAc   = sym<float>(g_ArAc);
    float* p_hintra = sym<float>(g_hintra);
    float* p_v2n    = sym<float>(g_v2n);
    float* p_mix    = sym<float>(g_mix);
    float* p_ef     = sym<float>(g_ef);
    float* p_mvv    = sym<float>(g_mvv);
    float* p_unit   = sym<float>(g_unit);
    float* p_usum   = sym<float>(g_usum);
    float* p_va     = sym<float>(g_va);
    float* p_vb     = sym<float>(g_vb);
    float* p_vagg   = sym<float>(g_vagg);
    float* p_vp     = sym<float>(g_vp);
    float* p_w      = sym<float>(g_w);
    float* p_meanp  = sym<float>(g_meanp);
    float* p_meanh  = sym<float>(g_meanh);
    float* p_pv     = sym<float>(g_pv);
    float* p_pred   = sym<float>(g_pred);
    float* p_We1cat = sym<float>(g_We1cat);
    float* p_Wef    = sym<float>(g_Wef);
    float* p_W2v    = sym<float>(g_W2v);
    float* p_MWv    = sym<float>(g_MWv);
    float* p_Wgvcat = sym<float>(g_Wgvcat);
    float* p_b9     = sym<float>(g_b9);
    float* p_bWv    = sym<float>(g_bWv);
    float* p_bWvv   = sym<float>(g_bWvv);

    __nv_bfloat16* pa_cat = sym<__nv_bfloat16>(a2_cat);
    __nv_bfloat16* pa_u   = sym<__nv_bfloat16>(a2_u);
    __nv_bfloat16* pa_x   = sym<__nv_bfloat16>(a2_x);
    __nv_bfloat16* pa_t   = sym<__nv_bfloat16>(a2_t);
    __nv_bfloat16* pa_ef  = sym<__nv_bfloat16>(a2_ef);
    __nv_bfloat16* pa_M   = sym<__nv_bfloat16>(a2_M);
    __nv_bfloat16* pb_We1 = sym<__nv_bfloat16>(b2_We1cat);
    __nv_bfloat16* pb_Wef = sym<__nv_bfloat16>(b2_Wef);
    __nv_bfloat16* pb_W2v = sym<__nv_bfloat16>(b2_W2v);
    __nv_bfloat16* pb_MWv = sym<__nv_bfloat16>(b2_MWv);
    __nv_bfloat16* pb_We2 = sym<__nv_bfloat16>(b2_We2);
    __nv_bfloat16* pb_Wh1 = sym<__nv_bfloat16>(b2_Wh1);
    __nv_bfloat16* pb_Wh2 = sym<__nv_bfloat16>(b2_Wh2);
    __nv_bfloat16* pb_Wi1 = sym<__nv_bfloat16>(b2_Wi1);
    __nv_bfloat16* pb_Wi2 = sym<__nv_bfloat16>(b2_Wi2);
    __nv_bfloat16* pb_Wgv = sym<__nv_bfloat16>(b2_Wgv);
    __nv_bfloat16* pb_Wg1 = sym<__nv_bfloat16>(b2_Wg1);
    __nv_bfloat16* pb_Wg2 = sym<__nv_bfloat16>(b2_Wg2);

    // ---- weight staging ----
    pack_We1cat_kernel<<<(4 * HD * 256 + 255) / 256, 256>>>(We1, p_We1cat);
    pack_Wef_kernel<<<(4 * EFK * HD + 255) / 256, 256>>>(We1, p_Wef);
    pack_Wgv_kernel<<<(HD * 256 + 255) / 256, 256>>>(Wgv1, Wgv2, p_Wgvcat);
    launch_gemm(We2, Wvv, nullptr, nullptr, p_W2v, HD, HD, HD, 0,
                4, (long)HD * HD, (long)HD * HD, (long)HD * HD);
    launch_gemm(We2, Wv, nullptr, nullptr, p_MWv, HD, HD, HD, 0,
                4, (long)HD * HD, (long)HD * HD, (long)HD * HD);
    bias_pre_kernel<<<4, HD>>>(be2, Wv, Wvv, p_b9, p_bWv, p_bWvv);

    // ---- single fused bf16 B-pack ----
    {
        PackJobs J;
        auto set = [&](int j, const float* src, long ss, int K, int N,
                       __nv_bfloat16* dst, long ds, int ldd, int coff, int layers) {
            J.src[j] = src; J.sstride[j] = ss; J.K[j] = K; J.N[j] = N;
            J.dst[j] = dst; J.dstride[j] = ds; J.ldd[j] = ldd; J.coff[j] = coff;
            J.layers[j] = layers;
        };
        set(0,  p_We1cat, (long)HD * 256, 128, 256, pb_We1, (long)256 * 384, 384, 0, 4);
        set(1,  p_Wef, (long)EFK * HD, 64, 128, pb_Wef, (long)128 * 192, 192, 0, 4);
        set(2,  p_W2v, (long)HD * HD, 128, 128, pb_W2v, (long)128 * 384, 384, 0, 4);
        set(3,  p_MWv, (long)HD * HD, 128, 128, pb_MWv, (long)128 * 384, 384, 0, 4);
        set(4,  We2, (long)HD * HD, 128, 128, pb_We2, (long)128 * 384, 384, 0, 4);
        set(5,  Wh1, (long)256 * HD, 128, 128, pb_Wh1, (long)128 * 768, 768, 0, 4);
        set(6,  Wh1 + 128 * HD, (long)256 * HD, 128, 128, pb_Wh1, (long)128 * 768, 768, 384, 4);
        set(7,  Wh2, (long)HD * HD, 128, 128, pb_Wh2, (long)128 * 384, 384, 0, 4);
        set(8,  Wi1, (long)HD * HD, 128, 128, pb_Wi1, (long)128 * 384, 384, 0, 4);
        set(9,  Wi2, (long)HD * HD, 128, 128, pb_Wi2, (long)128 * 384, 384, 0, 4);
        set(10, p_Wgvcat, 0, 128, 256, pb_Wgv, 0, 384, 0, 1);
        set(11, Wg1, 0, 128, 128, pb_Wg1, 0, 768, 0, 1);
        set(12, Wg1 + 128 * HD, 0, 128, 128, pb_Wg1, 0, 768, 384, 1);
        set(13, Wg2, 0, 128, 256, pb_Wg2, 0, 384, 0, 1);
        dim3 grid(128, NJOBS, 4);
        pack_all_kernel<<<grid, 256>>>(J);
    }

    // edge geometry + split ef (static across layers)
    edge_geom_kernel<<<(E_EDGES + 255) / 256, 256>>>(X, edge_attr, edges, p_unit, p_ef);
    launch_split(p_ef, E_EDGES, 64, pa_ef, 192, 0, nullptr);

    // h = silu(node_attr @ W_in1 + b_in1) @ W_in2 + b_in2  (fp32), split into pa_cat[0:384]
    launch_gemm(node_attr, W_in1, b_in1, nullptr, p_t0, N_NODES, HD, 64, FLAG_SILU);
    launch_gemm(p_t0, W_in2, b_in2, nullptr, p_h, N_NODES, HD, HD, 0);
    launch_split(p_h, N_NODES, HD, pa_cat, 768, 0, nullptr);

    float* vin = nullptr;     // layer 0: v = 0
    float* vbuf0 = p_va;
    float* vbuf1 = p_vb;

    for (int i = 0; i < 4; i++) {
        const float* be1_i = be1 + i * HD;
        const float* bh1_i = bh1 + i * HD;
        const float* bh2_i = bh2 + i * HD;
        const float* bi1_i = bi1 + i * HD;
        const float* bi2_i = bi2 + i * HD;
        float* vout = (i & 1) ? vbuf1 : vbuf0;

        // [Ar|Ac] = h @ [W_r|W_c]
        launch_tc(pa_cat, 768, 384, pb_We1 + (long)i * 256 * 384,
                  nullptr, nullptr, p_ArAc, N_NODES, 256, 0);

        // t = silu(ef@Wef + be1 + Ar[row] + Ac[col]) -> split pa_t
        launch_tc(pa_ef, 192, 192, pb_Wef + (long)i * 128 * 192,
                  be1_i, nullptr, nullptr, E_EDGES, 128, FLAG_SILU | FLAG_COMBINE,
                  pa_t, 384, edges, p_ArAc);

        // mvv = t @ (We2@Wvv) + be2@Wvv   (edge GEMM, N=128)
        launch_tc(pa_t, 384, 384, pb_W2v + (long)i * 128 * 384,
                  p_bWvv + i * HD, nullptr, p_mvv, E_EDGES, 128, 0);

        // aggregate t: agg_t split -> pa_x ; Mt split -> pa_M ; Usum
        aggT_kernel<<<N_NODES, HD>>>(pa_t, p_unit, pa_x, pa_M, p_usum);

        // agg = agg_t @ We2 + 9*be2 -> split into pa_cat[384:]
        launch_tc(pa_x, 384, 384, pb_We2 + (long)i * 128 * 384,
                  p_b9 + i * HD, nullptr, nullptr, N_NODES, 128, 0, pa_cat + 384, 768);

        // u = silu([h|agg] @ Wh1 + bh1) -> split pa_u
        launch_tc(pa_cat, 768, 768, pb_Wh1 + (long)i * 128 * 768,
                  bh1_i, nullptr, nullptr, N_NODES, 128, FLAG_SILU, pa_u, 384);
        // h_intra = h + u @ Wh2 + bh2
        launch_tc(pa_u, 384, 384, pb_Wh2 + (long)i * 128 * 384,
                  bh2_i, p_h, p_hintra, N_NODES, 128, 0);

        // vagg = Mt @ (We2@Wv)
        launch_tc(pa_M, 384, 384, pb_MWv + (long)i * 128 * 384,
                  nullptr, nullptr, p_vagg, 3 * N_NODES, 128, 0);
        vupdate_kernel<<<N_NODES, HD>>>(vin, vout, p_mvv, p_vagg, p_usum,
                                        p_bWv + i * HD, edges);

        // segment attention
        {
            dim3 g1(NSEG, 8);
            meanh1_kernel<<<g1, HD>>>(p_hintra, p_meanp);
            meanh2_kernel<<<NSEG, HD>>>(p_meanp, p_meanh);
        }
        attn_kernel<<<NSEG, SEGSZ>>>(p_hintra, p_meanh, p_w);
        // u = silu((hintra*w) @ Wi1 + bi1)
        launch_split(p_hintra, N_NODES, HD, pa_x, 384, 0, p_w);
        launch_tc(pa_x, 384, 384, pb_Wi1 + (long)i * 128 * 384,
                  bi1_i, nullptr, nullptr, N_NODES, 128, FLAG_SILU, pa_u, 384);
        // h = hintra + u @ Wi2 + bi2 ; split new h into pa_cat[0:384]
        launch_tc(pa_u, 384, 384, pb_Wi2 + (long)i * 128 * 384,
                  bi2_i, p_hintra, p_h, N_NODES, 128, 0, pa_cat, 768);

        vin = vout;
    }

    // [v1 | v2] = v @ [Wgv1 | Wgv2]
    launch_split(vin, 3 * N_NODES, HD, pa_M, 384, 0, nullptr);
    launch_tc(pa_M, 384, 384, pb_Wgv, nullptr, nullptr, p_vp, 3 * N_NODES, 256, 0);
    v2n_kernel<<<(N_NODES * HD + 255) / 256, 256>>>(p_vp, p_v2n);

    // mix = silu([h|v2n] @ Wg1 + bg1) @ Wg2 + bg2
    launch_split(p_v2n, N_NODES, HD, pa_cat, 768, 384, nullptr);
    launch_tc(pa_cat, 768, 768, pb_Wg1, bg1, nullptr, nullptr, N_NODES, 128, FLAG_SILU, pa_u, 384);
    launch_tc(pa_u, 384, 384, pb_Wg2, bg2, nullptr, p_mix, N_NODES, 256, 0);

    // epilogue
    pv_kernel<<<N_NODES, HD>>>(p_vp, p_mix, Wf, p_pv);
    predsum_kernel<<<NSEG, 32>>>(p_pv, p_pred);
    final_kernel<<<1, 32>>>(p_pred, out);
}

// round 8
// speedup vs baseline: 2.3010x; 1.2153x over previous
#include <cuda_runtime.h>
#include <cuda_bf16.h>
#include <math.h>
#include <stdint.h>

#define N_NODES 16384
#define E_EDGES 147456
#define HD 128
#define NSEG 32
#define SEGSZ 512
#define KEDGE 9
#define EFK 64

#define FLAG_SILU 1
#define FLAG_RESPRE 2
#define FLAG_COMBINE 4

// ---------------- fp32 scratch ----------------
__device__ float g_t0[N_NODES * HD];
__device__ float g_h[N_NODES * HD];
__device__ float g_ArAc[N_NODES * 2 * HD];
__device__ float g_hintra[N_NODES * HD];
__device__ float g_v2n[N_NODES * HD];
__device__ float g_mix[N_NODES * 2 * HD];
__device__ float g_ef[(long)E_EDGES * EFK];
__device__ float g_mvv[(long)E_EDGES * HD];
__device__ float g_unit[E_EDGES * 3];
__device__ float g_usum[N_NODES * 3];
__device__ float g_va[N_NODES * 3 * HD];
__device__ float g_vb[N_NODES * 3 * HD];
__device__ float g_vagg[N_NODES * 3 * HD];
__device__ float g_vp[(long)N_NODES * 3 * 256];
__device__ float g_w[N_NODES];
__device__ float g_meanp[NSEG * 8 * HD];
__device__ float g_meanh[NSEG * HD];
__device__ float g_pv[N_NODES * 27];
__device__ float g_pred[NSEG * 27];
// fp32 weight staging
__device__ float g_We1cat[4 * HD * 256];
__device__ float g_Wef[4 * EFK * HD];
__device__ float g_W2v[4 * HD * HD];   // We2 @ Wvv
__device__ float g_MWv[4 * HD * HD];   // We2 @ Wv
__device__ float g_Wgvcat[HD * 256];
__device__ float g_b9[4 * HD];
__device__ float g_bWv[4 * HD];
__device__ float g_bWvv[4 * HD];

// ---------------- bf16 split operand buffers ----------------
__device__ __align__(16) __nv_bfloat16 a2_cat[(long)N_NODES * 768];
__device__ __align__(16) __nv_bfloat16 a2_u[(long)N_NODES * 384];
__device__ __align__(16) __nv_bfloat16 a2_x[(long)N_NODES * 384];
__device__ __align__(16) __nv_bfloat16 a2_t[(long)E_EDGES * 384];
__device__ __align__(16) __nv_bfloat16 a2_ef[(long)E_EDGES * 192];
__device__ __align__(16) __nv_bfloat16 a2_M[(long)3 * N_NODES * 384];
__device__ __align__(16) __nv_bfloat16 b2_We1cat[4 * 256 * 384];
__device__ __align__(16) __nv_bfloat16 b2_Wef[4 * 128 * 192];
__device__ __align__(16) __nv_bfloat16 b2_W2v[4 * 128 * 384];
__device__ __align__(16) __nv_bfloat16 b2_MWv[4 * 128 * 384];
__device__ __align__(16) __nv_bfloat16 b2_We2[4 * 128 * 384];
__device__ __align__(16) __nv_bfloat16 b2_Wh1[4 * 128 * 768];
__device__ __align__(16) __nv_bfloat16 b2_Wh2[4 * 128 * 384];
__device__ __align__(16) __nv_bfloat16 b2_Wi1[4 * 128 * 384];
__device__ __align__(16) __nv_bfloat16 b2_Wi2[4 * 128 * 384];
__device__ __align__(16) __nv_bfloat16 b2_Wgv[256 * 384];
__device__ __align__(16) __nv_bfloat16 b2_Wg1[128 * 768];
__device__ __align__(16) __nv_bfloat16 b2_Wg2[256 * 384];

// ---------------- helpers ----------------
__device__ __forceinline__ uint32_t smem_to_u32(const void* p) {
    uint32_t a;
    asm("{ .reg .u64 t; cvta.to.shared.u64 t, %1; cvt.u32.u64 %0, t; }" : "=r"(a) : "l"(p));
    return a;
}
__device__ __forceinline__ void wsplit1(__nv_bfloat16* d, int K, float x) {
    __nv_bfloat16 hi = __float2bfloat16(x);
    __nv_bfloat16 lo = __float2bfloat16(x - __bfloat162float(hi));
    d[0] = hi; d[K] = lo; d[2 * K] = hi;
}
#define CP16(dst, src) \
    asm volatile("cp.async.cg.shared.global [%0], [%1], 16;" :: "r"(dst), "l"(src) : "memory")
#define CP_COMMIT() asm volatile("cp.async.commit_group;" ::: "memory")
#define CP_WAIT1()  asm volatile("cp.async.wait_group 1;" ::: "memory")
#define CP_WAIT0()  asm volatile("cp.async.wait_group 0;" ::: "memory")

// ---------------- bf16-split tensor-core GEMM: mma.sync + 3-stage cp.async ----------------
// A2: (M, lda) bf16 row-major. B2: (Nt, Ktot) bf16 row-major. Ktot % 32 == 0, Ktot >= 64.
// 128x128 block tile, 8 warps (64x32 warp tile), 3-stage pipeline, 1 sync/iter.
#define SMS 40
#define STAGE_ELEMS 10240           // (As 5120 + Bs 5120) bf16 per stage
#define TCSMEM (3 * STAGE_ELEMS * 2)  // 61440 bytes

__global__ __launch_bounds__(256, 2)
void tcgemm(const __nv_bfloat16* __restrict__ A2, int lda, int Ktot,
            const __nv_bfloat16* __restrict__ B2,
            const float* __restrict__ bias, const float* __restrict__ res,
            float* __restrict__ C, int Nt, int flags,
            __nv_bfloat16* __restrict__ sdst, int sldd,
            const int* __restrict__ edges, const float* __restrict__ ArAc)
{
    extern __shared__ __align__(16) char smraw[];
    __nv_bfloat16* sm = (__nv_bfloat16*)smraw;

    const int t = threadIdx.x;
    const int lid = t & 31;
    const int wid = t >> 5;
    const int wm = wid & 1;
    const int wn = wid >> 1;
    const int bm = blockIdx.y * 128;
    const int bn = blockIdx.x * 128;

    float acc[4][4][4];
#pragma unroll
    for (int i = 0; i < 4; i++)
#pragma unroll
        for (int j = 0; j < 4; j++)
#pragma unroll
            for (int r = 0; r < 4; r++) acc[i][j][r] = 0.0f;

    const int r0 = t >> 2;
    const int r1 = r0 + 64;
    const int kq = (t & 3) << 3;

    const int a_row = wm * 64 + (lid & 7) + ((lid >> 3) & 1) * 8;
    const int a_col = ((lid >> 4) & 1) * 8;
    const int a_off = a_row * SMS + a_col;
    const int b_row = wn * 32 + (lid & 7);
    const int b_col = ((lid >> 3) & 1) * 8;
    const int b_off = b_row * SMS + b_col;

    const int iters = Ktot >> 5;

    const long arow0 = (long)(bm + r0) * lda + kq;
    const long arow1 = (long)(bm + r1) * lda + kq;
    const long brow0 = (long)(bn + r0) * Ktot + kq;
    const long brow1 = (long)(bn + r1) * Ktot + kq;

    // prologue: stages 0,1
#pragma unroll
    for (int p = 0; p < 2; p++) {
        __nv_bfloat16* sA = sm + p * STAGE_ELEMS;
        __nv_bfloat16* sB = sA + 5120;
        const int k0 = p << 5;
        CP16(smem_to_u32(sA + r0 * SMS + kq), A2 + arow0 + k0);
        CP16(smem_to_u32(sA + r1 * SMS + kq), A2 + arow1 + k0);
        CP16(smem_to_u32(sB + r0 * SMS + kq), B2 + brow0 + k0);
        CP16(smem_to_u32(sB + r1 * SMS + kq), B2 + brow1 + k0);
        CP_COMMIT();
    }

    int stage = 0;
    for (int it = 0; it < iters; it++) {
        if (it + 1 < iters) { CP_WAIT1(); } else { CP_WAIT0(); }
        __syncthreads();

        const uint32_t aBase = smem_to_u32(sm + stage * STAGE_ELEMS);
        const uint32_t bBase = aBase + 5120 * 2;
#pragma unroll
        for (int ks = 0; ks < 2; ks++) {
            uint32_t a[4][4];
#pragma unroll
            for (int i = 0; i < 4; i++) {
                const uint32_t addr = aBase + 2u * (a_off + i * 16 * SMS + ks * 16);
                asm volatile(
                    "ldmatrix.sync.aligned.m8n8.x4.shared.b16 {%0,%1,%2,%3}, [%4];"
                    : "=r"(a[i][0]), "=r"(a[i][1]), "=r"(a[i][2]), "=r"(a[i][3])
                    : "r"(addr));
            }
            uint32_t b[4][2];
#pragma unroll
            for (int j = 0; j < 4; j++) {
                const uint32_t addr = bBase + 2u * (b_off + j * 8 * SMS + ks * 16);
                asm volatile(
                    "ldmatrix.sync.aligned.m8n8.x2.shared.b16 {%0,%1}, [%2];"
                    : "=r"(b[j][0]), "=r"(b[j][1])
                    : "r"(addr));
            }
#pragma unroll
            for (int i = 0; i < 4; i++)
#pragma unroll
                for (int j = 0; j < 4; j++) {
                    asm volatile(
                        "mma.sync.aligned.m16n8k16.row.col.f32.bf16.bf16.f32 "
                        "{%0,%1,%2,%3}, {%4,%5,%6,%7}, {%8,%9}, {%0,%1,%2,%3};"
                        : "+f"(acc[i][j][0]), "+f"(acc[i][j][1]),
                          "+f"(acc[i][j][2]), "+f"(acc[i][j][3])
                        : "r"(a[i][0]), "r"(a[i][1]), "r"(a[i][2]), "r"(a[i][3]),
                          "r"(b[j][0]), "r"(b[j][1]));
                }
        }

        if (it + 2 < iters) {
            int ps = stage;  // (it+2)%3 == stage (3-buffer rotation)
            __nv_bfloat16* sA = sm + ((stage + 2) % 3) * STAGE_ELEMS;
            __nv_bfloat16* sB = sA + 5120;
            (void)ps;
            const int k0 = (it + 2) << 5;
            CP16(smem_to_u32(sA + r0 * SMS + kq), A2 + arow0 + k0);
            CP16(smem_to_u32(sA + r1 * SMS + kq), A2 + arow1 + k0);
            CP16(smem_to_u32(sB + r0 * SMS + kq), B2 + brow0 + k0);
            CP16(smem_to_u32(sB + r1 * SMS + kq), B2 + brow1 + k0);
            CP_COMMIT();
        }
        stage = (stage + 1) % 3;
    }

    // epilogue
    const bool f_silu = (flags & FLAG_SILU) != 0;
    const bool f_respre = (flags & FLAG_RESPRE) != 0;
    const bool f_comb = (flags & FLAG_COMBINE) != 0;
    const int g = lid >> 2;
    const int t2 = (lid & 3) << 1;
#pragma unroll
    for (int i = 0; i < 4; i++) {
#pragma unroll
        for (int half = 0; half < 2; half++) {
            const int m = bm + wm * 64 + i * 16 + g + half * 8;
            int rrow = 0, ccol = 0;
            if (f_comb) { rrow = m / KEDGE; ccol = edges[E_EDGES + m]; }
#pragma unroll
            for (int j = 0; j < 4; j++) {
                const int n0 = bn + wn * 32 + j * 8 + t2;
                const long base = (long)m * Nt + n0;
                float v0 = acc[i][j][2 * half + 0];
                float v1 = acc[i][j][2 * half + 1];
                if (bias) { v0 += bias[n0]; v1 += bias[n0 + 1]; }
                if (f_comb) {
                    v0 += ArAc[(long)rrow * 256 + n0] + ArAc[(long)ccol * 256 + 128 + n0];
                    v1 += ArAc[(long)rrow * 256 + n0 + 1] + ArAc[(long)ccol * 256 + 128 + n0 + 1];
                }
                if (f_respre && res) { v0 += res[base]; v1 += res[base + 1]; }
                if (f_silu) {
                    v0 = v0 / (1.0f + __expf(-v0));
                    v1 = v1 / (1.0f + __expf(-v1));
                }
                if (!f_respre && res) { v0 += res[base]; v1 += res[base + 1]; }
                if (C) *(float2*)&C[base] = make_float2(v0, v1);
                if (sdst) {
                    __nv_bfloat16 h0 = __float2bfloat16(v0);
                    __nv_bfloat16 h1 = __float2bfloat16(v1);
                    __nv_bfloat16 l0 = __float2bfloat16(v0 - __bfloat162float(h0));
                    __nv_bfloat16 l1 = __float2bfloat16(v1 - __bfloat162float(h1));
                    __nv_bfloat16* d = sdst + (long)m * sldd + n0;
                    __nv_bfloat162 hv; hv.x = h0; hv.y = h1;
                    __nv_bfloat162 lv; lv.x = l0; lv.y = l1;
                    *(__nv_bfloat162*)&d[0] = hv;
                    *(__nv_bfloat162*)&d[Nt] = lv;
                    *(__nv_bfloat162*)&d[2 * Nt] = hv;
                }
            }
        }
    }
}

// ---------------- split kernel (fp32 -> [hi|lo|hi]) ----------------
__global__ void splitA_kernel(const float* __restrict__ src, int K,
                              __nv_bfloat16* __restrict__ dst, int ldd, int coff,
                              const float* __restrict__ rowscale, long total)
{
    long idx = (long)blockIdx.x * blockDim.x + threadIdx.x;
    if (idx >= total) return;
    int k = (int)(idx % K);
    long row = idx / K;
    float x = src[idx];
    if (rowscale) x *= rowscale[row];
    wsplit1(dst + row * ldd + coff + k, K, x);
}

// ---------------- fp32 GEMM (initial MLP) ----------------
__device__ __forceinline__ unsigned long long pack2(float lo, float hi) {
    unsigned long long r;
    asm("mov.b64 %0, {%1, %2};" : "=l"(r) : "f"(lo), "f"(hi));
    return r;
}
__device__ __forceinline__ unsigned long long dup2(float v) {
    unsigned long long r;
    asm("mov.b64 %0, {%1, %1};" : "=l"(r) : "f"(v));
    return r;
}
__device__ __forceinline__ void fma2(unsigned long long& acc, unsigned long long a, unsigned long long b) {
    asm("fma.rn.f32x2 %0, %1, %2, %0;" : "+l"(acc) : "l"(a), "l"(b));
}
__device__ __forceinline__ void unpack2(unsigned long long p, float& lo, float& hi) {
    asm("mov.b64 {%0, %1}, %2;" : "=f"(lo), "=f"(hi) : "l"(p));
}

__global__ __launch_bounds__(256, 1)
void gemm128(const float* __restrict__ A, const float* __restrict__ B,
             const float* __restrict__ bias, const float* __restrict__ res,
             float* __restrict__ C, int M, int N, int K, int flags,
             long sA, long sB, long sC)
{
    A += blockIdx.z * sA; B += blockIdx.z * sB; C += blockIdx.z * sC;
    __shared__ float As[2][16][128];
    __shared__ float Bs[2][16][128];
    const int bm = blockIdx.y * 128;
    const int bn = blockIdx.x * 128;
    const int t = threadIdx.x;
    const int ty = t >> 4;
    const int tx = t & 15;

    unsigned long long acc2[8][4];
#pragma unroll
    for (int i = 0; i < 8; i++)
#pragma unroll
        for (int j = 0; j < 4; j++) acc2[i][j] = 0ull;

    const int tiles = K >> 4;
    const int a_row0 = t >> 2;
    const int a_kc = (t & 3) << 2;
    const int b_k0 = t >> 5;
    const int b_n4 = (t & 31) << 2;

    {
#pragma unroll
        for (int r = 0; r < 2; r++) {
            int row = a_row0 + r * 64;
            float4 v = *(const float4*)&A[(long)(bm + row) * K + a_kc];
            As[0][a_kc + 0][row] = v.x; As[0][a_kc + 1][row] = v.y;
            As[0][a_kc + 2][row] = v.z; As[0][a_kc + 3][row] = v.w;
        }
#pragma unroll
        for (int r = 0; r < 2; r++) {
            int k = b_k0 + r * 8;
            *(float4*)&Bs[0][k][b_n4] = *(const float4*)&B[(long)k * N + bn + b_n4];
        }
    }
    __syncthreads();

    for (int tt = 0; tt < tiles; tt++) {
        const int buf = tt & 1;
        float4 pa[2], pb[2];
        if (tt + 1 < tiles) {
            const int k0n = (tt + 1) << 4;
#pragma unroll
            for (int r = 0; r < 2; r++)
                pa[r] = *(const float4*)&A[(long)(bm + a_row0 + r * 64) * K + k0n + a_kc];
#pragma unroll
            for (int r = 0; r < 2; r++)
                pb[r] = *(const float4*)&B[(long)(k0n + b_k0 + r * 8) * N + bn + b_n4];
        }
#pragma unroll
        for (int k = 0; k < 16; k++) {
            float a[8];
            float4 a0 = *(const float4*)&As[buf][k][ty * 8];
            float4 a1 = *(const float4*)&As[buf][k][ty * 8 + 4];
            a[0] = a0.x; a[1] = a0.y; a[2] = a0.z; a[3] = a0.w;
            a[4] = a1.x; a[5] = a1.y; a[6] = a1.z; a[7] = a1.w;
            float4 b0 = *(const float4*)&Bs[buf][k][tx * 8];
            float4 b1 = *(const float4*)&Bs[buf][k][tx * 8 + 4];
            unsigned long long b2[4];
            b2[0] = pack2(b0.x, b0.y); b2[1] = pack2(b0.z, b0.w);
            b2[2] = pack2(b1.x, b1.y); b2[3] = pack2(b1.z, b1.w);
#pragma unroll
            for (int i = 0; i < 8; i++) {
                unsigned long long ad = dup2(a[i]);
#pragma unroll
                for (int j = 0; j < 4; j++) fma2(acc2[i][j], ad, b2[j]);
            }
        }
        if (tt + 1 < tiles) {
            const int nb = buf ^ 1;
#pragma unroll
            for (int r = 0; r < 2; r++) {
                int row = a_row0 + r * 64;
                As[nb][a_kc + 0][row] = pa[r].x; As[nb][a_kc + 1][row] = pa[r].y;
                As[nb][a_kc + 2][row] = pa[r].z; As[nb][a_kc + 3][row] = pa[r].w;
            }
#pragma unroll
            for (int r = 0; r < 2; r++)
                *(float4*)&Bs[nb][b_k0 + r * 8][b_n4] = pb[r];
        }
        __syncthreads();
    }

    const bool silu = (flags & FLAG_SILU) != 0;
#pragma unroll
    for (int i = 0; i < 8; i++) {
        const int m = bm + ty * 8 + i;
        float cv[8];
#pragma unroll
        for (int j = 0; j < 4; j++) unpack2(acc2[i][j], cv[2 * j], cv[2 * j + 1]);
        const long base = (long)m * N + bn + tx * 8;
#pragma unroll
        for (int j = 0; j < 8; j++) {
            float v = cv[j];
            if (bias) v += bias[bn + tx * 8 + j];
            if (silu) v = v / (1.0f + __expf(-v));
            if (res) v += res[base + j];
            cv[j] = v;
        }
        float4* cp = (float4*)&C[base];
        cp[0] = make_float4(cv[0], cv[1], cv[2], cv[3]);
        cp[1] = make_float4(cv[4], cv[5], cv[6], cv[7]);
    }
}

// ---------------- small weight-product kernel: W2v = We2@Wvv, MWv = We2@Wv ----------------
__global__ void wprod_kernel(const float* __restrict__ We2, const float* __restrict__ Wv,
                             const float* __restrict__ Wvv,
                             float* __restrict__ MWv, float* __restrict__ W2v)
{
    int l = blockIdx.z;
    int row = blockIdx.y;
    int n = threadIdx.x;
    __shared__ float a[HD];
    a[n] = We2[(long)l * HD * HD + row * HD + n];
    __syncthreads();
    const float* B = blockIdx.x ? Wv : Wvv;
    B += (long)l * HD * HD;
    float s = 0.0f;
#pragma unroll 8
    for (int k = 0; k < HD; k++) s += a[k] * B[k * HD + n];
    float* O = blockIdx.x ? MWv : W2v;
    O[(long)l * HD * HD + row * HD + n] = s;
}

// ---------------- staging pack kernels (fp32) ----------------
__global__ void pack_We1cat_kernel(const float* __restrict__ We1, float* __restrict__ out)
{
    int idx = blockIdx.x * blockDim.x + threadIdx.x;
    if (idx >= 4 * HD * 256) return;
    int l = idx / (HD * 256);
    int rem = idx - l * HD * 256;
    int k = rem >> 8, n = rem & 255;
    const float* base = We1 + (long)l * 292 * HD;
    out[idx] = (n < HD) ? base[k * HD + n] : base[(HD + k) * HD + (n - HD)];
}
__global__ void pack_Wef_kernel(const float* __restrict__ We1, float* __restrict__ out)
{
    int idx = blockIdx.x * blockDim.x + threadIdx.x;
    if (idx >= 4 * EFK * HD) return;
    int l = idx / (EFK * HD);
    int rem = idx - l * EFK * HD;
    int k = rem >> 7, n = rem & 127;
    out[idx] = (k < 36) ? We1[(long)l * 292 * HD + (256 + k) * HD + n] : 0.0f;
}
__global__ void pack_Wgv_kernel(const float* __restrict__ Wgv1, const float* __restrict__ Wgv2,
                                float* __restrict__ out)
{
    int idx = blockIdx.x * blockDim.x + threadIdx.x;
    if (idx >= HD * 256) return;
    int k = idx >> 8, n = idx & 255;
    out[idx] = (n < HD) ? Wgv1[k * HD + n] : Wgv2[k * HD + (n - HD)];
}
__global__ void bias_pre_kernel(const float* __restrict__ be2, const float* __restrict__ Wv,
                                const float* __restrict__ Wvv,
                                float* __restrict__ b9, float* __restrict__ bWv,
                                float* __restrict__ bWvv)
{
    int l = blockIdx.x;
    int n = threadIdx.x;
    const float* b = be2 + l * HD;
    b9[l * HD + n] = 9.0f * b[n];
    float s1 = 0.f, s2 = 0.f;
    const float* w1 = Wv + (long)l * HD * HD;
    const float* w2 = Wvv + (long)l * HD * HD;
#pragma unroll 8
    for (int k = 0; k < HD; k++) {
        s1 += b[k] * w1[k * HD + n];
        s2 += b[k] * w2[k * HD + n];
    }
    bWv[l * HD + n] = s1;
    bWvv[l * HD + n] = s2;
}

// ---------------- single fused bf16 B-pack ----------------
#define NJOBS 14
struct PackJobs {
    const float* src[NJOBS];
    long sstride[NJOBS];
    long dstride[NJOBS];
    __nv_bfloat16* dst[NJOBS];
    int K[NJOBS];
    int N[NJOBS];
    int ldd[NJOBS];
    int coff[NJOBS];
    int layers[NJOBS];
};
__global__ void pack_all_kernel(PackJobs J)
{
    int j = blockIdx.y;
    int l = blockIdx.z;
    if (l >= J.layers[j]) return;
    int idx = blockIdx.x * 256 + threadIdx.x;
    int KN = J.K[j] * J.N[j];
    if (idx >= KN) return;
    int k = idx / J.N[j], n = idx % J.N[j];
    float x = J.src[j][(long)l * J.sstride[j] + idx];
    __nv_bfloat16 hi = __float2bfloat16(x);
    __nv_bfloat16 lo = __float2bfloat16(x - __bfloat162float(hi));
    __nv_bfloat16* d = J.dst[j] + (long)l * J.dstride[j] + (long)n * J.ldd[j] + J.coff[j];
    d[k] = hi;
    d[J.K[j] + k] = hi;
    d[2 * J.K[j] + k] = lo;
}

// ---------------- elementwise / reduction kernels ----------------
__global__ void edge_geom_kernel(const float* __restrict__ X, const float* __restrict__ edge_attr,
                                 const int* __restrict__ edges,
                                 float* __restrict__ unit, float* __restrict__ ef)
{
    int e = blockIdx.x * blockDim.x + threadIdx.x;
    if (e >= E_EDGES) return;
    int r = edges[e];
    int c = edges[E_EDGES + e];
    float dx = X[r * 3 + 0] - X[c * 3 + 0];
    float dy = X[r * 3 + 1] - X[c * 3 + 1];
    float dz = X[r * 3 + 2] - X[c * 3 + 2];
    float norm = sqrtf(dx * dx + dy * dy + dz * dz) + 1e-8f;
    float invn = 1.0f / norm;
    unit[e * 3 + 0] = dx * invn;
    unit[e * 3 + 1] = dy * invn;
    unit[e * 3 + 2] = dz * invn;
    const float PI_ = 3.14159265358979323846f;
    float cn = fminf(norm, 1.0f);
    float cut = 0.5f * (cosf(PI_ * cn) + 1.0f);
    float f = cut * invn;
#pragma unroll
    for (int j = 0; j < 20; j++)
        ef[(long)e * EFK + j] = sinf(norm * PI_ * (float)(j + 1)) * f;
#pragma unroll
    for (int j = 0; j < 16; j++)
        ef[(long)e * EFK + 20 + j] = edge_attr[e * 16 + j];
#pragma unroll
    for (int j = 36; j < EFK; j++)
        ef[(long)e * EFK + j] = 0.0f;
}

__global__ void aggT_kernel(const __nv_bfloat16* __restrict__ t2, const float* __restrict__ unit,
                            __nv_bfloat16* __restrict__ aggdst, __nv_bfloat16* __restrict__ Mdst,
                            float* __restrict__ usum)
{
    int n = blockIdx.x;
    int hh = threadIdx.x;
    float s = 0.f, mx = 0.f, my = 0.f, mz = 0.f;
#pragma unroll
    for (int j = 0; j < KEDGE; j++) {
        long e = (long)n * KEDGE + j;
        float tt = __bfloat162float(t2[e * 384 + hh]) + __bfloat162float(t2[e * 384 + 128 + hh]);
        float ux = unit[e * 3 + 0];
        float uy = unit[e * 3 + 1];
        float uz = unit[e * 3 + 2];
        s += tt; mx += tt * ux; my += tt * uy; mz += tt * uz;
    }
    wsplit1(aggdst + (long)n * 384 + hh, 128, s);
    wsplit1(Mdst + (long)(3 * n + 0) * 384 + hh, 128, mx);
    wsplit1(Mdst + (long)(3 * n + 1) * 384 + hh, 128, my);
    wsplit1(Mdst + (long)(3 * n + 2) * 384 + hh, 128, mz);
    if (hh < 3) {
        float u = 0.f;
#pragma unroll
        for (int j = 0; j < KEDGE; j++) u += unit[((long)n * KEDGE + j) * 3 + hh];
        usum[n * 3 + hh] = u;
    }
}

__global__ void vupdate_kernel(const float* __restrict__ vin, float* __restrict__ vout,
                               const float* __restrict__ mvv, const float* __restrict__ vagg,
                               const float* __restrict__ usum, const float* __restrict__ bWv,
                               const int* __restrict__ edges)
{
    int n = blockIdx.x;
    int hh = threadIdx.x;
    float bw = bWv[hh];
    float a0 = vagg[(long)n * 384 + hh]       + usum[n * 3 + 0] * bw;
    float a1 = vagg[(long)n * 384 + 128 + hh] + usum[n * 3 + 1] * bw;
    float a2 = vagg[(long)n * 384 + 256 + hh] + usum[n * 3 + 2] * bw;
    if (vin) {
        a0 += vin[(long)n * 384 + hh];
        a1 += vin[(long)n * 384 + 128 + hh];
        a2 += vin[(long)n * 384 + 256 + hh];
#pragma unroll
        for (int j = 0; j < KEDGE; j++) {
            long e = (long)n * KEDGE + j;
            int c = edges[E_EDGES + e];
            float b = mvv[e * HD + hh];
            a0 += b * vin[(long)c * 384 + hh];
            a1 += b * vin[(long)c * 384 + 128 + hh];
            a2 += b * vin[(long)c * 384 + 256 + hh];
        }
    }
    vout[(long)n * 384 + hh] = a0;
    vout[(long)n * 384 + 128 + hh] = a1;
    vout[(long)n * 384 + 256 + hh] = a2;
}

__global__ void meanh1_kernel(const float* __restrict__ hintra, float* __restrict__ part)
{
    int s = blockIdx.x;
    int c = blockIdx.y;
    int k = threadIdx.x;
    float acc = 0.0f;
    const float* p = hintra + ((long)s * SEGSZ + c * 64) * HD + k;
#pragma unroll 8
    for (int u = 0; u < 64; u++) acc += p[u * HD];
    part[(s * 8 + c) * HD + k] = acc;
}
__global__ void meanh2_kernel(const float* __restrict__ part, float* __restrict__ meanh)
{
    int s = blockIdx.x;
    int k = threadIdx.x;
    float a = 0.0f;
#pragma unroll
    for (int c = 0; c < 8; c++) a += part[(s * 8 + c) * HD + k];
    meanh[s * HD + k] = a * (1.0f / (float)SEGSZ);
}

__global__ void attn_kernel(const float* __restrict__ hintra, const float* __restrict__ meanh,
                            float* __restrict__ w)
{
    int s = blockIdx.x;
    int t = threadIdx.x;
    __shared__ float sm[HD];
    __shared__ float red[SEGSZ];
    int opp = s ^ 1;
    if (t < HD) sm[t] = meanh[opp * HD + t];
    __syncthreads();
    int node = s * SEGSZ + t;
    const float* hr = hintra + (long)node * HD;
    float sc = 0.0f;
#pragma unroll 8
    for (int k = 0; k < HD; k++) sc += hr[k] * sm[k];
    red[t] = sc;
    __syncthreads();
    for (int st = SEGSZ / 2; st > 0; st >>= 1) {
        if (t < st) red[t] = fmaxf(red[t], red[t + st]);
        __syncthreads();
    }
    float mx = red[0];
    __syncthreads();
    float ex = expf(sc - mx);
    red[t] = ex;
    __syncthreads();
    for (int st = SEGSZ / 2; st > 0; st >>= 1) {
        if (t < st) red[t] += red[t + st];
        __syncthreads();
    }
    w[node] = ex / red[0];
}

__global__ void v2n_kernel(const float* __restrict__ vp, float* __restrict__ v2n)
{
    int idx = blockIdx.x * blockDim.x + threadIdx.x;
    if (idx >= N_NODES * HD) return;
    int n = idx / HD;
    int k = idx % HD;
    float a = vp[(long)(n * 3 + 0) * 256 + HD + k];
    float b = vp[(long)(n * 3 + 1) * 256 + HD + k];
    float c = vp[(long)(n * 3 + 2) * 256 + HD + k];
    v2n[idx] = sqrtf(a * a + b * b + c * c + 1e-8f);
}

__global__ void pv_kernel(const float* __restrict__ vp, const float* __restrict__ mix,
                          const float* __restrict__ Wf, float* __restrict__ pv)
{
    int n = blockIdx.x;
    int k = threadIdx.x;
    __shared__ float sd[3][HD];
    float hf = mix[(long)n * 256 + k];
    float bg = mix[(long)n * 256 + HD + k];
    float s = hf * bg;
    sd[0][k] = vp[(long)(n * 3 + 0) * 256 + k] * s;
    sd[1][k] = vp[(long)(n * 3 + 1) * 256 + k] * s;
    sd[2][k] = vp[(long)(n * 3 + 2) * 256 + k] * s;
    __syncthreads();
    if (k < 27) {
        int o = k / 3, c = k % 3;
        float acc = 0.0f;
#pragma unroll 8
        for (int kk = 0; kk < HD; kk++) acc += sd[c][kk] * Wf[kk * 9 + o];
        pv[(long)n * 27 + k] = acc;
    }
}

__global__ void predsum_kernel(const float* __restrict__ pv, float* __restrict__ pred)
{
    int s = blockIdx.x;
    int j = threadIdx.x;
    if (j >= 27) return;
    float acc = 0.0f;
    for (int u = 0; u < SEGSZ; u++)
        acc += pv[(long)(s * SEGSZ + u) * 27 + j];
    pred[s * 27 + j] = acc;
}

__global__ void final_kernel(const float* __restrict__ pred, float* __restrict__ out)
{
    int s = threadIdx.x;
    if (s >= NSEG) return;
    const float* p = pred + s * 27;
#pragma unroll
    for (int r = 0; r < 3; r++) {
#pragma unroll
        for (int c = 0; c < 3; c++) {
            float A = p[0 * 3 + r] * p[1 * 3 + c]
                    + p[3 * 3 + r] * p[2 * 3 + c]
                    + p[4 * 3 + r] * p[5 * 3 + c]
                    + p[7 * 3 + r] * p[6 * 3 + c];
            out[s * 12 + r * 4 + c] = A * 100.0f;
        }
        out[s * 12 + r * 4 + 3] = p[8 * 3 + r] * 10.0f;
    }
}

// ---------------- host driver ----------------
static void launch_tc(const __nv_bfloat16* A2, int lda, int Ktot, const __nv_bfloat16* B2,
                      const float* bias, const float* res, float* C, int M, int Nt, int flags,
                      __nv_bfloat16* sdst = nullptr, int sldd = 0,
                      const int* edges = nullptr, const float* ArAc = nullptr)
{
    dim3 grid(Nt / 128, M / 128);
    tcgemm<<<grid, 256, TCSMEM>>>(A2, lda, Ktot, B2, bias, res, C, Nt, flags,
                                  sdst, sldd, edges, ArAc);
}

static void launch_gemm(const float* A, const float* B, const float* bias,
                        const float* res, float* C, int M, int N, int K, int flags,
                        int batch = 1, long sA = 0, long sB = 0, long sC = 0)
{
    dim3 grid(N / 128, M / 128, batch);
    gemm128<<<grid, 256>>>(A, B, bias, res, C, M, N, K, flags, sA, sB, sC);
}

static void launch_split(const float* src, int M, int K, __nv_bfloat16* dst, int ldd, int coff,
                         const float* rowscale)
{
    long total = (long)M * K;
    splitA_kernel<<<(int)((total + 255) / 256), 256>>>(src, K, dst, ldd, coff, rowscale, total);
}

template <typename T>
static T* sym(const void* s)
{
    void* p = nullptr;
    cudaGetSymbolAddress(&p, s);
    return (T*)p;
}

extern "C" void kernel_launch(void* const* d_in, const int* in_sizes, int n_in,
                              void* d_out, int out_size)
{
    const float* X        = (const float*)d_in[0];
    const float* node_attr= (const float*)d_in[1];
    const float* edge_attr= (const float*)d_in[2];
    const float* W_in1    = (const float*)d_in[3];
    const float* b_in1    = (const float*)d_in[4];
    const float* W_in2    = (const float*)d_in[5];
    const float* b_in2    = (const float*)d_in[6];
    const float* We1      = (const float*)d_in[7];
    const float* be1      = (const float*)d_in[8];
    const float* We2      = (const float*)d_in[9];
    const float* be2      = (const float*)d_in[10];
    const float* Wv       = (const float*)d_in[11];
    const float* Wvv      = (const float*)d_in[12];
    const float* Wh1      = (const float*)d_in[13];
    const float* bh1      = (const float*)d_in[14];
    const float* Wh2      = (const float*)d_in[15];
    const float* bh2      = (const float*)d_in[16];
    const float* Wi1      = (const float*)d_in[17];
    const float* bi1      = (const float*)d_in[18];
    const float* Wi2      = (const float*)d_in[19];
    const float* bi2      = (const float*)d_in[20];
    const float* Wgv1     = (const float*)d_in[21];
    const float* Wgv2     = (const float*)d_in[22];
    const float* Wg1      = (const float*)d_in[23];
    const float* bg1      = (const float*)d_in[24];
    const float* Wg2      = (const float*)d_in[25];
    const float* bg2      = (const float*)d_in[26];
    const float* Wf       = (const float*)d_in[27];
    const int*   edges    = (const int*)d_in[28];
    float* out = (float*)d_out;

    static bool attr_done = false;
    if (!attr_done) {
        cudaFuncSetAttribute(tcgemm, cudaFuncAttributeMaxDynamicSharedMemorySize, TCSMEM);
        attr_done = true;
    }

    float* p_t0     = sym<float>(g_t0);
    float* p_h      = sym<float>(g_h);
    float* p_ArAc   = sym<float>(g_ArAc);
    float* p_hintra = sym<float>(g_hintra);
    float* p_v2n    = sym<float>(g_v2n);
    float* p_mix    = sym<float>(g_mix);
    float* p_ef     = sym<float>(g_ef);
    float* p_mvv    = sym<float>(g_mvv);
    float* p_unit   = sym<float>(g_unit);
    float* p_usum   = sym<float>(g_usum);
    float* p_va     = sym<float>(g_va);
    float* p_vb     = sym<float>(g_vb);
    float* p_vagg   = sym<float>(g_vagg);
    float* p_vp     = sym<float>(g_vp);
    float* p_w      = sym<float>(g_w);
    float* p_meanp  = sym<float>(g_meanp);
    float* p_meanh  = sym<float>(g_meanh);
    float* p_pv     = sym<float>(g_pv);
    float* p_pred   = sym<float>(g_pred);
    float* p_We1cat = sym<float>(g_We1cat);
    float* p_Wef    = sym<float>(g_Wef);
    float* p_W2v    = sym<float>(g_W2v);
    float* p_MWv    = sym<float>(g_MWv);
    float* p_Wgvcat = sym<float>(g_Wgvcat);
    float* p_b9     = sym<float>(g_b9);
    float* p_bWv    = sym<float>(g_bWv);
    float* p_bWvv   = sym<float>(g_bWvv);

    __nv_bfloat16* pa_cat = sym<__nv_bfloat16>(a2_cat);
    __nv_bfloat16* pa_u   = sym<__nv_bfloat16>(a2_u);
    __nv_bfloat16* pa_x   = sym<__nv_bfloat16>(a2_x);
    __nv_bfloat16* pa_t   = sym<__nv_bfloat16>(a2_t);
    __nv_bfloat16* pa_ef  = sym<__nv_bfloat16>(a2_ef);
    __nv_bfloat16* pa_M   = sym<__nv_bfloat16>(a2_M);
    __nv_bfloat16* pb_We1 = sym<__nv_bfloat16>(b2_We1cat);
    __nv_bfloat16* pb_Wef = sym<__nv_bfloat16>(b2_Wef);
    __nv_bfloat16* pb_W2v = sym<__nv_bfloat16>(b2_W2v);
    __nv_bfloat16* pb_MWv = sym<__nv_bfloat16>(b2_MWv);
    __nv_bfloat16* pb_We2 = sym<__nv_bfloat16>(b2_We2);
    __nv_bfloat16* pb_Wh1 = sym<__nv_bfloat16>(b2_Wh1);
    __nv_bfloat16* pb_Wh2 = sym<__nv_bfloat16>(b2_Wh2);
    __nv_bfloat16* pb_Wi1 = sym<__nv_bfloat16>(b2_Wi1);
    __nv_bfloat16* pb_Wi2 = sym<__nv_bfloat16>(b2_Wi2);
    __nv_bfloat16* pb_Wgv = sym<__nv_bfloat16>(b2_Wgv);
    __nv_bfloat16* pb_Wg1 = sym<__nv_bfloat16>(b2_Wg1);
    __nv_bfloat16* pb_Wg2 = sym<__nv_bfloat16>(b2_Wg2);

    // ---- weight staging ----
    pack_We1cat_kernel<<<(4 * HD * 256 + 255) / 256, 256>>>(We1, p_We1cat);
    pack_Wef_kernel<<<(4 * EFK * HD + 255) / 256, 256>>>(We1, p_Wef);
    pack_Wgv_kernel<<<(HD * 256 + 255) / 256, 256>>>(Wgv1, Wgv2, p_Wgvcat);
    {
        dim3 g(2, HD, 4);
        wprod_kernel<<<g, HD>>>(We2, Wv, Wvv, p_MWv, p_W2v);
    }
    bias_pre_kernel<<<4, HD>>>(be2, Wv, Wvv, p_b9, p_bWv, p_bWvv);

    // ---- single fused bf16 B-pack ----
    {
        PackJobs J;
        auto set = [&](int j, const float* src, long ss, int K, int N,
                       __nv_bfloat16* dst, long ds, int ldd, int coff, int layers) {
            J.src[j] = src; J.sstride[j] = ss; J.K[j] = K; J.N[j] = N;
            J.dst[j] = dst; J.dstride[j] = ds; J.ldd[j] = ldd; J.coff[j] = coff;
            J.layers[j] = layers;
        };
        set(0,  p_We1cat, (long)HD * 256, 128, 256, pb_We1, (long)256 * 384, 384, 0, 4);
        set(1,  p_Wef, (long)EFK * HD, 64, 128, pb_Wef, (long)128 * 192, 192, 0, 4);
        set(2,  p_W2v, (long)HD * HD, 128, 128, pb_W2v, (long)128 * 384, 384, 0, 4);
        set(3,  p_MWv, (long)HD * HD, 128, 128, pb_MWv, (long)128 * 384, 384, 0, 4);
        set(4,  We2, (long)HD * HD, 128, 128, pb_We2, (long)128 * 384, 384, 0, 4);
        set(5,  Wh1, (long)256 * HD, 128, 128, pb_Wh1, (long)128 * 768, 768, 0, 4);
        set(6,  Wh1 + 128 * HD, (long)256 * HD, 128, 128, pb_Wh1, (long)128 * 768, 768, 384, 4);
        set(7,  Wh2, (long)HD * HD, 128, 128, pb_Wh2, (long)128 * 384, 384, 0, 4);
        set(8,  Wi1, (long)HD * HD, 128, 128, pb_Wi1, (long)128 * 384, 384, 0, 4);
        set(9,  Wi2, (long)HD * HD, 128, 128, pb_Wi2, (long)128 * 384, 384, 0, 4);
        set(10, p_Wgvcat, 0, 128, 256, pb_Wgv, 0, 384, 0, 1);
        set(11, Wg1, 0, 128, 128, pb_Wg1, 0, 768, 0, 1);
        set(12, Wg1 + 128 * HD, 0, 128, 128, pb_Wg1, 0, 768, 384, 1);
        set(13, Wg2, 0, 128, 256, pb_Wg2, 0, 384, 0, 1);
        dim3 grid(128, NJOBS, 4);
        pack_all_kernel<<<grid, 256>>>(J);
    }

    // edge geometry + split ef
    edge_geom_kernel<<<(E_EDGES + 255) / 256, 256>>>(X, edge_attr, edges, p_unit, p_ef);
    launch_split(p_ef, E_EDGES, 64, pa_ef, 192, 0, nullptr);

    // h = silu(node_attr @ W_in1 + b_in1) @ W_in2 + b_in2  (fp32), split into pa_cat[0:384]
    launch_gemm(node_attr, W_in1, b_in1, nullptr, p_t0, N_NODES, HD, 64, FLAG_SILU);
    launch_gemm(p_t0, W_in2, b_in2, nullptr, p_h, N_NODES, HD, HD, 0);
    launch_split(p_h, N_NODES, HD, pa_cat, 768, 0, nullptr);

    float* vin = nullptr;
    float* vbuf0 = p_va;
    float* vbuf1 = p_vb;

    for (int i = 0; i < 4; i++) {
        const float* be1_i = be1 + i * HD;
        const float* bh1_i = bh1 + i * HD;
        const float* bh2_i = bh2 + i * HD;
        const float* bi1_i = bi1 + i * HD;
        const float* bi2_i = bi2 + i * HD;
        float* vout = (i & 1) ? vbuf1 : vbuf0;

        // [Ar|Ac] = h @ [W_r|W_c]
        launch_tc(pa_cat, 768, 384, pb_We1 + (long)i * 256 * 384,
                  nullptr, nullptr, p_ArAc, N_NODES, 256, 0);

        // t = silu(ef@Wef + be1 + Ar[row] + Ac[col]) -> split pa_t
        launch_tc(pa_ef, 192, 192, pb_Wef + (long)i * 128 * 192,
                  be1_i, nullptr, nullptr, E_EDGES, 128, FLAG_SILU | FLAG_COMBINE,
                  pa_t, 384, edges, p_ArAc);

        // mvv = t @ (We2@Wvv) + be2@Wvv
        launch_tc(pa_t, 384, 384, pb_W2v + (long)i * 128 * 384,
                  p_bWvv + i * HD, nullptr, p_mvv, E_EDGES, 128, 0);

        // aggregate t
        aggT_kernel<<<N_NODES, HD>>>(pa_t, p_unit, pa_x, pa_M, p_usum);

        // agg = agg_t @ We2 + 9*be2 -> split into pa_cat[384:]
        launch_tc(pa_x, 384, 384, pb_We2 + (long)i * 128 * 384,
                  p_b9 + i * HD, nullptr, nullptr, N_NODES, 128, 0, pa_cat + 384, 768);

        // u = silu([h|agg] @ Wh1 + bh1) -> split pa_u
        launch_tc(pa_cat, 768, 768, pb_Wh1 + (long)i * 128 * 768,
                  bh1_i, nullptr, nullptr, N_NODES, 128, FLAG_SILU, pa_u, 384);
        // h_intra = h + u @ Wh2 + bh2
        launch_tc(pa_u, 384, 384, pb_Wh2 + (long)i * 128 * 384,
                  bh2_i, p_h, p_hintra, N_NODES, 128, 0);

        // vagg = Mt @ (We2@Wv)
        launch_tc(pa_M, 384, 384, pb_MWv + (long)i * 128 * 384,
                  nullptr, nullptr, p_vagg, 3 * N_NODES, 128, 0);
        vupdate_kernel<<<N_NODES, HD>>>(vin, vout, p_mvv, p_vagg, p_usum,
                                        p_bWv + i * HD, edges);

        // segment attention
        {
            dim3 g1(NSEG, 8);
            meanh1_kernel<<<g1, HD>>>(p_hintra, p_meanp);
            meanh2_kernel<<<NSEG, HD>>>(p_meanp, p_meanh);
        }
        attn_kernel<<<NSEG, SEGSZ>>>(p_hintra, p_meanh, p_w);
        launch_split(p_hintra, N_NODES, HD, pa_x, 384, 0, p_w);
        launch_tc(pa_x, 384, 384, pb_Wi1 + (long)i * 128 * 384,
                  bi1_i, nullptr, nullptr, N_NODES, 128, FLAG_SILU, pa_u, 384);
        launch_tc(pa_u, 384, 384, pb_Wi2 + (long)i * 128 * 384,
                  bi2_i, p_hintra, p_h, N_NODES, 128, 0, pa_cat, 768);

        vin = vout;
    }

    // [v1 | v2] = v @ [Wgv1 | Wgv2]
    launch_split(vin, 3 * N_NODES, HD, pa_M, 384, 0, nullptr);
    launch_tc(pa_M, 384, 384, pb_Wgv, nullptr, nullptr, p_vp, 3 * N_NODES, 256, 0);
    v2n_kernel<<<(N_NODES * HD + 255) / 256, 256>>>(p_vp, p_v2n);

    // mix = silu([h|v2n] @ Wg1 + bg1) @ Wg2 + bg2
    launch_split(p_v2n, N_NODES, HD, pa_cat, 768, 384, nullptr);
    launch_tc(pa_cat, 768, 768, pb_Wg1, bg1, nullptr, nullptr, N_NODES, 128, FLAG_SILU, pa_u, 384);
    launch_tc(pa_u, 384, 384, pb_Wg2, bg2, nullptr, p_mix, N_NODES, 256, 0);

    // epilogue
    pv_kernel<<<N_NODES, HD>>>(p_vp, p_mix, Wf, p_pv);
    predsum_kernel<<<NSEG, 32>>>(p_pv, p_pred);
    final_kernel<<<1, 32>>>(p_pred, out);
}